// round 7
// baseline (speedup 1.0000x reference)
#include <cuda_runtime.h>
#include <cuda_bf16.h>
#include <cstdint>
#include <cstddef>

#define Nn 20000
#define Ee 320000
#define Ff 128
#define Hh 8
#define EFe 64
#define Aa 128
#define Gg 32
#define F2 256
#define TILE_N 64
#define ETILE 128
#define NTILES (Ee / ETILE)

// ---------------- scratch (device globals; no allocations allowed) ----------------
__device__ float g_sb_mix[Gg * F2];
__device__ float g_sb_mlp[Gg * F2];
__device__ float g_hsrc[(size_t)Nn * Ff];
__device__ float g_hdst[(size_t)Nn * Ff];
__device__ float g_wsum[Nn * Hh];
__device__ float g_o[(size_t)Nn * Ff];

__device__ __forceinline__ float siluf(float x) { return x / (1.f + __expf(-x)); }

// bf16 warp MMA: D[16x8] += A[16x16] * B[16x8], A row-major frags, B col-major frags
__device__ __forceinline__ void mma_bf16(float* d, uint32_t a0, uint32_t a1,
                                         uint32_t a2, uint32_t a3,
                                         uint32_t b0, uint32_t b1) {
    asm volatile(
        "mma.sync.aligned.m16n8k16.row.col.f32.bf16.bf16.f32 "
        "{%0,%1,%2,%3}, {%4,%5,%6,%7}, {%8,%9}, {%0,%1,%2,%3};"
        : "+f"(d[0]), "+f"(d[1]), "+f"(d[2]), "+f"(d[3])
        : "r"(a0), "r"(a1), "r"(a2), "r"(a3), "r"(b0), "r"(b1));
}

__device__ __forceinline__ uint32_t pack_bf16(float a, float b) {
    __nv_bfloat162 p = __floats2bfloat162_rn(a, b);
    return *(uint32_t*)&p;
}

// ---------------- init: zero accumulators ----------------------------------------
__global__ void k_init() {
    int i = blockIdx.x * 256 + threadIdx.x;
    if (i < Nn * Ff) g_o[i] = 0.f;
    if (i < Nn * Hh) g_wsum[i] = 0.f;
}

// ---------------- cond GEMMs ------------------------------------------------------
__global__ __launch_bounds__(256) void k_cond(const float* __restrict__ cond,
                                              const float* __restrict__ w_mix,
                                              const float* __restrict__ b_mix,
                                              const float* __restrict__ w_mlp,
                                              const float* __restrict__ b_mlp) {
    __shared__ float cs[Aa];
    int g = blockIdx.x;
    int which = blockIdx.y;
    const float* w = which ? w_mlp : w_mix;
    const float* b = which ? b_mlp : b_mix;
    float* outp = which ? g_sb_mlp : g_sb_mix;
    int t = threadIdx.x;
    if (t < Aa) cs[t] = cond[g * Aa + t];
    __syncthreads();
    float acc = b[t];
    #pragma unroll 8
    for (int k = 0; k < Aa; k++) acc = fmaf(cs[k], w[k * F2 + t], acc);
    outp[g * F2 + t] = acc;
}

// ============== node kernel 1 (HMMA): hh = ada_ln(x) @ w_h + b_h ===================
#define N1STR 272
#define N1_OFF_XM 0         // 64*272  = 17408
#define N1_OFF_W  17408     // 256*272 = 69632
#define SM_NODE1  87040

__global__ __launch_bounds__(512) void k_node1(const float* __restrict__ input,
                                               const int* __restrict__ batch,
                                               const float* __restrict__ w_h,
                                               const float* __restrict__ b_h) {
    extern __shared__ __align__(16) char smem_raw[];
    const int tid = threadIdx.x;
    const int warp = tid >> 5, lane = tid & 31;
    const int g = lane >> 2, tg = lane & 3;
    const int nb = blockIdx.x * TILE_N;
    char* xm = smem_raw + N1_OFF_XM;
    char* wb = smem_raw + N1_OFF_W;

    // ada_ln(mix) -> xm bf16 (each warp: 4 rows)
    #pragma unroll
    for (int q = 0; q < 4; q++) {
        int r = warp * 4 + q;
        int n = nb + r;
        int nc = n < Nn ? n : Nn - 1;
        float4 x = ((const float4*)(input + (size_t)nc * Ff))[lane];
        float s  = x.x + x.y + x.z + x.w;
        float ss = fmaf(x.x, x.x, fmaf(x.y, x.y, fmaf(x.z, x.z, x.w * x.w)));
        #pragma unroll
        for (int o = 16; o > 0; o >>= 1) {
            s  += __shfl_xor_sync(0xffffffffu, s, o);
            ss += __shfl_xor_sync(0xffffffffu, ss, o);
        }
        float mu = s * (1.f / Ff);
        float rstd = rsqrtf(ss * (1.f / Ff) - mu * mu + 1e-5f);
        int bix = batch[nc];
        const float* sb = g_sb_mix + bix * F2;
        float4 sc = *((const float4*)(sb + lane * 4));
        float4 sh = *((const float4*)(sb + Ff + lane * 4));
        float o0 = (x.x - mu) * rstd * (1.f + sc.x) + sh.x;
        float o1 = (x.y - mu) * rstd * (1.f + sc.y) + sh.y;
        float o2 = (x.z - mu) * rstd * (1.f + sc.z) + sh.z;
        float o3 = (x.w - mu) * rstd * (1.f + sc.w) + sh.w;
        *(uint32_t*)(xm + r * N1STR + lane * 8)     = pack_bf16(o0, o1);
        *(uint32_t*)(xm + r * N1STR + lane * 8 + 4) = pack_bf16(o2, o3);
    }
    // stage w_h^T [256n][128k] bf16
    for (int i = tid; i < 256 * 128; i += 512) {
        int n = i >> 7, k = i & 127;
        *(__nv_bfloat16*)(wb + n * N1STR + k * 2) = __float2bfloat16(w_h[k * F2 + n]);
    }
    __syncthreads();

    const int wr = warp & 3, wq = warp >> 2;
    const int row0 = wr * 16 + g, row1 = row0 + 8;
    float d[8][4];
    #pragma unroll
    for (int i = 0; i < 8; i++) { d[i][0]=0.f; d[i][1]=0.f; d[i][2]=0.f; d[i][3]=0.f; }
    #pragma unroll
    for (int ks = 0; ks < 8; ks++) {
        int k0 = ks * 16;
        uint32_t a0 = *(const uint32_t*)(xm + row0 * N1STR + (k0 + 2 * tg) * 2);
        uint32_t a1 = *(const uint32_t*)(xm + row1 * N1STR + (k0 + 2 * tg) * 2);
        uint32_t a2 = *(const uint32_t*)(xm + row0 * N1STR + (k0 + 2 * tg + 8) * 2);
        uint32_t a3 = *(const uint32_t*)(xm + row1 * N1STR + (k0 + 2 * tg + 8) * 2);
        #pragma unroll
        for (int nb2 = 0; nb2 < 8; nb2++) {
            int n0 = wq * 64 + nb2 * 8;
            uint32_t b0 = *(const uint32_t*)(wb + (n0 + g) * N1STR + (k0 + 2 * tg) * 2);
            uint32_t b1 = *(const uint32_t*)(wb + (n0 + g) * N1STR + (k0 + 2 * tg + 8) * 2);
            mma_bf16(d[nb2], a0, a1, a2, a3, b0, b1);
        }
    }
    int na = nb + row0, nbr = nb + row1;
    #pragma unroll
    for (int nb2 = 0; nb2 < 8; nb2++) {
        int c = wq * 64 + nb2 * 8 + 2 * tg;
        float bb0 = __ldg(b_h + c), bb1 = __ldg(b_h + c + 1);
        if (c < Ff) {
            if (na < Nn) { float2 v = {d[nb2][0]+bb0, d[nb2][1]+bb1};
                           *(float2*)(g_hsrc + (size_t)na * Ff + c) = v; }
            if (nbr < Nn) { float2 v = {d[nb2][2]+bb0, d[nb2][3]+bb1};
                           *(float2*)(g_hsrc + (size_t)nbr * Ff + c) = v; }
        } else {
            int c2 = c - Ff;
            if (na < Nn) { float2 v = {d[nb2][0]+bb0, d[nb2][1]+bb1};
                           *(float2*)(g_hdst + (size_t)na * Ff + c2) = v; }
            if (nbr < Nn) { float2 v = {d[nb2][2]+bb0, d[nb2][3]+bb1};
                           *(float2*)(g_hdst + (size_t)nbr * Ff + c2) = v; }
        }
    }
}

// ========================= mma.sync bf16 edge kernel (unchanged) ===================
#define STRA 144
#define STRB 272
#define OFF_WAT  0
#define OFF_WCT  18432
#define OFF_AN   79360
#define OFF_M    97792
#define OFF_WEXP 132608
#define OFF_SRC  137216
#define OFF_DST  137728
#define OFF_GE   138240
#define OFF_BE   138496
#define OFF_BD   138752
#define SMEDGE   139008

__global__ __launch_bounds__(512) void k_edge(const float* __restrict__ ain,
                                              const int* __restrict__ edges,
                                              const float* __restrict__ w_a,
                                              const float* __restrict__ w_vatt,
                                              const float* __restrict__ w_edge,
                                              const float* __restrict__ gain_e,
                                              const float* __restrict__ bias_e,
                                              const float* __restrict__ b_edge,
                                              float* __restrict__ aout) {
    extern __shared__ __align__(16) char smem_raw[];
    const int tid = threadIdx.x;
    const int warp = tid >> 5, lane = tid & 31;
    const int g = lane >> 2, tg = lane & 3;
    const int wr = warp & 7;
    const int wc = warp >> 3;

    float* wexp_s = (float*)(smem_raw + OFF_WEXP);
    int*   src_s  = (int*)(smem_raw + OFF_SRC);
    int*   dst_s  = (int*)(smem_raw + OFF_DST);
    float* ge_s   = (float*)(smem_raw + OFF_GE);
    float* be_s   = (float*)(smem_raw + OFF_BE);
    float* bd_s   = (float*)(smem_raw + OFF_BD);

    for (int i = tid; i < 128 * 64; i += 512) {
        int n = i >> 6, k = i & 63;
        *(__nv_bfloat16*)(smem_raw + OFF_WAT + n * STRA + k * 2) =
            __float2bfloat16(w_a[k * Ff + n]);
    }
    for (int i = tid; i < 224 * 128; i += 512) {
        int n = i >> 7, k = i & 127;
        float v = 0.f;
        if (n < 136)               v = w_vatt[k * 136 + n];
        else if (n < 200)          v = w_edge[k * EFe + (n - 136)];
        *(__nv_bfloat16*)(smem_raw + OFF_WCT + n * STRB + k * 2) = __float2bfloat16(v);
    }
    if (tid < EFe) { ge_s[tid] = gain_e[tid]; be_s[tid] = bias_e[tid]; bd_s[tid] = b_edge[tid]; }
    __syncthreads();

    for (int tile = blockIdx.x; tile < NTILES; tile += gridDim.x) {
        const int e0 = tile * ETILE;

        if (tid < ETILE) {
            src_s[tid] = edges[e0 + tid];
            dst_s[tid] = edges[Ee + e0 + tid];
        }

        #pragma unroll
        for (int q = 0; q < 8; q++) {
            int r = warp * 8 + q;
            const float* arow = ain + (size_t)(e0 + r) * EFe;
            float x0 = __ldg(arow + lane);
            float x1 = __ldg(arow + lane + 32);
            float s = x0 + x1;
            float ss = fmaf(x0, x0, x1 * x1);
            #pragma unroll
            for (int o = 16; o > 0; o >>= 1) {
                s  += __shfl_xor_sync(0xffffffffu, s, o);
                ss += __shfl_xor_sync(0xffffffffu, ss, o);
            }
            float mu = s * (1.f / EFe);
            float rstd = rsqrtf(ss * (1.f / EFe) - mu * mu + 1e-5f);
            float v0 = (x0 - mu) * rstd * ge_s[lane]      + be_s[lane];
            float v1 = (x1 - mu) * rstd * ge_s[lane + 32] + be_s[lane + 32];
            *(__nv_bfloat16*)(smem_raw + OFF_AN + r * STRA + lane * 2)        = __float2bfloat16(v0);
            *(__nv_bfloat16*)(smem_raw + OFF_AN + r * STRA + (lane + 32) * 2) = __float2bfloat16(v1);
        }
        __syncthreads();

        const int row0 = wr * 16 + g, row1 = row0 + 8;
        const int s0 = src_s[row0], s1 = src_s[row1];

        float d1[8][4];
        #pragma unroll
        for (int i = 0; i < 8; i++) { d1[i][0]=0.f; d1[i][1]=0.f; d1[i][2]=0.f; d1[i][3]=0.f; }
        {
            const char* anp = smem_raw + OFF_AN;
            const char* wap = smem_raw + OFF_WAT;
            #pragma unroll
            for (int ks = 0; ks < 4; ks++) {
                int k0 = ks * 16;
                uint32_t a0 = *(const uint32_t*)(anp + row0 * STRA + (k0 + 2 * tg) * 2);
                uint32_t a1 = *(const uint32_t*)(anp + row1 * STRA + (k0 + 2 * tg) * 2);
                uint32_t a2 = *(const uint32_t*)(anp + row0 * STRA + (k0 + 2 * tg + 8) * 2);
                uint32_t a3 = *(const uint32_t*)(anp + row1 * STRA + (k0 + 2 * tg + 8) * 2);
                #pragma unroll
                for (int nb = 0; nb < 8; nb++) {
                    int n0 = wc * 64 + nb * 8;
                    uint32_t b0 = *(const uint32_t*)(wap + (n0 + g) * STRA + (k0 + 2 * tg) * 2);
                    uint32_t b1 = *(const uint32_t*)(wap + (n0 + g) * STRA + (k0 + 2 * tg + 8) * 2);
                    mma_bf16(d1[nb], a0, a1, a2, a3, b0, b1);
                }
            }
        }

        {
            const int dd0 = dst_s[row0], dd1 = dst_s[row1];
            #pragma unroll
            for (int nb = 0; nb < 8; nb++) {
                int col = wc * 64 + nb * 8 + 2 * tg;
                float2 hs0 = *(const float2*)(g_hsrc + (size_t)s0 * Ff + col);
                float2 hd0 = *(const float2*)(g_hdst + (size_t)dd0 * Ff + col);
                float2 hs1 = *(const float2*)(g_hsrc + (size_t)s1 * Ff + col);
                float2 hd1 = *(const float2*)(g_hdst + (size_t)dd1 * Ff + col);
                float m00 = siluf(d1[nb][0] + hs0.x + hd0.x);
                float m01 = siluf(d1[nb][1] + hs0.y + hd0.y);
                float m10 = siluf(d1[nb][2] + hs1.x + hd1.x);
                float m11 = siluf(d1[nb][3] + hs1.y + hd1.y);
                *(uint32_t*)(smem_raw + OFF_M + row0 * STRB + col * 2) = pack_bf16(m00, m01);
                *(uint32_t*)(smem_raw + OFF_M + row1 * STRB + col * 2) = pack_bf16(m10, m11);
            }
        }
        __syncthreads();

        float d2[14][4];
        #pragma unroll
        for (int i = 0; i < 14; i++) { d2[i][0]=0.f; d2[i][1]=0.f; d2[i][2]=0.f; d2[i][3]=0.f; }
        {
            const char* mp  = smem_raw + OFF_M;
            const char* wcp = smem_raw + OFF_WCT;
            #pragma unroll
            for (int ks = 0; ks < 8; ks++) {
                int k0 = ks * 16;
                uint32_t a0 = *(const uint32_t*)(mp + row0 * STRB + (k0 + 2 * tg) * 2);
                uint32_t a1 = *(const uint32_t*)(mp + row1 * STRB + (k0 + 2 * tg) * 2);
                uint32_t a2 = *(const uint32_t*)(mp + row0 * STRB + (k0 + 2 * tg + 8) * 2);
                uint32_t a3 = *(const uint32_t*)(mp + row1 * STRB + (k0 + 2 * tg + 8) * 2);
                #pragma unroll
                for (int nb = 0; nb < 14; nb++) {
                    int n0 = wc * 112 + nb * 8;
                    uint32_t b0 = *(const uint32_t*)(wcp + (n0 + g) * STRB + (k0 + 2 * tg) * 2);
                    uint32_t b1 = *(const uint32_t*)(wcp + (n0 + g) * STRB + (k0 + 2 * tg + 8) * 2);
                    mma_bf16(d2[nb], a0, a1, a2, a3, b0, b1);
                }
            }
        }

        if (wc == 1) {
            int h = 2 * tg;
            float e00 = __expf(d2[2][0]);
            float e01 = __expf(d2[2][1]);
            float e10 = __expf(d2[2][2]);
            float e11 = __expf(d2[2][3]);
            wexp_s[row0 * 9 + h]     = e00;
            wexp_s[row0 * 9 + h + 1] = e01;
            wexp_s[row1 * 9 + h]     = e10;
            wexp_s[row1 * 9 + h + 1] = e11;
            float* p0 = g_wsum + (size_t)s0 * Hh + h;
            float* p1 = g_wsum + (size_t)s1 * Hh + h;
            asm volatile("red.global.add.f32 [%0], %1;" :: "l"(p0),     "f"(e00) : "memory");
            asm volatile("red.global.add.f32 [%0], %1;" :: "l"(p0 + 1), "f"(e01) : "memory");
            asm volatile("red.global.add.f32 [%0], %1;" :: "l"(p1),     "f"(e10) : "memory");
            asm volatile("red.global.add.f32 [%0], %1;" :: "l"(p1 + 1), "f"(e11) : "memory");
        }
        __syncthreads();

        #pragma unroll
        for (int nb = 0; nb < 14; nb++) {
            int col = wc * 112 + nb * 8 + 2 * tg;
            if (col < Ff) {
                int h = col >> 4;
                float w0 = wexp_s[row0 * 9 + h];
                float w1 = wexp_s[row1 * 9 + h];
                float* o0 = g_o + (size_t)s0 * Ff + col;
                float* o1 = g_o + (size_t)s1 * Ff + col;
                asm volatile("red.global.add.v2.f32 [%0], {%1, %2};"
                             :: "l"(o0), "f"(d2[nb][0] * w0), "f"(d2[nb][1] * w0) : "memory");
                asm volatile("red.global.add.v2.f32 [%0], {%1, %2};"
                             :: "l"(o1), "f"(d2[nb][2] * w1), "f"(d2[nb][3] * w1) : "memory");
            } else if (col >= 136 && col < 200) {
                int k2 = col - 136;
                float2 a0v = *(const float2*)(ain + (size_t)(e0 + row0) * EFe + k2);
                float2 a1v = *(const float2*)(ain + (size_t)(e0 + row1) * EFe + k2);
                float2 r0v, r1v;
                r0v.x = a0v.x + d2[nb][0] + bd_s[k2];
                r0v.y = a0v.y + d2[nb][1] + bd_s[k2 + 1];
                r1v.x = a1v.x + d2[nb][2] + bd_s[k2];
                r1v.y = a1v.y + d2[nb][3] + bd_s[k2 + 1];
                *(float2*)(aout + (size_t)(e0 + row0) * EFe + k2) = r0v;
                *(float2*)(aout + (size_t)(e0 + row1) * EFe + k2) = r1v;
            }
        }
        __syncthreads();
    }
}

// ============== fused node kernel 2 + MLP (HMMA) ==================================
#define N2STR 272
#define OFF2_W  0          // 128*272 = 34816
#define OFF2_XN 34816      // 64*272  = 17408
#define OFF2_T  52224      // 64*272  = 17408
#define OFF2_HM 69632      // 64*136*4= 34816
#define SM_N2M  104448

__global__ __launch_bounds__(512) void k_node2mlp(const float* __restrict__ input,
                                                  const int* __restrict__ batch,
                                                  const float* __restrict__ w_out,
                                                  const float* __restrict__ b_out,
                                                  const float* __restrict__ w1,
                                                  const float* __restrict__ b1,
                                                  const float* __restrict__ w2,
                                                  const float* __restrict__ b2,
                                                  float* __restrict__ hout) {
    extern __shared__ __align__(16) char smem_raw[];
    const int tid = threadIdx.x;
    const int warp = tid >> 5, lane = tid & 31;
    const int g = lane >> 2, tg = lane & 3;
    const int wr = warp & 3, wq = warp >> 2;
    const int nb = blockIdx.x * TILE_N;
    char* wbuf = smem_raw + OFF2_W;
    char* xnb  = smem_raw + OFF2_XN;
    char* tb   = smem_raw + OFF2_T;
    float* hm_s = (float*)(smem_raw + OFF2_HM);

    // stage A = o / wsum (bf16) into T
    for (int i = tid; i < TILE_N * 32; i += 512) {
        int r = i >> 5, c4 = i & 31;
        int n = nb + r;
        int nc = n < Nn ? n : Nn - 1;
        float4 o4 = ((const float4*)(g_o + (size_t)nc * Ff))[c4];
        int h = c4 >> 2;
        float inv = 1.f / (g_wsum[nc * Hh + h] + 1e-16f);
        *(uint32_t*)(tb + r * N2STR + c4 * 8)     = pack_bf16(o4.x * inv, o4.y * inv);
        *(uint32_t*)(tb + r * N2STR + c4 * 8 + 4) = pack_bf16(o4.z * inv, o4.w * inv);
    }
    // stage w_out^T bf16
    for (int i = tid; i < 128 * 128; i += 512) {
        int n = i >> 7, k = i & 127;
        *(__nv_bfloat16*)(wbuf + n * N2STR + k * 2) = __float2bfloat16(w_out[k * Ff + n]);
    }
    __syncthreads();

    const int row0 = wr * 16 + g, row1 = row0 + 8;
    const int na = nb + row0, nb1 = nb + row1;
    const int nca = na < Nn ? na : Nn - 1;
    const int ncb = nb1 < Nn ? nb1 : Nn - 1;

    // GEMM: hm = (o/wsum) @ w_out
    {
        float d[4][4];
        #pragma unroll
        for (int i = 0; i < 4; i++) { d[i][0]=0.f; d[i][1]=0.f; d[i][2]=0.f; d[i][3]=0.f; }
        #pragma unroll
        for (int ks = 0; ks < 8; ks++) {
            int k0 = ks * 16;
            uint32_t a0 = *(const uint32_t*)(tb + row0 * N2STR + (k0 + 2 * tg) * 2);
            uint32_t a1 = *(const uint32_t*)(tb + row1 * N2STR + (k0 + 2 * tg) * 2);
            uint32_t a2 = *(const uint32_t*)(tb + row0 * N2STR + (k0 + 2 * tg + 8) * 2);
            uint32_t a3 = *(const uint32_t*)(tb + row1 * N2STR + (k0 + 2 * tg + 8) * 2);
            #pragma unroll
            for (int nb2 = 0; nb2 < 4; nb2++) {
                int n0 = wq * 32 + nb2 * 8;
                uint32_t b0 = *(const uint32_t*)(wbuf + (n0 + g) * N2STR + (k0 + 2 * tg) * 2);
                uint32_t b1 = *(const uint32_t*)(wbuf + (n0 + g) * N2STR + (k0 + 2 * tg + 8) * 2);
                mma_bf16(d[nb2], a0, a1, a2, a3, b0, b1);
            }
        }
        // hm = d + input + b_out -> hm_s (fp32)
        #pragma unroll
        for (int nb2 = 0; nb2 < 4; nb2++) {
            int c = wq * 32 + nb2 * 8 + 2 * tg;
            float2 ia = *(const float2*)(input + (size_t)nca * Ff + c);
            float2 ib = *(const float2*)(input + (size_t)ncb * Ff + c);
            float bb0 = __ldg(b_out + c), bb1 = __ldg(b_out + c + 1);
            hm_s[row0 * 136 + c]     = d[nb2][0] + ia.x + bb0;
            hm_s[row0 * 136 + c + 1] = d[nb2][1] + ia.y + bb1;
            hm_s[row1 * 136 + c]     = d[nb2][2] + ib.x + bb0;
            hm_s[row1 * 136 + c + 1] = d[nb2][3] + ib.y + bb1;
        }
    }
    __syncthreads();

    // ada_ln(mlp) from hm_s -> xn bf16
    #pragma unroll
    for (int q = 0; q < 4; q++) {
        int r = warp * 4 + q;
        int n = nb + r;
        int nc = n < Nn ? n : Nn - 1;
        float4 x = ((const float4*)(hm_s + r * 136))[lane];
        float s  = x.x + x.y + x.z + x.w;
        float ss = fmaf(x.x, x.x, fmaf(x.y, x.y, fmaf(x.z, x.z, x.w * x.w)));
        #pragma unroll
        for (int o = 16; o > 0; o >>= 1) {
            s  += __shfl_xor_sync(0xffffffffu, s, o);
            ss += __shfl_xor_sync(0xffffffffu, ss, o);
        }
        float mu = s * (1.f / Ff);
        float rstd = rsqrtf(ss * (1.f / Ff) - mu * mu + 1e-5f);
        int bix = batch[nc];
        const float* sb = g_sb_mlp + bix * F2;
        float4 sc = *((const float4*)(sb + lane * 4));
        float4 sh = *((const float4*)(sb + Ff + lane * 4));
        float o0 = (x.x - mu) * rstd * (1.f + sc.x) + sh.x;
        float o1 = (x.y - mu) * rstd * (1.f + sc.y) + sh.y;
        float o2 = (x.z - mu) * rstd * (1.f + sc.z) + sh.z;
        float o3 = (x.w - mu) * rstd * (1.f + sc.w) + sh.w;
        *(uint32_t*)(xnb + r * N2STR + lane * 8)     = pack_bf16(o0, o1);
        *(uint32_t*)(xnb + r * N2STR + lane * 8 + 4) = pack_bf16(o2, o3);
    }

    // MLP: oacc accumulates across 4 hidden chunks (MMA layout)
    float oacc[4][4];
    #pragma unroll
    for (int i = 0; i < 4; i++) { oacc[i][0]=0.f; oacc[i][1]=0.f; oacc[i][2]=0.f; oacc[i][3]=0.f; }

    for (int ch = 0; ch < 4; ch++) {
        __syncthreads();   // guards W overwrite + xn/T readiness
        for (int i = tid; i < 128 * 128; i += 512) {
            int n = i >> 7, k = i & 127;
            *(__nv_bfloat16*)(wbuf + n * N2STR + k * 2) =
                __float2bfloat16(w1[k * 512 + ch * 128 + n]);
        }
        __syncthreads();
        float dt[4][4];
        #pragma unroll
        for (int i = 0; i < 4; i++) { dt[i][0]=0.f; dt[i][1]=0.f; dt[i][2]=0.f; dt[i][3]=0.f; }
        #pragma unroll
        for (int ks = 0; ks < 8; ks++) {
            int k0 = ks * 16;
            uint32_t a0 = *(const uint32_t*)(xnb + row0 * N2STR + (k0 + 2 * tg) * 2);
            uint32_t a1 = *(const uint32_t*)(xnb + row1 * N2STR + (k0 + 2 * tg) * 2);
            uint32_t a2 = *(const uint32_t*)(xnb + row0 * N2STR + (k0 + 2 * tg + 8) * 2);
            uint32_t a3 = *(const uint32_t*)(xnb + row1 * N2STR + (k0 + 2 * tg + 8) * 2);
            #pragma unroll
            for (int nb2 = 0; nb2 < 4; nb2++) {
                int n0 = wq * 32 + nb2 * 8;
                uint32_t b0 = *(const uint32_t*)(wbuf + (n0 + g) * N2STR + (k0 + 2 * tg) * 2);
                uint32_t b1 = *(const uint32_t*)(wbuf + (n0 + g) * N2STR + (k0 + 2 * tg + 8) * 2);
                mma_bf16(dt[nb2], a0, a1, a2, a3, b0, b1);
            }
        }
        // silu(+b1) -> T bf16
        #pragma unroll
        for (int nb2 = 0; nb2 < 4; nb2++) {
            int c = wq * 32 + nb2 * 8 + 2 * tg;
            float b10 = __ldg(b1 + ch * 128 + c), b11 = __ldg(b1 + ch * 128 + c + 1);
            *(uint32_t*)(tb + row0 * N2STR + c * 2) =
                pack_bf16(siluf(dt[nb2][0] + b10), siluf(dt[nb2][1] + b11));
            *(uint32_t*)(tb + row1 * N2STR + c * 2) =
                pack_bf16(siluf(dt[nb2][2] + b10), siluf(dt[nb2][3] + b11));
        }
        __syncthreads();
        for (int i = tid; i < 128 * 128; i += 512) {
            int n = i >> 7, k = i & 127;
            *(__nv_bfloat16*)(wbuf + n * N2STR + k * 2) =
                __float2bfloat16(w2[(size_t)(ch * 128 + k) * Ff + n]);
        }
        __syncthreads();
        #pragma unroll
        for (int ks = 0; ks < 8; ks++) {
            int k0 = ks * 16;
            uint32_t a0 = *(const uint32_t*)(tb + row0 * N2STR + (k0 + 2 * tg) * 2);
            uint32_t a1 = *(const uint32_t*)(tb + row1 * N2STR + (k0 + 2 * tg) * 2);
            uint32_t a2 = *(const uint32_t*)(tb + row0 * N2STR + (k0 + 2 * tg + 8) * 2);
            uint32_t a3 = *(const uint32_t*)(tb + row1 * N2STR + (k0 + 2 * tg + 8) * 2);
            #pragma unroll
            for (int nb2 = 0; nb2 < 4; nb2++) {
                int n0 = wq * 32 + nb2 * 8;
                uint32_t b0 = *(const uint32_t*)(wbuf + (n0 + g) * N2STR + (k0 + 2 * tg) * 2);
                uint32_t b1 = *(const uint32_t*)(wbuf + (n0 + g) * N2STR + (k0 + 2 * tg + 8) * 2);
                mma_bf16(oacc[nb2], a0, a1, a2, a3, b0, b1);
            }
        }
    }

    // final: out = oacc + hm + b2
    #pragma unroll
    for (int nb2 = 0; nb2 < 4; nb2++) {
        int c = wq * 32 + nb2 * 8 + 2 * tg;
        float b20 = __ldg(b2 + c), b21 = __ldg(b2 + c + 1);
        if (na < Nn) {
            float2 v = {oacc[nb2][0] + hm_s[row0 * 136 + c]     + b20,
                        oacc[nb2][1] + hm_s[row0 * 136 + c + 1] + b21};
            *(float2*)(hout + (size_t)na * Ff + c) = v;
        }
        if (nb1 < Nn) {
            float2 v = {oacc[nb2][2] + hm_s[row1 * 136 + c]     + b20,
                        oacc[nb2][3] + hm_s[row1 * 136 + c + 1] + b21};
            *(float2*)(hout + (size_t)nb1 * Ff + c) = v;
        }
    }
}

// ---------------- launcher ---------------------------------------------------------
extern "C" void kernel_launch(void* const* d_in, const int* in_sizes, int n_in,
                              void* d_out, int out_size) {
    const float* input     = (const float*)d_in[0];
    const float* cond      = (const float*)d_in[1];
    const float* a         = (const float*)d_in[2];
    const int*   batch     = (const int*)d_in[3];
    const int*   edges     = (const int*)d_in[4];
    const float* w_ada_mix = (const float*)d_in[5];
    const float* b_ada_mix = (const float*)d_in[6];
    const float* w_h       = (const float*)d_in[7];
    const float* b_h       = (const float*)d_in[8];
    const float* w_a       = (const float*)d_in[9];
    const float* w_vatt    = (const float*)d_in[10];
    const float* w_out     = (const float*)d_in[11];
    const float* b_out     = (const float*)d_in[12];
    const float* g_edge_p  = (const float*)d_in[13];
    const float* be_edge_p = (const float*)d_in[14];
    const float* w_edge    = (const float*)d_in[15];
    const float* b_edge    = (const float*)d_in[16];
    const float* w_ada_mlp = (const float*)d_in[17];
    const float* b_ada_mlp = (const float*)d_in[18];
    const float* w1        = (const float*)d_in[19];
    const float* b1        = (const float*)d_in[20];
    const float* w2        = (const float*)d_in[21];
    const float* b2        = (const float*)d_in[22];

    float* hout = (float*)d_out;                       // h: [N, F]
    float* aout = (float*)d_out + (size_t)Nn * Ff;     // a_out: [E, EF]

    cudaFuncSetAttribute(k_node1,    cudaFuncAttributeMaxDynamicSharedMemorySize, SM_NODE1);
    cudaFuncSetAttribute(k_edge,     cudaFuncAttributeMaxDynamicSharedMemorySize, SMEDGE);
    cudaFuncSetAttribute(k_node2mlp, cudaFuncAttributeMaxDynamicSharedMemorySize, SM_N2M);

    const int NT = (Nn + TILE_N - 1) / TILE_N;  // 313

    k_init<<<(Nn * Ff + 255) / 256, 256>>>();
    k_cond<<<dim3(Gg, 2), 256>>>(cond, w_ada_mix, b_ada_mix, w_ada_mlp, b_ada_mlp);
    k_node1<<<NT, 512, SM_NODE1>>>(input, batch, w_h, b_h);
    k_edge<<<148, 512, SMEDGE>>>(a, edges, w_a, w_vatt, w_edge,
                                 g_edge_p, be_edge_p, b_edge, aout);
    k_node2mlp<<<NT, 512, SM_N2M>>>(input, batch, w_out, b_out, w1, b1, w2, b2, hout);
}

// round 8
// speedup vs baseline: 1.4166x; 1.4166x over previous
#include <cuda_runtime.h>
#include <cuda_bf16.h>
#include <cstdint>
#include <cstddef>

#define Nn 20000
#define Ee 320000
#define Ff 128
#define Hh 8
#define EFe 64
#define Aa 128
#define Gg 32
#define F2 256
#define NTILE 128
#define ETILE 128
#define NTILES (Ee / ETILE)

// ---------------- scratch (device globals; no allocations allowed) ----------------
__device__ float g_sb_mix[Gg * F2];
__device__ float g_sb_mlp[Gg * F2];
__device__ float g_hsrc[(size_t)Nn * Ff];
__device__ float g_hdst[(size_t)Nn * Ff];
__device__ float g_wsum[Nn * Hh];
__device__ float g_o[(size_t)Nn * Ff];

__device__ __forceinline__ float siluf(float x) { return x / (1.f + __expf(-x)); }

// bf16 warp MMA: D[16x8] += A[16x16] * B[16x8], A row-major frags, B col-major frags
__device__ __forceinline__ void mma_bf16(float* d, uint32_t a0, uint32_t a1,
                                         uint32_t a2, uint32_t a3,
                                         uint32_t b0, uint32_t b1) {
    asm volatile(
        "mma.sync.aligned.m16n8k16.row.col.f32.bf16.bf16.f32 "
        "{%0,%1,%2,%3}, {%4,%5,%6,%7}, {%8,%9}, {%0,%1,%2,%3};"
        : "+f"(d[0]), "+f"(d[1]), "+f"(d[2]), "+f"(d[3])
        : "r"(a0), "r"(a1), "r"(a2), "r"(a3), "r"(b0), "r"(b1));
}

__device__ __forceinline__ uint32_t pack_bf16(float a, float b) {
    __nv_bfloat162 p = __floats2bfloat162_rn(a, b);
    return *(uint32_t*)&p;
}

// ---------------- init: zero accumulators ----------------------------------------
__global__ void k_init() {
    int i = blockIdx.x * 256 + threadIdx.x;
    if (i < Nn * Ff) g_o[i] = 0.f;
    if (i < Nn * Hh) g_wsum[i] = 0.f;
}

// ---------------- cond GEMMs ------------------------------------------------------
__global__ __launch_bounds__(256) void k_cond(const float* __restrict__ cond,
                                              const float* __restrict__ w_mix,
                                              const float* __restrict__ b_mix,
                                              const float* __restrict__ w_mlp,
                                              const float* __restrict__ b_mlp) {
    __shared__ float cs[Aa];
    int g = blockIdx.x;
    int which = blockIdx.y;
    const float* w = which ? w_mlp : w_mix;
    const float* b = which ? b_mlp : b_mix;
    float* outp = which ? g_sb_mlp : g_sb_mix;
    int t = threadIdx.x;
    if (t < Aa) cs[t] = cond[g * Aa + t];
    __syncthreads();
    float acc = b[t];
    #pragma unroll 8
    for (int k = 0; k < Aa; k++) acc = fmaf(cs[k], w[k * F2 + t], acc);
    outp[g * F2 + t] = acc;
}

// ============== node kernel 1 (HMMA, 128-row tile): hh = ada_ln(x) @ w_h + b_h =====
#define N1STR 272
#define N1_OFF_XM 0         // 128*272 = 34816
#define N1_OFF_W  34816     // 256*272 = 69632
#define SM_NODE1  104448

__global__ __launch_bounds__(512) void k_node1(const float* __restrict__ input,
                                               const int* __restrict__ batch,
                                               const float* __restrict__ w_h,
                                               const float* __restrict__ b_h) {
    extern __shared__ __align__(16) char smem_raw[];
    const int tid = threadIdx.x;
    const int warp = tid >> 5, lane = tid & 31;
    const int g = lane >> 2, tg = lane & 3;
    const int nb = blockIdx.x * NTILE;
    char* xm = smem_raw + N1_OFF_XM;
    char* wb = smem_raw + N1_OFF_W;

    // stage w_h^T [256n][128k] bf16 — COALESCED: consecutive threads -> consecutive n
    for (int i = tid; i < 256 * 128; i += 512) {
        int n = i & 255, k = i >> 8;
        *(__nv_bfloat16*)(wb + n * N1STR + k * 2) = __float2bfloat16(w_h[k * F2 + n]);
    }
    // ada_ln(mix) -> xm bf16 (each warp: 8 rows)
    #pragma unroll
    for (int q = 0; q < 8; q++) {
        int r = warp * 8 + q;
        int n = nb + r;
        int nc = n < Nn ? n : Nn - 1;
        float4 x = ((const float4*)(input + (size_t)nc * Ff))[lane];
        float s  = x.x + x.y + x.z + x.w;
        float ss = fmaf(x.x, x.x, fmaf(x.y, x.y, fmaf(x.z, x.z, x.w * x.w)));
        #pragma unroll
        for (int o = 16; o > 0; o >>= 1) {
            s  += __shfl_xor_sync(0xffffffffu, s, o);
            ss += __shfl_xor_sync(0xffffffffu, ss, o);
        }
        float mu = s * (1.f / Ff);
        float rstd = rsqrtf(ss * (1.f / Ff) - mu * mu + 1e-5f);
        int bix = batch[nc];
        const float* sb = g_sb_mix + bix * F2;
        float4 sc = *((const float4*)(sb + lane * 4));
        float4 sh = *((const float4*)(sb + Ff + lane * 4));
        float o0 = (x.x - mu) * rstd * (1.f + sc.x) + sh.x;
        float o1 = (x.y - mu) * rstd * (1.f + sc.y) + sh.y;
        float o2 = (x.z - mu) * rstd * (1.f + sc.z) + sh.z;
        float o3 = (x.w - mu) * rstd * (1.f + sc.w) + sh.w;
        *(uint32_t*)(xm + r * N1STR + lane * 8)     = pack_bf16(o0, o1);
        *(uint32_t*)(xm + r * N1STR + lane * 8 + 4) = pack_bf16(o2, o3);
    }
    __syncthreads();

    const int wr = warp & 7, wq = warp >> 3;
    const int row0 = wr * 16 + g, row1 = row0 + 8;
    const int na = nb + row0, nbr = nb + row1;

    // two N passes of 128 cols each (keeps d[8][4])
    #pragma unroll
    for (int npass = 0; npass < 2; npass++) {
        float d[8][4];
        #pragma unroll
        for (int i = 0; i < 8; i++) { d[i][0]=0.f; d[i][1]=0.f; d[i][2]=0.f; d[i][3]=0.f; }
        #pragma unroll
        for (int ks = 0; ks < 8; ks++) {
            int k0 = ks * 16;
            uint32_t a0 = *(const uint32_t*)(xm + row0 * N1STR + (k0 + 2 * tg) * 2);
            uint32_t a1 = *(const uint32_t*)(xm + row1 * N1STR + (k0 + 2 * tg) * 2);
            uint32_t a2 = *(const uint32_t*)(xm + row0 * N1STR + (k0 + 2 * tg + 8) * 2);
            uint32_t a3 = *(const uint32_t*)(xm + row1 * N1STR + (k0 + 2 * tg + 8) * 2);
            #pragma unroll
            for (int nb2 = 0; nb2 < 8; nb2++) {
                int n0 = npass * 128 + wq * 64 + nb2 * 8;
                uint32_t b0 = *(const uint32_t*)(wb + (n0 + g) * N1STR + (k0 + 2 * tg) * 2);
                uint32_t b1 = *(const uint32_t*)(wb + (n0 + g) * N1STR + (k0 + 2 * tg + 8) * 2);
                mma_bf16(d[nb2], a0, a1, a2, a3, b0, b1);
            }
        }
        float* gout = (npass == 0) ? g_hsrc : g_hdst;
        #pragma unroll
        for (int nb2 = 0; nb2 < 8; nb2++) {
            int c = npass * 128 + wq * 64 + nb2 * 8 + 2 * tg;
            float bb0 = __ldg(b_h + c), bb1 = __ldg(b_h + c + 1);
            int c2 = c - npass * 128;
            if (na < Nn) { float2 v = {d[nb2][0]+bb0, d[nb2][1]+bb1};
                           *(float2*)(gout + (size_t)na * Ff + c2) = v; }
            if (nbr < Nn) { float2 v = {d[nb2][2]+bb0, d[nb2][3]+bb1};
                           *(float2*)(gout + (size_t)nbr * Ff + c2) = v; }
        }
    }
}

// ========================= mma.sync bf16 edge kernel ===============================
#define STRA 144
#define STRB 272
#define OFF_WAT  0
#define OFF_WCT  18432
#define OFF_AN   79360
#define OFF_M    97792
#define OFF_WEXP 132608
#define OFF_SRC  137216
#define OFF_DST  137728
#define OFF_GE   138240
#define OFF_BE   138496
#define OFF_BD   138752
#define SMEDGE   139008

__global__ __launch_bounds__(512) void k_edge(const float* __restrict__ ain,
                                              const int* __restrict__ edges,
                                              const float* __restrict__ w_a,
                                              const float* __restrict__ w_vatt,
                                              const float* __restrict__ w_edge,
                                              const float* __restrict__ gain_e,
                                              const float* __restrict__ bias_e,
                                              const float* __restrict__ b_edge,
                                              float* __restrict__ aout) {
    extern __shared__ __align__(16) char smem_raw[];
    const int tid = threadIdx.x;
    const int warp = tid >> 5, lane = tid & 31;
    const int g = lane >> 2, tg = lane & 3;
    const int wr = warp & 7;
    const int wc = warp >> 3;

    float* wexp_s = (float*)(smem_raw + OFF_WEXP);
    int*   src_s  = (int*)(smem_raw + OFF_SRC);
    int*   dst_s  = (int*)(smem_raw + OFF_DST);
    float* ge_s   = (float*)(smem_raw + OFF_GE);
    float* be_s   = (float*)(smem_raw + OFF_BE);
    float* bd_s   = (float*)(smem_raw + OFF_BD);

    // staging — coalesced index maps (consecutive threads -> consecutive n)
    for (int i = tid; i < 128 * 64; i += 512) {
        int n = i & 127, k = i >> 7;
        *(__nv_bfloat16*)(smem_raw + OFF_WAT + n * STRA + k * 2) =
            __float2bfloat16(w_a[k * Ff + n]);
    }
    for (int i = tid; i < 224 * 128; i += 512) {
        int n = i % 224, k = i / 224;
        float v = 0.f;
        if (n < 136)               v = w_vatt[k * 136 + n];
        else if (n < 200)          v = w_edge[k * EFe + (n - 136)];
        *(__nv_bfloat16*)(smem_raw + OFF_WCT + n * STRB + k * 2) = __float2bfloat16(v);
    }
    if (tid < EFe) { ge_s[tid] = gain_e[tid]; be_s[tid] = bias_e[tid]; bd_s[tid] = b_edge[tid]; }
    __syncthreads();

    for (int tile = blockIdx.x; tile < NTILES; tile += gridDim.x) {
        const int e0 = tile * ETILE;

        if (tid < ETILE) {
            src_s[tid] = edges[e0 + tid];
            dst_s[tid] = edges[Ee + e0 + tid];
        }

        #pragma unroll
        for (int q = 0; q < 8; q++) {
            int r = warp * 8 + q;
            const float* arow = ain + (size_t)(e0 + r) * EFe;
            float x0 = __ldg(arow + lane);
            float x1 = __ldg(arow + lane + 32);
            float s = x0 + x1;
            float ss = fmaf(x0, x0, x1 * x1);
            #pragma unroll
            for (int o = 16; o > 0; o >>= 1) {
                s  += __shfl_xor_sync(0xffffffffu, s, o);
                ss += __shfl_xor_sync(0xffffffffu, ss, o);
            }
            float mu = s * (1.f / EFe);
            float rstd = rsqrtf(ss * (1.f / EFe) - mu * mu + 1e-5f);
            float v0 = (x0 - mu) * rstd * ge_s[lane]      + be_s[lane];
            float v1 = (x1 - mu) * rstd * ge_s[lane + 32] + be_s[lane + 32];
            *(__nv_bfloat16*)(smem_raw + OFF_AN + r * STRA + lane * 2)        = __float2bfloat16(v0);
            *(__nv_bfloat16*)(smem_raw + OFF_AN + r * STRA + (lane + 32) * 2) = __float2bfloat16(v1);
        }
        __syncthreads();

        const int row0 = wr * 16 + g, row1 = row0 + 8;
        const int s0 = src_s[row0], s1 = src_s[row1];

        float d1[8][4];
        #pragma unroll
        for (int i = 0; i < 8; i++) { d1[i][0]=0.f; d1[i][1]=0.f; d1[i][2]=0.f; d1[i][3]=0.f; }
        {
            const char* anp = smem_raw + OFF_AN;
            const char* wap = smem_raw + OFF_WAT;
            #pragma unroll
            for (int ks = 0; ks < 4; ks++) {
                int k0 = ks * 16;
                uint32_t a0 = *(const uint32_t*)(anp + row0 * STRA + (k0 + 2 * tg) * 2);
                uint32_t a1 = *(const uint32_t*)(anp + row1 * STRA + (k0 + 2 * tg) * 2);
                uint32_t a2 = *(const uint32_t*)(anp + row0 * STRA + (k0 + 2 * tg + 8) * 2);
                uint32_t a3 = *(const uint32_t*)(anp + row1 * STRA + (k0 + 2 * tg + 8) * 2);
                #pragma unroll
                for (int nb = 0; nb < 8; nb++) {
                    int n0 = wc * 64 + nb * 8;
                    uint32_t b0 = *(const uint32_t*)(wap + (n0 + g) * STRA + (k0 + 2 * tg) * 2);
                    uint32_t b1 = *(const uint32_t*)(wap + (n0 + g) * STRA + (k0 + 2 * tg + 8) * 2);
                    mma_bf16(d1[nb], a0, a1, a2, a3, b0, b1);
                }
            }
        }

        {
            const int dd0 = dst_s[row0], dd1 = dst_s[row1];
            #pragma unroll
            for (int nb = 0; nb < 8; nb++) {
                int col = wc * 64 + nb * 8 + 2 * tg;
                float2 hs0 = *(const float2*)(g_hsrc + (size_t)s0 * Ff + col);
                float2 hd0 = *(const float2*)(g_hdst + (size_t)dd0 * Ff + col);
                float2 hs1 = *(const float2*)(g_hsrc + (size_t)s1 * Ff + col);
                float2 hd1 = *(const float2*)(g_hdst + (size_t)dd1 * Ff + col);
                float m00 = siluf(d1[nb][0] + hs0.x + hd0.x);
                float m01 = siluf(d1[nb][1] + hs0.y + hd0.y);
                float m10 = siluf(d1[nb][2] + hs1.x + hd1.x);
                float m11 = siluf(d1[nb][3] + hs1.y + hd1.y);
                *(uint32_t*)(smem_raw + OFF_M + row0 * STRB + col * 2) = pack_bf16(m00, m01);
                *(uint32_t*)(smem_raw + OFF_M + row1 * STRB + col * 2) = pack_bf16(m10, m11);
            }
        }
        __syncthreads();

        float d2[14][4];
        #pragma unroll
        for (int i = 0; i < 14; i++) { d2[i][0]=0.f; d2[i][1]=0.f; d2[i][2]=0.f; d2[i][3]=0.f; }
        {
            const char* mp  = smem_raw + OFF_M;
            const char* wcp = smem_raw + OFF_WCT;
            #pragma unroll
            for (int ks = 0; ks < 8; ks++) {
                int k0 = ks * 16;
                uint32_t a0 = *(const uint32_t*)(mp + row0 * STRB + (k0 + 2 * tg) * 2);
                uint32_t a1 = *(const uint32_t*)(mp + row1 * STRB + (k0 + 2 * tg) * 2);
                uint32_t a2 = *(const uint32_t*)(mp + row0 * STRB + (k0 + 2 * tg + 8) * 2);
                uint32_t a3 = *(const uint32_t*)(mp + row1 * STRB + (k0 + 2 * tg + 8) * 2);
                #pragma unroll
                for (int nb = 0; nb < 14; nb++) {
                    int n0 = wc * 112 + nb * 8;
                    uint32_t b0 = *(const uint32_t*)(wcp + (n0 + g) * STRB + (k0 + 2 * tg) * 2);
                    uint32_t b1 = *(const uint32_t*)(wcp + (n0 + g) * STRB + (k0 + 2 * tg + 8) * 2);
                    mma_bf16(d2[nb], a0, a1, a2, a3, b0, b1);
                }
            }
        }

        if (wc == 1) {
            int h = 2 * tg;
            float e00 = __expf(d2[2][0]);
            float e01 = __expf(d2[2][1]);
            float e10 = __expf(d2[2][2]);
            float e11 = __expf(d2[2][3]);
            wexp_s[row0 * 9 + h]     = e00;
            wexp_s[row0 * 9 + h + 1] = e01;
            wexp_s[row1 * 9 + h]     = e10;
            wexp_s[row1 * 9 + h + 1] = e11;
            float* p0 = g_wsum + (size_t)s0 * Hh + h;
            float* p1 = g_wsum + (size_t)s1 * Hh + h;
            asm volatile("red.global.add.f32 [%0], %1;" :: "l"(p0),     "f"(e00) : "memory");
            asm volatile("red.global.add.f32 [%0], %1;" :: "l"(p0 + 1), "f"(e01) : "memory");
            asm volatile("red.global.add.f32 [%0], %1;" :: "l"(p1),     "f"(e10) : "memory");
            asm volatile("red.global.add.f32 [%0], %1;" :: "l"(p1 + 1), "f"(e11) : "memory");
        }
        __syncthreads();

        #pragma unroll
        for (int nb = 0; nb < 14; nb++) {
            int col = wc * 112 + nb * 8 + 2 * tg;
            if (col < Ff) {
                int h = col >> 4;
                float w0 = wexp_s[row0 * 9 + h];
                float w1 = wexp_s[row1 * 9 + h];
                float* o0 = g_o + (size_t)s0 * Ff + col;
                float* o1 = g_o + (size_t)s1 * Ff + col;
                asm volatile("red.global.add.v2.f32 [%0], {%1, %2};"
                             :: "l"(o0), "f"(d2[nb][0] * w0), "f"(d2[nb][1] * w0) : "memory");
                asm volatile("red.global.add.v2.f32 [%0], {%1, %2};"
                             :: "l"(o1), "f"(d2[nb][2] * w1), "f"(d2[nb][3] * w1) : "memory");
            } else if (col >= 136 && col < 200) {
                int k2 = col - 136;
                float2 a0v = *(const float2*)(ain + (size_t)(e0 + row0) * EFe + k2);
                float2 a1v = *(const float2*)(ain + (size_t)(e0 + row1) * EFe + k2);
                float2 r0v, r1v;
                r0v.x = a0v.x + d2[nb][0] + bd_s[k2];
                r0v.y = a0v.y + d2[nb][1] + bd_s[k2 + 1];
                r1v.x = a1v.x + d2[nb][2] + bd_s[k2];
                r1v.y = a1v.y + d2[nb][3] + bd_s[k2 + 1];
                *(float2*)(aout + (size_t)(e0 + row0) * EFe + k2) = r0v;
                *(float2*)(aout + (size_t)(e0 + row1) * EFe + k2) = r1v;
            }
        }
        __syncthreads();
    }
}

// ============== fused node kernel 2 + MLP (HMMA, 128-row tile) =====================
#define N2STR 272
#define OFF2_W  0           // 128*272 = 34816
#define OFF2_XN 34816       // 128*272 = 34816
#define OFF2_T  69632       // 128*272 = 34816
#define OFF2_HM 104448      // 128*136*4 = 69632
#define SM_N2M  174080

__global__ __launch_bounds__(512) void k_node2mlp(const float* __restrict__ input,
                                                  const int* __restrict__ batch,
                                                  const float* __restrict__ w_out,
                                                  const float* __restrict__ b_out,
                                                  const float* __restrict__ w1,
                                                  const float* __restrict__ b1,
                                                  const float* __restrict__ w2,
                                                  const float* __restrict__ b2,
                                                  float* __restrict__ hout) {
    extern __shared__ __align__(16) char smem_raw[];
    const int tid = threadIdx.x;
    const int warp = tid >> 5, lane = tid & 31;
    const int g = lane >> 2, tg = lane & 3;
    const int wr = warp & 7, wq = warp >> 3;
    const int nb = blockIdx.x * NTILE;
    char* wbuf = smem_raw + OFF2_W;
    char* xnb  = smem_raw + OFF2_XN;
    char* tb   = smem_raw + OFF2_T;
    float* hm_s = (float*)(smem_raw + OFF2_HM);

    // stage A = o / wsum (bf16) into T
    for (int i = tid; i < NTILE * 32; i += 512) {
        int r = i >> 5, c4 = i & 31;
        int n = nb + r;
        int nc = n < Nn ? n : Nn - 1;
        float4 o4 = ((const float4*)(g_o + (size_t)nc * Ff))[c4];
        int h = c4 >> 2;
        float inv = 1.f / (g_wsum[nc * Hh + h] + 1e-16f);
        *(uint32_t*)(tb + r * N2STR + c4 * 8)     = pack_bf16(o4.x * inv, o4.y * inv);
        *(uint32_t*)(tb + r * N2STR + c4 * 8 + 4) = pack_bf16(o4.z * inv, o4.w * inv);
    }
    // stage w_out^T bf16 — coalesced
    for (int i = tid; i < 128 * 128; i += 512) {
        int n = i & 127, k = i >> 7;
        *(__nv_bfloat16*)(wbuf + n * N2STR + k * 2) = __float2bfloat16(w_out[k * Ff + n]);
    }
    __syncthreads();

    const int row0 = wr * 16 + g, row1 = row0 + 8;
    const int na = nb + row0, nb1 = nb + row1;
    const int nca = na < Nn ? na : Nn - 1;
    const int ncb = nb1 < Nn ? nb1 : Nn - 1;

    // GEMM: hm = (o/wsum) @ w_out
    {
        float d[8][4];
        #pragma unroll
        for (int i = 0; i < 8; i++) { d[i][0]=0.f; d[i][1]=0.f; d[i][2]=0.f; d[i][3]=0.f; }
        #pragma unroll
        for (int ks = 0; ks < 8; ks++) {
            int k0 = ks * 16;
            uint32_t a0 = *(const uint32_t*)(tb + row0 * N2STR + (k0 + 2 * tg) * 2);
            uint32_t a1 = *(const uint32_t*)(tb + row1 * N2STR + (k0 + 2 * tg) * 2);
            uint32_t a2 = *(const uint32_t*)(tb + row0 * N2STR + (k0 + 2 * tg + 8) * 2);
            uint32_t a3 = *(const uint32_t*)(tb + row1 * N2STR + (k0 + 2 * tg + 8) * 2);
            #pragma unroll
            for (int nb2 = 0; nb2 < 8; nb2++) {
                int n0 = wq * 64 + nb2 * 8;
                uint32_t b0 = *(const uint32_t*)(wbuf + (n0 + g) * N2STR + (k0 + 2 * tg) * 2);
                uint32_t b1 = *(const uint32_t*)(wbuf + (n0 + g) * N2STR + (k0 + 2 * tg + 8) * 2);
                mma_bf16(d[nb2], a0, a1, a2, a3, b0, b1);
            }
        }
        #pragma unroll
        for (int nb2 = 0; nb2 < 8; nb2++) {
            int c = wq * 64 + nb2 * 8 + 2 * tg;
            float2 ia = *(const float2*)(input + (size_t)nca * Ff + c);
            float2 ib = *(const float2*)(input + (size_t)ncb * Ff + c);
            float bb0 = __ldg(b_out + c), bb1 = __ldg(b_out + c + 1);
            hm_s[row0 * 136 + c]     = d[nb2][0] + ia.x + bb0;
            hm_s[row0 * 136 + c + 1] = d[nb2][1] + ia.y + bb1;
            hm_s[row1 * 136 + c]     = d[nb2][2] + ib.x + bb0;
            hm_s[row1 * 136 + c + 1] = d[nb2][3] + ib.y + bb1;
        }
    }
    __syncthreads();

    // ada_ln(mlp) from hm_s -> xn bf16 (each warp: 8 rows)
    #pragma unroll
    for (int q = 0; q < 8; q++) {
        int r = warp * 8 + q;
        int n = nb + r;
        int nc = n < Nn ? n : Nn - 1;
        float4 x = ((const float4*)(hm_s + r * 136))[lane];
        float s  = x.x + x.y + x.z + x.w;
        float ss = fmaf(x.x, x.x, fmaf(x.y, x.y, fmaf(x.z, x.z, x.w * x.w)));
        #pragma unroll
        for (int o = 16; o > 0; o >>= 1) {
            s  += __shfl_xor_sync(0xffffffffu, s, o);
            ss += __shfl_xor_sync(0xffffffffu, ss, o);
        }
        float mu = s * (1.f / Ff);
        float rstd = rsqrtf(ss * (1.f / Ff) - mu * mu + 1e-5f);
        int bix = batch[nc];
        const float* sb = g_sb_mlp + bix * F2;
        float4 sc = *((const float4*)(sb + lane * 4));
        float4 sh = *((const float4*)(sb + Ff + lane * 4));
        float o0 = (x.x - mu) * rstd * (1.f + sc.x) + sh.x;
        float o1 = (x.y - mu) * rstd * (1.f + sc.y) + sh.y;
        float o2 = (x.z - mu) * rstd * (1.f + sc.z) + sh.z;
        float o3 = (x.w - mu) * rstd * (1.f + sc.w) + sh.w;
        *(uint32_t*)(xnb + r * N2STR + lane * 8)     = pack_bf16(o0, o1);
        *(uint32_t*)(xnb + r * N2STR + lane * 8 + 4) = pack_bf16(o2, o3);
    }

    // MLP: oacc accumulates across 4 hidden chunks (MMA layout)
    float oacc[8][4];
    #pragma unroll
    for (int i = 0; i < 8; i++) { oacc[i][0]=0.f; oacc[i][1]=0.f; oacc[i][2]=0.f; oacc[i][3]=0.f; }

    for (int ch = 0; ch < 4; ch++) {
        __syncthreads();   // guards W overwrite + xn/T readiness
        for (int i = tid; i < 128 * 128; i += 512) {
            int n = i & 127, k = i >> 7;
            *(__nv_bfloat16*)(wbuf + n * N2STR + k * 2) =
                __float2bfloat16(w1[k * 512 + ch * 128 + n]);
        }
        __syncthreads();
        float dt[8][4];
        #pragma unroll
        for (int i = 0; i < 8; i++) { dt[i][0]=0.f; dt[i][1]=0.f; dt[i][2]=0.f; dt[i][3]=0.f; }
        #pragma unroll
        for (int ks = 0; ks < 8; ks++) {
            int k0 = ks * 16;
            uint32_t a0 = *(const uint32_t*)(xnb + row0 * N2STR + (k0 + 2 * tg) * 2);
            uint32_t a1 = *(const uint32_t*)(xnb + row1 * N2STR + (k0 + 2 * tg) * 2);
            uint32_t a2 = *(const uint32_t*)(xnb + row0 * N2STR + (k0 + 2 * tg + 8) * 2);
            uint32_t a3 = *(const uint32_t*)(xnb + row1 * N2STR + (k0 + 2 * tg + 8) * 2);
            #pragma unroll
            for (int nb2 = 0; nb2 < 8; nb2++) {
                int n0 = wq * 64 + nb2 * 8;
                uint32_t b0 = *(const uint32_t*)(wbuf + (n0 + g) * N2STR + (k0 + 2 * tg) * 2);
                uint32_t b1 = *(const uint32_t*)(wbuf + (n0 + g) * N2STR + (k0 + 2 * tg + 8) * 2);
                mma_bf16(dt[nb2], a0, a1, a2, a3, b0, b1);
            }
        }
        // silu(+b1) -> T bf16
        #pragma unroll
        for (int nb2 = 0; nb2 < 8; nb2++) {
            int c = wq * 64 + nb2 * 8 + 2 * tg;
            float b10 = __ldg(b1 + ch * 128 + c), b11 = __ldg(b1 + ch * 128 + c + 1);
            *(uint32_t*)(tb + row0 * N2STR + c * 2) =
                pack_bf16(siluf(dt[nb2][0] + b10), siluf(dt[nb2][1] + b11));
            *(uint32_t*)(tb + row1 * N2STR + c * 2) =
                pack_bf16(siluf(dt[nb2][2] + b10), siluf(dt[nb2][3] + b11));
        }
        __syncthreads();
        for (int i = tid; i < 128 * 128; i += 512) {
            int n = i & 127, k = i >> 7;
            *(__nv_bfloat16*)(wbuf + n * N2STR + k * 2) =
                __float2bfloat16(w2[(size_t)(ch * 128 + k) * Ff + n]);
        }
        __syncthreads();
        #pragma unroll
        for (int ks = 0; ks < 8; ks++) {
            int k0 = ks * 16;
            uint32_t a0 = *(const uint32_t*)(tb + row0 * N2STR + (k0 + 2 * tg) * 2);
            uint32_t a1 = *(const uint32_t*)(tb + row1 * N2STR + (k0 + 2 * tg) * 2);
            uint32_t a2 = *(const uint32_t*)(tb + row0 * N2STR + (k0 + 2 * tg + 8) * 2);
            uint32_t a3 = *(const uint32_t*)(tb + row1 * N2STR + (k0 + 2 * tg + 8) * 2);
            #pragma unroll
            for (int nb2 = 0; nb2 < 8; nb2++) {
                int n0 = wq * 64 + nb2 * 8;
                uint32_t b0 = *(const uint32_t*)(wbuf + (n0 + g) * N2STR + (k0 + 2 * tg) * 2);
                uint32_t b1 = *(const uint32_t*)(wbuf + (n0 + g) * N2STR + (k0 + 2 * tg + 8) * 2);
                mma_bf16(oacc[nb2], a0, a1, a2, a3, b0, b1);
            }
        }
    }

    // final: out = oacc + hm + b2
    #pragma unroll
    for (int nb2 = 0; nb2 < 8; nb2++) {
        int c = wq * 64 + nb2 * 8 + 2 * tg;
        float b20 = __ldg(b2 + c), b21 = __ldg(b2 + c + 1);
        if (na < Nn) {
            float2 v = {oacc[nb2][0] + hm_s[row0 * 136 + c]     + b20,
                        oacc[nb2][1] + hm_s[row0 * 136 + c + 1] + b21};
            *(float2*)(hout + (size_t)na * Ff + c) = v;
        }
        if (nb1 < Nn) {
            float2 v = {oacc[nb2][2] + hm_s[row1 * 136 + c]     + b20,
                        oacc[nb2][3] + hm_s[row1 * 136 + c + 1] + b21};
            *(float2*)(hout + (size_t)nb1 * Ff + c) = v;
        }
    }
}

// ---------------- launcher ---------------------------------------------------------
extern "C" void kernel_launch(void* const* d_in, const int* in_sizes, int n_in,
                              void* d_out, int out_size) {
    const float* input     = (const float*)d_in[0];
    const float* cond      = (const float*)d_in[1];
    const float* a         = (const float*)d_in[2];
    const int*   batch     = (const int*)d_in[3];
    const int*   edges     = (const int*)d_in[4];
    const float* w_ada_mix = (const float*)d_in[5];
    const float* b_ada_mix = (const float*)d_in[6];
    const float* w_h       = (const float*)d_in[7];
    const float* b_h       = (const float*)d_in[8];
    const float* w_a       = (const float*)d_in[9];
    const float* w_vatt    = (const float*)d_in[10];
    const float* w_out     = (const float*)d_in[11];
    const float* b_out     = (const float*)d_in[12];
    const float* g_edge_p  = (const float*)d_in[13];
    const float* be_edge_p = (const float*)d_in[14];
    const float* w_edge    = (const float*)d_in[15];
    const float* b_edge    = (const float*)d_in[16];
    const float* w_ada_mlp = (const float*)d_in[17];
    const float* b_ada_mlp = (const float*)d_in[18];
    const float* w1        = (const float*)d_in[19];
    const float* b1        = (const float*)d_in[20];
    const float* w2        = (const float*)d_in[21];
    const float* b2        = (const float*)d_in[22];

    float* hout = (float*)d_out;                       // h: [N, F]
    float* aout = (float*)d_out + (size_t)Nn * Ff;     // a_out: [E, EF]

    cudaFuncSetAttribute(k_node1,    cudaFuncAttributeMaxDynamicSharedMemorySize, SM_NODE1);
    cudaFuncSetAttribute(k_edge,     cudaFuncAttributeMaxDynamicSharedMemorySize, SMEDGE);
    cudaFuncSetAttribute(k_node2mlp, cudaFuncAttributeMaxDynamicSharedMemorySize, SM_N2M);

    const int NT = (Nn + NTILE - 1) / NTILE;  // 157

    k_init<<<(Nn * Ff + 255) / 256, 256>>>();
    k_cond<<<dim3(Gg, 2), 256>>>(cond, w_ada_mix, b_ada_mix, w_ada_mlp, b_ada_mlp);
    k_node1<<<NT, 512, SM_NODE1>>>(input, batch, w_h, b_h);
    k_edge<<<148, 512, SMEDGE>>>(a, edges, w_a, w_vatt, w_edge,
                                 g_edge_p, be_edge_p, b_edge, aout);
    k_node2mlp<<<NT, 512, SM_N2M>>>(input, batch, w_out, b_out, w1, b1, w2, b2, hout);
}

// round 9
// speedup vs baseline: 1.4405x; 1.0169x over previous
#include <cuda_runtime.h>
#include <cuda_bf16.h>
#include <cstdint>
#include <cstddef>

#define Nn 20000
#define Ee 320000
#define Ff 128
#define Hh 8
#define EFe 64
#define Aa 128
#define Gg 32
#define F2 256
#define NTILE 128
#define ETILE 64
#define NTILES (Ee / ETILE)

// ---------------- scratch (device globals; no allocations allowed) ----------------
__device__ float g_sb_mix[Gg * F2];
__device__ float g_sb_mlp[Gg * F2];
__device__ float g_hsrc[(size_t)Nn * Ff];
__device__ float g_hdst[(size_t)Nn * Ff];
__device__ float g_wsum[Nn * Hh];
__device__ float g_o[(size_t)Nn * Ff];

__device__ __forceinline__ float siluf(float x) { return x / (1.f + __expf(-x)); }

// bf16 warp MMA: D[16x8] += A[16x16] * B[16x8], A row-major frags, B col-major frags
__device__ __forceinline__ void mma_bf16(float* d, uint32_t a0, uint32_t a1,
                                         uint32_t a2, uint32_t a3,
                                         uint32_t b0, uint32_t b1) {
    asm volatile(
        "mma.sync.aligned.m16n8k16.row.col.f32.bf16.bf16.f32 "
        "{%0,%1,%2,%3}, {%4,%5,%6,%7}, {%8,%9}, {%0,%1,%2,%3};"
        : "+f"(d[0]), "+f"(d[1]), "+f"(d[2]), "+f"(d[3])
        : "r"(a0), "r"(a1), "r"(a2), "r"(a3), "r"(b0), "r"(b1));
}

__device__ __forceinline__ uint32_t pack_bf16(float a, float b) {
    __nv_bfloat162 p = __floats2bfloat162_rn(a, b);
    return *(uint32_t*)&p;
}

// ---------------- init: zero accumulators ----------------------------------------
__global__ void k_init() {
    int i = blockIdx.x * 256 + threadIdx.x;
    if (i < Nn * Ff) g_o[i] = 0.f;
    if (i < Nn * Hh) g_wsum[i] = 0.f;
}

// ---------------- cond GEMMs ------------------------------------------------------
__global__ __launch_bounds__(256) void k_cond(const float* __restrict__ cond,
                                              const float* __restrict__ w_mix,
                                              const float* __restrict__ b_mix,
                                              const float* __restrict__ w_mlp,
                                              const float* __restrict__ b_mlp) {
    __shared__ float cs[Aa];
    int g = blockIdx.x;
    int which = blockIdx.y;
    const float* w = which ? w_mlp : w_mix;
    const float* b = which ? b_mlp : b_mix;
    float* outp = which ? g_sb_mlp : g_sb_mix;
    int t = threadIdx.x;
    if (t < Aa) cs[t] = cond[g * Aa + t];
    __syncthreads();
    float acc = b[t];
    #pragma unroll 8
    for (int k = 0; k < Aa; k++) acc = fmaf(cs[k], w[k * F2 + t], acc);
    outp[g * F2 + t] = acc;
}

// ============== node kernel 1 (HMMA, 128-row tile): hh = ada_ln(x) @ w_h + b_h =====
#define N1STR 272
#define N1_OFF_XM 0         // 128*272 = 34816
#define N1_OFF_W  34816     // 256*272 = 69632
#define SM_NODE1  104448

__global__ __launch_bounds__(512) void k_node1(const float* __restrict__ input,
                                               const int* __restrict__ batch,
                                               const float* __restrict__ w_h,
                                               const float* __restrict__ b_h) {
    extern __shared__ __align__(16) char smem_raw[];
    const int tid = threadIdx.x;
    const int warp = tid >> 5, lane = tid & 31;
    const int g = lane >> 2, tg = lane & 3;
    const int nb = blockIdx.x * NTILE;
    char* xm = smem_raw + N1_OFF_XM;
    char* wb = smem_raw + N1_OFF_W;

    for (int i = tid; i < 256 * 128; i += 512) {
        int n = i & 255, k = i >> 8;
        *(__nv_bfloat16*)(wb + n * N1STR + k * 2) = __float2bfloat16(w_h[k * F2 + n]);
    }
    #pragma unroll
    for (int q = 0; q < 8; q++) {
        int r = warp * 8 + q;
        int n = nb + r;
        int nc = n < Nn ? n : Nn - 1;
        float4 x = ((const float4*)(input + (size_t)nc * Ff))[lane];
        float s  = x.x + x.y + x.z + x.w;
        float ss = fmaf(x.x, x.x, fmaf(x.y, x.y, fmaf(x.z, x.z, x.w * x.w)));
        #pragma unroll
        for (int o = 16; o > 0; o >>= 1) {
            s  += __shfl_xor_sync(0xffffffffu, s, o);
            ss += __shfl_xor_sync(0xffffffffu, ss, o);
        }
        float mu = s * (1.f / Ff);
        float rstd = rsqrtf(ss * (1.f / Ff) - mu * mu + 1e-5f);
        int bix = batch[nc];
        const float* sb = g_sb_mix + bix * F2;
        float4 sc = *((const float4*)(sb + lane * 4));
        float4 sh = *((const float4*)(sb + Ff + lane * 4));
        float o0 = (x.x - mu) * rstd * (1.f + sc.x) + sh.x;
        float o1 = (x.y - mu) * rstd * (1.f + sc.y) + sh.y;
        float o2 = (x.z - mu) * rstd * (1.f + sc.z) + sh.z;
        float o3 = (x.w - mu) * rstd * (1.f + sc.w) + sh.w;
        *(uint32_t*)(xm + r * N1STR + lane * 8)     = pack_bf16(o0, o1);
        *(uint32_t*)(xm + r * N1STR + lane * 8 + 4) = pack_bf16(o2, o3);
    }
    __syncthreads();

    const int wr = warp & 7, wq = warp >> 3;
    const int row0 = wr * 16 + g, row1 = row0 + 8;
    const int na = nb + row0, nbr = nb + row1;

    #pragma unroll
    for (int npass = 0; npass < 2; npass++) {
        float d[8][4];
        #pragma unroll
        for (int i = 0; i < 8; i++) { d[i][0]=0.f; d[i][1]=0.f; d[i][2]=0.f; d[i][3]=0.f; }
        #pragma unroll
        for (int ks = 0; ks < 8; ks++) {
            int k0 = ks * 16;
            uint32_t a0 = *(const uint32_t*)(xm + row0 * N1STR + (k0 + 2 * tg) * 2);
            uint32_t a1 = *(const uint32_t*)(xm + row1 * N1STR + (k0 + 2 * tg) * 2);
            uint32_t a2 = *(const uint32_t*)(xm + row0 * N1STR + (k0 + 2 * tg + 8) * 2);
            uint32_t a3 = *(const uint32_t*)(xm + row1 * N1STR + (k0 + 2 * tg + 8) * 2);
            #pragma unroll
            for (int nb2 = 0; nb2 < 8; nb2++) {
                int n0 = npass * 128 + wq * 64 + nb2 * 8;
                uint32_t b0 = *(const uint32_t*)(wb + (n0 + g) * N1STR + (k0 + 2 * tg) * 2);
                uint32_t b1 = *(const uint32_t*)(wb + (n0 + g) * N1STR + (k0 + 2 * tg + 8) * 2);
                mma_bf16(d[nb2], a0, a1, a2, a3, b0, b1);
            }
        }
        float* gout = (npass == 0) ? g_hsrc : g_hdst;
        #pragma unroll
        for (int nb2 = 0; nb2 < 8; nb2++) {
            int c = npass * 128 + wq * 64 + nb2 * 8 + 2 * tg;
            float bb0 = __ldg(b_h + c), bb1 = __ldg(b_h + c + 1);
            int c2 = c - npass * 128;
            if (na < Nn) { float2 v = {d[nb2][0]+bb0, d[nb2][1]+bb1};
                           *(float2*)(gout + (size_t)na * Ff + c2) = v; }
            if (nbr < Nn) { float2 v = {d[nb2][2]+bb0, d[nb2][3]+bb1};
                           *(float2*)(gout + (size_t)nbr * Ff + c2) = v; }
        }
    }
}

// ========== mma.sync bf16 edge kernel — 64-edge tile, 2 CTAs/SM ====================
#define STRA 144
#define STRB 272
#define OFF_WAT  0            // 128*144 = 18432
#define OFF_WCT  18432        // 224*272 = 60928 -> 79360
#define OFF_AN   79360        // 64*144  = 9216  -> 88576
#define OFF_M    88576        // 64*272  = 17408 -> 105984
#define OFF_WEXP 105984       // 64*9*4  = 2304  -> 108288
#define OFF_SRC  108288       // 256
#define OFF_DST  108544       // 256
#define OFF_GE   108800       // 256
#define OFF_BE   109056       // 256
#define OFF_BD   109312       // 256
#define SMEDGE   109568       // x2 CTAs = 219136 <= 228KB

__global__ __launch_bounds__(512, 2) void k_edge(const float* __restrict__ ain,
                                                 const int* __restrict__ edges,
                                                 const float* __restrict__ w_a,
                                                 const float* __restrict__ w_vatt,
                                                 const float* __restrict__ w_edge,
                                                 const float* __restrict__ gain_e,
                                                 const float* __restrict__ bias_e,
                                                 const float* __restrict__ b_edge,
                                                 float* __restrict__ aout) {
    extern __shared__ __align__(16) char smem_raw[];
    const int tid = threadIdx.x;
    const int warp = tid >> 5, lane = tid & 31;
    const int g = lane >> 2, tg = lane & 3;
    const int wr = warp & 3;       // M block (16 rows), 4 blocks = 64 rows
    const int wq = warp >> 2;      // N group (0..3)

    float* wexp_s = (float*)(smem_raw + OFF_WEXP);
    int*   src_s  = (int*)(smem_raw + OFF_SRC);
    int*   dst_s  = (int*)(smem_raw + OFF_DST);
    float* ge_s   = (float*)(smem_raw + OFF_GE);
    float* be_s   = (float*)(smem_raw + OFF_BE);
    float* bd_s   = (float*)(smem_raw + OFF_BD);

    // staging — coalesced
    for (int i = tid; i < 128 * 64; i += 512) {
        int n = i & 127, k = i >> 7;
        *(__nv_bfloat16*)(smem_raw + OFF_WAT + n * STRA + k * 2) =
            __float2bfloat16(w_a[k * Ff + n]);
    }
    for (int i = tid; i < 224 * 128; i += 512) {
        int n = i % 224, k = i / 224;
        float v = 0.f;
        if (n < 136)               v = w_vatt[k * 136 + n];
        else if (n < 200)          v = w_edge[k * EFe + (n - 136)];
        *(__nv_bfloat16*)(smem_raw + OFF_WCT + n * STRB + k * 2) = __float2bfloat16(v);
    }
    if (tid < EFe) { ge_s[tid] = gain_e[tid]; be_s[tid] = bias_e[tid]; bd_s[tid] = b_edge[tid]; }
    __syncthreads();

    for (int tile = blockIdx.x; tile < NTILES; tile += gridDim.x) {
        const int e0 = tile * ETILE;

        if (tid < ETILE) {
            src_s[tid] = edges[e0 + tid];
            dst_s[tid] = edges[Ee + e0 + tid];
        }

        // ---- LN(a) -> an (bf16). Each warp: 4 rows ----
        #pragma unroll
        for (int q = 0; q < 4; q++) {
            int r = warp * 4 + q;
            const float* arow = ain + (size_t)(e0 + r) * EFe;
            float x0 = __ldg(arow + lane);
            float x1 = __ldg(arow + lane + 32);
            float s = x0 + x1;
            float ss = fmaf(x0, x0, x1 * x1);
            #pragma unroll
            for (int o = 16; o > 0; o >>= 1) {
                s  += __shfl_xor_sync(0xffffffffu, s, o);
                ss += __shfl_xor_sync(0xffffffffu, ss, o);
            }
            float mu = s * (1.f / EFe);
            float rstd = rsqrtf(ss * (1.f / EFe) - mu * mu + 1e-5f);
            float v0 = (x0 - mu) * rstd * ge_s[lane]      + be_s[lane];
            float v1 = (x1 - mu) * rstd * ge_s[lane + 32] + be_s[lane + 32];
            *(__nv_bfloat16*)(smem_raw + OFF_AN + r * STRA + lane * 2)        = __float2bfloat16(v0);
            *(__nv_bfloat16*)(smem_raw + OFF_AN + r * STRA + (lane + 32) * 2) = __float2bfloat16(v1);
        }
        __syncthreads();

        const int row0 = wr * 16 + g, row1 = row0 + 8;
        const int s0 = src_s[row0], s1 = src_s[row1];

        // ---- GEMM1: D1[64,128] = an[64,64] @ w_a[64,128]; each warp: 32 cols ----
        float d1[4][4];
        #pragma unroll
        for (int i = 0; i < 4; i++) { d1[i][0]=0.f; d1[i][1]=0.f; d1[i][2]=0.f; d1[i][3]=0.f; }
        {
            const char* anp = smem_raw + OFF_AN;
            const char* wap = smem_raw + OFF_WAT;
            #pragma unroll
            for (int ks = 0; ks < 4; ks++) {
                int k0 = ks * 16;
                uint32_t a0 = *(const uint32_t*)(anp + row0 * STRA + (k0 + 2 * tg) * 2);
                uint32_t a1 = *(const uint32_t*)(anp + row1 * STRA + (k0 + 2 * tg) * 2);
                uint32_t a2 = *(const uint32_t*)(anp + row0 * STRA + (k0 + 2 * tg + 8) * 2);
                uint32_t a3 = *(const uint32_t*)(anp + row1 * STRA + (k0 + 2 * tg + 8) * 2);
                #pragma unroll
                for (int nb = 0; nb < 4; nb++) {
                    int n0 = wq * 32 + nb * 8;
                    uint32_t b0 = *(const uint32_t*)(wap + (n0 + g) * STRA + (k0 + 2 * tg) * 2);
                    uint32_t b1 = *(const uint32_t*)(wap + (n0 + g) * STRA + (k0 + 2 * tg + 8) * 2);
                    mma_bf16(d1[nb], a0, a1, a2, a3, b0, b1);
                }
            }
        }

        // ---- epilogue 1: m = silu(D1 + hsrc[src] + hdst[dst]) -> m_s (bf16) ----
        {
            const int dd0 = dst_s[row0], dd1 = dst_s[row1];
            #pragma unroll
            for (int nb = 0; nb < 4; nb++) {
                int col = wq * 32 + nb * 8 + 2 * tg;
                float2 hs0 = *(const float2*)(g_hsrc + (size_t)s0 * Ff + col);
                float2 hd0 = *(const float2*)(g_hdst + (size_t)dd0 * Ff + col);
                float2 hs1 = *(const float2*)(g_hsrc + (size_t)s1 * Ff + col);
                float2 hd1 = *(const float2*)(g_hdst + (size_t)dd1 * Ff + col);
                float m00 = siluf(d1[nb][0] + hs0.x + hd0.x);
                float m01 = siluf(d1[nb][1] + hs0.y + hd0.y);
                float m10 = siluf(d1[nb][2] + hs1.x + hd1.x);
                float m11 = siluf(d1[nb][3] + hs1.y + hd1.y);
                *(uint32_t*)(smem_raw + OFF_M + row0 * STRB + col * 2) = pack_bf16(m00, m01);
                *(uint32_t*)(smem_raw + OFF_M + row1 * STRB + col * 2) = pack_bf16(m10, m11);
            }
        }
        __syncthreads();

        // ---- GEMM2: D2[64,224] = m[64,128] @ wc[128,224]; each warp: 56 cols ----
        float d2[7][4];
        #pragma unroll
        for (int i = 0; i < 7; i++) { d2[i][0]=0.f; d2[i][1]=0.f; d2[i][2]=0.f; d2[i][3]=0.f; }
        {
            const char* mp  = smem_raw + OFF_M;
            const char* wcp = smem_raw + OFF_WCT;
            #pragma unroll
            for (int ks = 0; ks < 8; ks++) {
                int k0 = ks * 16;
                uint32_t a0 = *(const uint32_t*)(mp + row0 * STRB + (k0 + 2 * tg) * 2);
                uint32_t a1 = *(const uint32_t*)(mp + row1 * STRB + (k0 + 2 * tg) * 2);
                uint32_t a2 = *(const uint32_t*)(mp + row0 * STRB + (k0 + 2 * tg + 8) * 2);
                uint32_t a3 = *(const uint32_t*)(mp + row1 * STRB + (k0 + 2 * tg + 8) * 2);
                #pragma unroll
                for (int nb = 0; nb < 7; nb++) {
                    int n0 = wq * 56 + nb * 8;
                    uint32_t b0 = *(const uint32_t*)(wcp + (n0 + g) * STRB + (k0 + 2 * tg) * 2);
                    uint32_t b1 = *(const uint32_t*)(wcp + (n0 + g) * STRB + (k0 + 2 * tg + 8) * 2);
                    mma_bf16(d2[nb], a0, a1, a2, a3, b0, b1);
                }
            }
        }

        // ---- epilogue 2 ----
        // head logits: cols 128..135 = (wq==2, nb==2): col = 112 + 16 + 2tg
        if (wq == 2) {
            int h = 2 * tg;
            float e00 = __expf(d2[2][0]);
            float e01 = __expf(d2[2][1]);
            float e10 = __expf(d2[2][2]);
            float e11 = __expf(d2[2][3]);
            wexp_s[row0 * 9 + h]     = e00;
            wexp_s[row0 * 9 + h + 1] = e01;
            wexp_s[row1 * 9 + h]     = e10;
            wexp_s[row1 * 9 + h + 1] = e11;
            float* p0 = g_wsum + (size_t)s0 * Hh + h;
            float* p1 = g_wsum + (size_t)s1 * Hh + h;
            asm volatile("red.global.add.f32 [%0], %1;" :: "l"(p0),     "f"(e00) : "memory");
            asm volatile("red.global.add.f32 [%0], %1;" :: "l"(p0 + 1), "f"(e01) : "memory");
            asm volatile("red.global.add.f32 [%0], %1;" :: "l"(p1),     "f"(e10) : "memory");
            asm volatile("red.global.add.f32 [%0], %1;" :: "l"(p1 + 1), "f"(e11) : "memory");
        }
        __syncthreads();

        #pragma unroll
        for (int nb = 0; nb < 7; nb++) {
            int col = wq * 56 + nb * 8 + 2 * tg;
            if (col < Ff) {
                int h = col >> 4;
                float w0 = wexp_s[row0 * 9 + h];
                float w1 = wexp_s[row1 * 9 + h];
                float* o0 = g_o + (size_t)s0 * Ff + col;
                float* o1 = g_o + (size_t)s1 * Ff + col;
                asm volatile("red.global.add.v2.f32 [%0], {%1, %2};"
                             :: "l"(o0), "f"(d2[nb][0] * w0), "f"(d2[nb][1] * w0) : "memory");
                asm volatile("red.global.add.v2.f32 [%0], {%1, %2};"
                             :: "l"(o1), "f"(d2[nb][2] * w1), "f"(d2[nb][3] * w1) : "memory");
            } else if (col >= 136 && col < 200) {
                int k2 = col - 136;
                float2 a0v = *(const float2*)(ain + (size_t)(e0 + row0) * EFe + k2);
                float2 a1v = *(const float2*)(ain + (size_t)(e0 + row1) * EFe + k2);
                float2 r0v, r1v;
                r0v.x = a0v.x + d2[nb][0] + bd_s[k2];
                r0v.y = a0v.y + d2[nb][1] + bd_s[k2 + 1];
                r1v.x = a1v.x + d2[nb][2] + bd_s[k2];
                r1v.y = a1v.y + d2[nb][3] + bd_s[k2 + 1];
                *(float2*)(aout + (size_t)(e0 + row0) * EFe + k2) = r0v;
                *(float2*)(aout + (size_t)(e0 + row1) * EFe + k2) = r1v;
            }
        }
        __syncthreads();
    }
}

// ============== fused node kernel 2 + MLP (HMMA, 128-row tile) =====================
#define N2STR 272
#define OFF2_W  0           // 128*272 = 34816
#define OFF2_XN 34816       // 128*272 = 34816
#define OFF2_T  69632       // 128*272 = 34816
#define OFF2_HM 104448      // 128*136*4 = 69632
#define SM_N2M  174080

__global__ __launch_bounds__(512) void k_node2mlp(const float* __restrict__ input,
                                                  const int* __restrict__ batch,
                                                  const float* __restrict__ w_out,
                                                  const float* __restrict__ b_out,
                                                  const float* __restrict__ w1,
                                                  const float* __restrict__ b1,
                                                  const float* __restrict__ w2,
                                                  const float* __restrict__ b2,
                                                  float* __restrict__ hout) {
    extern __shared__ __align__(16) char smem_raw[];
    const int tid = threadIdx.x;
    const int warp = tid >> 5, lane = tid & 31;
    const int g = lane >> 2, tg = lane & 3;
    const int wr = warp & 7, wq = warp >> 3;
    const int nb = blockIdx.x * NTILE;
    char* wbuf = smem_raw + OFF2_W;
    char* xnb  = smem_raw + OFF2_XN;
    char* tb   = smem_raw + OFF2_T;
    float* hm_s = (float*)(smem_raw + OFF2_HM);

    for (int i = tid; i < NTILE * 32; i += 512) {
        int r = i >> 5, c4 = i & 31;
        int n = nb + r;
        int nc = n < Nn ? n : Nn - 1;
        float4 o4 = ((const float4*)(g_o + (size_t)nc * Ff))[c4];
        int h = c4 >> 2;
        float inv = 1.f / (g_wsum[nc * Hh + h] + 1e-16f);
        *(uint32_t*)(tb + r * N2STR + c4 * 8)     = pack_bf16(o4.x * inv, o4.y * inv);
        *(uint32_t*)(tb + r * N2STR + c4 * 8 + 4) = pack_bf16(o4.z * inv, o4.w * inv);
    }
    for (int i = tid; i < 128 * 128; i += 512) {
        int n = i & 127, k = i >> 7;
        *(__nv_bfloat16*)(wbuf + n * N2STR + k * 2) = __float2bfloat16(w_out[k * Ff + n]);
    }
    __syncthreads();

    const int row0 = wr * 16 + g, row1 = row0 + 8;
    const int na = nb + row0, nb1 = nb + row1;
    const int nca = na < Nn ? na : Nn - 1;
    const int ncb = nb1 < Nn ? nb1 : Nn - 1;

    {
        float d[8][4];
        #pragma unroll
        for (int i = 0; i < 8; i++) { d[i][0]=0.f; d[i][1]=0.f; d[i][2]=0.f; d[i][3]=0.f; }
        #pragma unroll
        for (int ks = 0; ks < 8; ks++) {
            int k0 = ks * 16;
            uint32_t a0 = *(const uint32_t*)(tb + row0 * N2STR + (k0 + 2 * tg) * 2);
            uint32_t a1 = *(const uint32_t*)(tb + row1 * N2STR + (k0 + 2 * tg) * 2);
            uint32_t a2 = *(const uint32_t*)(tb + row0 * N2STR + (k0 + 2 * tg + 8) * 2);
            uint32_t a3 = *(const uint32_t*)(tb + row1 * N2STR + (k0 + 2 * tg + 8) * 2);
            #pragma unroll
            for (int nb2 = 0; nb2 < 8; nb2++) {
                int n0 = wq * 64 + nb2 * 8;
                uint32_t b0 = *(const uint32_t*)(wbuf + (n0 + g) * N2STR + (k0 + 2 * tg) * 2);
                uint32_t b1 = *(const uint32_t*)(wbuf + (n0 + g) * N2STR + (k0 + 2 * tg + 8) * 2);
                mma_bf16(d[nb2], a0, a1, a2, a3, b0, b1);
            }
        }
        #pragma unroll
        for (int nb2 = 0; nb2 < 8; nb2++) {
            int c = wq * 64 + nb2 * 8 + 2 * tg;
            float2 ia = *(const float2*)(input + (size_t)nca * Ff + c);
            float2 ib = *(const float2*)(input + (size_t)ncb * Ff + c);
            float bb0 = __ldg(b_out + c), bb1 = __ldg(b_out + c + 1);
            hm_s[row0 * 136 + c]     = d[nb2][0] + ia.x + bb0;
            hm_s[row0 * 136 + c + 1] = d[nb2][1] + ia.y + bb1;
            hm_s[row1 * 136 + c]     = d[nb2][2] + ib.x + bb0;
            hm_s[row1 * 136 + c + 1] = d[nb2][3] + ib.y + bb1;
        }
    }
    __syncthreads();

    #pragma unroll
    for (int q = 0; q < 8; q++) {
        int r = warp * 8 + q;
        int n = nb + r;
        int nc = n < Nn ? n : Nn - 1;
        float4 x = ((const float4*)(hm_s + r * 136))[lane];
        float s  = x.x + x.y + x.z + x.w;
        float ss = fmaf(x.x, x.x, fmaf(x.y, x.y, fmaf(x.z, x.z, x.w * x.w)));
        #pragma unroll
        for (int o = 16; o > 0; o >>= 1) {
            s  += __shfl_xor_sync(0xffffffffu, s, o);
            ss += __shfl_xor_sync(0xffffffffu, ss, o);
        }
        float mu = s * (1.f / Ff);
        float rstd = rsqrtf(ss * (1.f / Ff) - mu * mu + 1e-5f);
        int bix = batch[nc];
        const float* sb = g_sb_mlp + bix * F2;
        float4 sc = *((const float4*)(sb + lane * 4));
        float4 sh = *((const float4*)(sb + Ff + lane * 4));
        float o0 = (x.x - mu) * rstd * (1.f + sc.x) + sh.x;
        float o1 = (x.y - mu) * rstd * (1.f + sc.y) + sh.y;
        float o2 = (x.z - mu) * rstd * (1.f + sc.z) + sh.z;
        float o3 = (x.w - mu) * rstd * (1.f + sc.w) + sh.w;
        *(uint32_t*)(xnb + r * N2STR + lane * 8)     = pack_bf16(o0, o1);
        *(uint32_t*)(xnb + r * N2STR + lane * 8 + 4) = pack_bf16(o2, o3);
    }

    float oacc[8][4];
    #pragma unroll
    for (int i = 0; i < 8; i++) { oacc[i][0]=0.f; oacc[i][1]=0.f; oacc[i][2]=0.f; oacc[i][3]=0.f; }

    for (int ch = 0; ch < 4; ch++) {
        __syncthreads();
        for (int i = tid; i < 128 * 128; i += 512) {
            int n = i & 127, k = i >> 7;
            *(__nv_bfloat16*)(wbuf + n * N2STR + k * 2) =
                __float2bfloat16(w1[k * 512 + ch * 128 + n]);
        }
        __syncthreads();
        float dt[8][4];
        #pragma unroll
        for (int i = 0; i < 8; i++) { dt[i][0]=0.f; dt[i][1]=0.f; dt[i][2]=0.f; dt[i][3]=0.f; }
        #pragma unroll
        for (int ks = 0; ks < 8; ks++) {
            int k0 = ks * 16;
            uint32_t a0 = *(const uint32_t*)(xnb + row0 * N2STR + (k0 + 2 * tg) * 2);
            uint32_t a1 = *(const uint32_t*)(xnb + row1 * N2STR + (k0 + 2 * tg) * 2);
            uint32_t a2 = *(const uint32_t*)(xnb + row0 * N2STR + (k0 + 2 * tg + 8) * 2);
            uint32_t a3 = *(const uint32_t*)(xnb + row1 * N2STR + (k0 + 2 * tg + 8) * 2);
            #pragma unroll
            for (int nb2 = 0; nb2 < 8; nb2++) {
                int n0 = wq * 64 + nb2 * 8;
                uint32_t b0 = *(const uint32_t*)(wbuf + (n0 + g) * N2STR + (k0 + 2 * tg) * 2);
                uint32_t b1 = *(const uint32_t*)(wbuf + (n0 + g) * N2STR + (k0 + 2 * tg + 8) * 2);
                mma_bf16(dt[nb2], a0, a1, a2, a3, b0, b1);
            }
        }
        #pragma unroll
        for (int nb2 = 0; nb2 < 8; nb2++) {
            int c = wq * 64 + nb2 * 8 + 2 * tg;
            float b10 = __ldg(b1 + ch * 128 + c), b11 = __ldg(b1 + ch * 128 + c + 1);
            *(uint32_t*)(tb + row0 * N2STR + c * 2) =
                pack_bf16(siluf(dt[nb2][0] + b10), siluf(dt[nb2][1] + b11));
            *(uint32_t*)(tb + row1 * N2STR + c * 2) =
                pack_bf16(siluf(dt[nb2][2] + b10), siluf(dt[nb2][3] + b11));
        }
        __syncthreads();
        for (int i = tid; i < 128 * 128; i += 512) {
            int n = i & 127, k = i >> 7;
            *(__nv_bfloat16*)(wbuf + n * N2STR + k * 2) =
                __float2bfloat16(w2[(size_t)(ch * 128 + k) * Ff + n]);
        }
        __syncthreads();
        #pragma unroll
        for (int ks = 0; ks < 8; ks++) {
            int k0 = ks * 16;
            uint32_t a0 = *(const uint32_t*)(tb + row0 * N2STR + (k0 + 2 * tg) * 2);
            uint32_t a1 = *(const uint32_t*)(tb + row1 * N2STR + (k0 + 2 * tg) * 2);
            uint32_t a2 = *(const uint32_t*)(tb + row0 * N2STR + (k0 + 2 * tg + 8) * 2);
            uint32_t a3 = *(const uint32_t*)(tb + row1 * N2STR + (k0 + 2 * tg + 8) * 2);
            #pragma unroll
            for (int nb2 = 0; nb2 < 8; nb2++) {
                int n0 = wq * 64 + nb2 * 8;
                uint32_t b0 = *(const uint32_t*)(wbuf + (n0 + g) * N2STR + (k0 + 2 * tg) * 2);
                uint32_t b1 = *(const uint32_t*)(wbuf + (n0 + g) * N2STR + (k0 + 2 * tg + 8) * 2);
                mma_bf16(oacc[nb2], a0, a1, a2, a3, b0, b1);
            }
        }
    }

    #pragma unroll
    for (int nb2 = 0; nb2 < 8; nb2++) {
        int c = wq * 64 + nb2 * 8 + 2 * tg;
        float b20 = __ldg(b2 + c), b21 = __ldg(b2 + c + 1);
        if (na < Nn) {
            float2 v = {oacc[nb2][0] + hm_s[row0 * 136 + c]     + b20,
                        oacc[nb2][1] + hm_s[row0 * 136 + c + 1] + b21};
            *(float2*)(hout + (size_t)na * Ff + c) = v;
        }
        if (nb1 < Nn) {
            float2 v = {oacc[nb2][2] + hm_s[row1 * 136 + c]     + b20,
                        oacc[nb2][3] + hm_s[row1 * 136 + c + 1] + b21};
            *(float2*)(hout + (size_t)nb1 * Ff + c) = v;
        }
    }
}

// ---------------- launcher ---------------------------------------------------------
extern "C" void kernel_launch(void* const* d_in, const int* in_sizes, int n_in,
                              void* d_out, int out_size) {
    const float* input     = (const float*)d_in[0];
    const float* cond      = (const float*)d_in[1];
    const float* a         = (const float*)d_in[2];
    const int*   batch     = (const int*)d_in[3];
    const int*   edges     = (const int*)d_in[4];
    const float* w_ada_mix = (const float*)d_in[5];
    const float* b_ada_mix = (const float*)d_in[6];
    const float* w_h       = (const float*)d_in[7];
    const float* b_h       = (const float*)d_in[8];
    const float* w_a       = (const float*)d_in[9];
    const float* w_vatt    = (const float*)d_in[10];
    const float* w_out     = (const float*)d_in[11];
    const float* b_out     = (const float*)d_in[12];
    const float* g_edge_p  = (const float*)d_in[13];
    const float* be_edge_p = (const float*)d_in[14];
    const float* w_edge    = (const float*)d_in[15];
    const float* b_edge    = (const float*)d_in[16];
    const float* w_ada_mlp = (const float*)d_in[17];
    const float* b_ada_mlp = (const float*)d_in[18];
    const float* w1        = (const float*)d_in[19];
    const float* b1        = (const float*)d_in[20];
    const float* w2        = (const float*)d_in[21];
    const float* b2        = (const float*)d_in[22];

    float* hout = (float*)d_out;                       // h: [N, F]
    float* aout = (float*)d_out + (size_t)Nn * Ff;     // a_out: [E, EF]

    cudaFuncSetAttribute(k_node1,    cudaFuncAttributeMaxDynamicSharedMemorySize, SM_NODE1);
    cudaFuncSetAttribute(k_edge,     cudaFuncAttributeMaxDynamicSharedMemorySize, SMEDGE);
    cudaFuncSetAttribute(k_node2mlp, cudaFuncAttributeMaxDynamicSharedMemorySize, SM_N2M);

    const int NT = (Nn + NTILE - 1) / NTILE;  // 157

    k_init<<<(Nn * Ff + 255) / 256, 256>>>();
    k_cond<<<dim3(Gg, 2), 256>>>(cond, w_ada_mix, b_ada_mix, w_ada_mlp, b_ada_mlp);
    k_node1<<<NT, 512, SM_NODE1>>>(input, batch, w_h, b_h);
    k_edge<<<296, 512, SMEDGE>>>(a, edges, w_a, w_vatt, w_edge,
                                 g_edge_p, be_edge_p, b_edge, aout);
    k_node2mlp<<<NT, 512, SM_N2M>>>(input, batch, w_out, b_out, w1, b1, w2, b2, hout);
}

// round 10
// speedup vs baseline: 1.5911x; 1.1045x over previous
#include <cuda_runtime.h>
#include <cuda_bf16.h>
#include <cstdint>
#include <cstddef>

#define Nn 20000
#define Ee 320000
#define Ff 128
#define Hh 8
#define EFe 64
#define Aa 128
#define Gg 32
#define F2 256
#define NTILE 128
#define ETILE 64
#define NTILES (Ee / ETILE)

// ---------------- scratch (device globals; no allocations allowed) ----------------
__device__ float g_sb_mix[Gg * F2];
__device__ float g_sb_mlp[Gg * F2];
__device__ float g_hsrc[(size_t)Nn * Ff];
__device__ float g_hdst[(size_t)Nn * Ff];
__device__ float g_wsum[Nn * Hh];
__device__ float g_o[(size_t)Nn * Ff];

__device__ __forceinline__ float siluf(float x) { return x / (1.f + __expf(-x)); }

// bf16 warp MMA: D[16x8] += A[16x16] * B[16x8], A row-major frags, B col-major frags
__device__ __forceinline__ void mma_bf16(float* d, uint32_t a0, uint32_t a1,
                                         uint32_t a2, uint32_t a3,
                                         uint32_t b0, uint32_t b1) {
    asm volatile(
        "mma.sync.aligned.m16n8k16.row.col.f32.bf16.bf16.f32 "
        "{%0,%1,%2,%3}, {%4,%5,%6,%7}, {%8,%9}, {%0,%1,%2,%3};"
        : "+f"(d[0]), "+f"(d[1]), "+f"(d[2]), "+f"(d[3])
        : "r"(a0), "r"(a1), "r"(a2), "r"(a3), "r"(b0), "r"(b1));
}

__device__ __forceinline__ uint32_t pack_bf16(float a, float b) {
    __nv_bfloat162 p = __floats2bfloat162_rn(a, b);
    return *(uint32_t*)&p;
}
__device__ __forceinline__ float2 unpack_bf16(uint32_t u) {
    __nv_bfloat162 p = *(__nv_bfloat162*)&u;
    return make_float2(__bfloat162float(p.x), __bfloat162float(p.y));
}

// ---------------- init: zero accumulators ----------------------------------------
__global__ void k_init() {
    int i = blockIdx.x * 256 + threadIdx.x;
    if (i < Nn * Ff) g_o[i] = 0.f;
    if (i < Nn * Hh) g_wsum[i] = 0.f;
}

// ---------------- cond GEMMs ------------------------------------------------------
__global__ __launch_bounds__(256) void k_cond(const float* __restrict__ cond,
                                              const float* __restrict__ w_mix,
                                              const float* __restrict__ b_mix,
                                              const float* __restrict__ w_mlp,
                                              const float* __restrict__ b_mlp) {
    __shared__ float cs[Aa];
    int g = blockIdx.x;
    int which = blockIdx.y;
    const float* w = which ? w_mlp : w_mix;
    const float* b = which ? b_mlp : b_mix;
    float* outp = which ? g_sb_mlp : g_sb_mix;
    int t = threadIdx.x;
    if (t < Aa) cs[t] = cond[g * Aa + t];
    __syncthreads();
    float acc = b[t];
    #pragma unroll 8
    for (int k = 0; k < Aa; k++) acc = fmaf(cs[k], w[k * F2 + t], acc);
    outp[g * F2 + t] = acc;
}

// ============== node kernel 1 (HMMA, 128-row tile): hh = ada_ln(x) @ w_h + b_h =====
#define N1STR 272
#define N1_OFF_XM 0         // 128*272 = 34816
#define N1_OFF_W  34816     // 256*272 = 69632
#define SM_NODE1  104448

__global__ __launch_bounds__(512) void k_node1(const float* __restrict__ input,
                                               const int* __restrict__ batch,
                                               const float* __restrict__ w_h,
                                               const float* __restrict__ b_h) {
    extern __shared__ __align__(16) char smem_raw[];
    const int tid = threadIdx.x;
    const int warp = tid >> 5, lane = tid & 31;
    const int g = lane >> 2, tg = lane & 3;
    const int nb = blockIdx.x * NTILE;
    char* xm = smem_raw + N1_OFF_XM;
    char* wb = smem_raw + N1_OFF_W;

    for (int i = tid; i < 256 * 128; i += 512) {
        int n = i & 255, k = i >> 8;
        *(__nv_bfloat16*)(wb + n * N1STR + k * 2) = __float2bfloat16(w_h[k * F2 + n]);
    }
    #pragma unroll
    for (int q = 0; q < 8; q++) {
        int r = warp * 8 + q;
        int n = nb + r;
        int nc = n < Nn ? n : Nn - 1;
        float4 x = ((const float4*)(input + (size_t)nc * Ff))[lane];
        float s  = x.x + x.y + x.z + x.w;
        float ss = fmaf(x.x, x.x, fmaf(x.y, x.y, fmaf(x.z, x.z, x.w * x.w)));
        #pragma unroll
        for (int o = 16; o > 0; o >>= 1) {
            s  += __shfl_xor_sync(0xffffffffu, s, o);
            ss += __shfl_xor_sync(0xffffffffu, ss, o);
        }
        float mu = s * (1.f / Ff);
        float rstd = rsqrtf(ss * (1.f / Ff) - mu * mu + 1e-5f);
        int bix = batch[nc];
        const float* sb = g_sb_mix + bix * F2;
        float4 sc = *((const float4*)(sb + lane * 4));
        float4 sh = *((const float4*)(sb + Ff + lane * 4));
        float o0 = (x.x - mu) * rstd * (1.f + sc.x) + sh.x;
        float o1 = (x.y - mu) * rstd * (1.f + sc.y) + sh.y;
        float o2 = (x.z - mu) * rstd * (1.f + sc.z) + sh.z;
        float o3 = (x.w - mu) * rstd * (1.f + sc.w) + sh.w;
        *(uint32_t*)(xm + r * N1STR + lane * 8)     = pack_bf16(o0, o1);
        *(uint32_t*)(xm + r * N1STR + lane * 8 + 4) = pack_bf16(o2, o3);
    }
    __syncthreads();

    const int wr = warp & 7, wq = warp >> 3;
    const int row0 = wr * 16 + g, row1 = row0 + 8;
    const int na = nb + row0, nbr = nb + row1;

    #pragma unroll
    for (int npass = 0; npass < 2; npass++) {
        float d[8][4];
        #pragma unroll
        for (int i = 0; i < 8; i++) { d[i][0]=0.f; d[i][1]=0.f; d[i][2]=0.f; d[i][3]=0.f; }
        #pragma unroll
        for (int ks = 0; ks < 8; ks++) {
            int k0 = ks * 16;
            uint32_t a0 = *(const uint32_t*)(xm + row0 * N1STR + (k0 + 2 * tg) * 2);
            uint32_t a1 = *(const uint32_t*)(xm + row1 * N1STR + (k0 + 2 * tg) * 2);
            uint32_t a2 = *(const uint32_t*)(xm + row0 * N1STR + (k0 + 2 * tg + 8) * 2);
            uint32_t a3 = *(const uint32_t*)(xm + row1 * N1STR + (k0 + 2 * tg + 8) * 2);
            #pragma unroll
            for (int nb2 = 0; nb2 < 8; nb2++) {
                int n0 = npass * 128 + wq * 64 + nb2 * 8;
                uint32_t b0 = *(const uint32_t*)(wb + (n0 + g) * N1STR + (k0 + 2 * tg) * 2);
                uint32_t b1 = *(const uint32_t*)(wb + (n0 + g) * N1STR + (k0 + 2 * tg + 8) * 2);
                mma_bf16(d[nb2], a0, a1, a2, a3, b0, b1);
            }
        }
        float* gout = (npass == 0) ? g_hsrc : g_hdst;
        #pragma unroll
        for (int nb2 = 0; nb2 < 8; nb2++) {
            int c = npass * 128 + wq * 64 + nb2 * 8 + 2 * tg;
            float bb0 = __ldg(b_h + c), bb1 = __ldg(b_h + c + 1);
            int c2 = c - npass * 128;
            if (na < Nn) { float2 v = {d[nb2][0]+bb0, d[nb2][1]+bb1};
                           *(float2*)(gout + (size_t)na * Ff + c2) = v; }
            if (nbr < Nn) { float2 v = {d[nb2][2]+bb0, d[nb2][3]+bb1};
                           *(float2*)(gout + (size_t)nbr * Ff + c2) = v; }
        }
    }
}

// ========== mma.sync bf16 edge kernel — 64-edge tile, 2 CTAs/SM, coalesced =========
#define STRA 144
#define STRB 272
#define OFF_WAT  0            // 128*144 = 18432
#define OFF_WCT  18432        // 224*272 = 60928 -> 79360
#define OFF_AN   79360        // 64*144  = 9216  -> 88576
#define OFF_M    88576        // 64*272  = 17408 -> 105984
#define OFF_WEXP 105984       // 64*9*4  = 2304  -> 108288
#define OFF_SRC  108288       // 256
#define OFF_DST  108544       // 256
#define OFF_GE   108800       // 256
#define OFF_BE   109056       // 256
#define OFF_BD   109312       // 256
#define SMEDGE   109568       // x2 CTAs = 219136 <= 228KB

__global__ __launch_bounds__(512, 2) void k_edge(const float* __restrict__ ain,
                                                 const int* __restrict__ edges,
                                                 const float* __restrict__ w_a,
                                                 const float* __restrict__ w_vatt,
                                                 const float* __restrict__ w_edge,
                                                 const float* __restrict__ gain_e,
                                                 const float* __restrict__ bias_e,
                                                 const float* __restrict__ b_edge,
                                                 float* __restrict__ aout) {
    extern __shared__ __align__(16) char smem_raw[];
    const int tid = threadIdx.x;
    const int warp = tid >> 5, lane = tid & 31;
    const int g = lane >> 2, tg = lane & 3;
    const int wr = warp & 3;       // M block (16 rows)
    const int wq = warp >> 2;      // N group (0..3)

    float* wexp_s = (float*)(smem_raw + OFF_WEXP);
    int*   src_s  = (int*)(smem_raw + OFF_SRC);
    int*   dst_s  = (int*)(smem_raw + OFF_DST);
    float* ge_s   = (float*)(smem_raw + OFF_GE);
    float* be_s   = (float*)(smem_raw + OFF_BE);
    float* bd_s   = (float*)(smem_raw + OFF_BD);

    // staging — coalesced
    for (int i = tid; i < 128 * 64; i += 512) {
        int n = i & 127, k = i >> 7;
        *(__nv_bfloat16*)(smem_raw + OFF_WAT + n * STRA + k * 2) =
            __float2bfloat16(w_a[k * Ff + n]);
    }
    for (int i = tid; i < 224 * 128; i += 512) {
        int n = i % 224, k = i / 224;
        float v = 0.f;
        if (n < 136)               v = w_vatt[k * 136 + n];
        else if (n < 200)          v = w_edge[k * EFe + (n - 136)];
        *(__nv_bfloat16*)(smem_raw + OFF_WCT + n * STRB + k * 2) = __float2bfloat16(v);
    }
    if (tid < EFe) { ge_s[tid] = gain_e[tid]; be_s[tid] = bias_e[tid]; bd_s[tid] = b_edge[tid]; }
    __syncthreads();

    for (int tile = blockIdx.x; tile < NTILES; tile += gridDim.x) {
        const int e0 = tile * ETILE;

        if (tid < ETILE) {
            src_s[tid] = edges[e0 + tid];
            dst_s[tid] = edges[Ee + e0 + tid];
        }

        // ---- LN(a) -> an (bf16, packed). Each warp: 4 rows, float2 per lane ----
        #pragma unroll
        for (int q = 0; q < 4; q++) {
            int r = warp * 4 + q;
            float2 x = *(const float2*)(ain + (size_t)(e0 + r) * EFe + 2 * lane);
            float s = x.x + x.y;
            float ss = fmaf(x.x, x.x, x.y * x.y);
            #pragma unroll
            for (int o = 16; o > 0; o >>= 1) {
                s  += __shfl_xor_sync(0xffffffffu, s, o);
                ss += __shfl_xor_sync(0xffffffffu, ss, o);
            }
            float mu = s * (1.f / EFe);
            float rstd = rsqrtf(ss * (1.f / EFe) - mu * mu + 1e-5f);
            float v0 = (x.x - mu) * rstd * ge_s[2 * lane]     + be_s[2 * lane];
            float v1 = (x.y - mu) * rstd * ge_s[2 * lane + 1] + be_s[2 * lane + 1];
            *(uint32_t*)(smem_raw + OFF_AN + r * STRA + lane * 4) = pack_bf16(v0, v1);
        }
        __syncthreads();   // sync1: an + src/dst ready

        // ---- phase A: hsum = hsrc[src] + hdst[dst] -> m_s (bf16, coalesced) ----
        #pragma unroll
        for (int q = 0; q < 4; q++) {
            int r = warp * 4 + q;
            int sr = src_s[r], dr = dst_s[r];
            float4 hs = ((const float4*)(g_hsrc + (size_t)sr * Ff))[lane];
            float4 hd = ((const float4*)(g_hdst + (size_t)dr * Ff))[lane];
            uint2 p;
            p.x = pack_bf16(hs.x + hd.x, hs.y + hd.y);
            p.y = pack_bf16(hs.z + hd.z, hs.w + hd.w);
            *(uint2*)(smem_raw + OFF_M + r * STRB + lane * 8) = p;
        }

        const int row0 = wr * 16 + g, row1 = row0 + 8;
        const int s0 = src_s[row0], s1 = src_s[row1];

        // ---- GEMM1: D1[64,128] = an[64,64] @ w_a[64,128]; each warp: 32 cols ----
        float d1[4][4];
        #pragma unroll
        for (int i = 0; i < 4; i++) { d1[i][0]=0.f; d1[i][1]=0.f; d1[i][2]=0.f; d1[i][3]=0.f; }
        {
            const char* anp = smem_raw + OFF_AN;
            const char* wap = smem_raw + OFF_WAT;
            #pragma unroll
            for (int ks = 0; ks < 4; ks++) {
                int k0 = ks * 16;
                uint32_t a0 = *(const uint32_t*)(anp + row0 * STRA + (k0 + 2 * tg) * 2);
                uint32_t a1 = *(const uint32_t*)(anp + row1 * STRA + (k0 + 2 * tg) * 2);
                uint32_t a2 = *(const uint32_t*)(anp + row0 * STRA + (k0 + 2 * tg + 8) * 2);
                uint32_t a3 = *(const uint32_t*)(anp + row1 * STRA + (k0 + 2 * tg + 8) * 2);
                #pragma unroll
                for (int nb = 0; nb < 4; nb++) {
                    int n0 = wq * 32 + nb * 8;
                    uint32_t b0 = *(const uint32_t*)(wap + (n0 + g) * STRA + (k0 + 2 * tg) * 2);
                    uint32_t b1 = *(const uint32_t*)(wap + (n0 + g) * STRA + (k0 + 2 * tg + 8) * 2);
                    mma_bf16(d1[nb], a0, a1, a2, a3, b0, b1);
                }
            }
        }
        __syncthreads();   // sync2: hsum in m_s ready

        // ---- epilogue 1: m = silu(D1 + hsum) -> m_s (in place, bf16) ----
        #pragma unroll
        for (int nb = 0; nb < 4; nb++) {
            int col = wq * 32 + nb * 8 + 2 * tg;
            float2 h0 = unpack_bf16(*(const uint32_t*)(smem_raw + OFF_M + row0 * STRB + col * 2));
            float2 h1 = unpack_bf16(*(const uint32_t*)(smem_raw + OFF_M + row1 * STRB + col * 2));
            float m00 = siluf(d1[nb][0] + h0.x);
            float m01 = siluf(d1[nb][1] + h0.y);
            float m10 = siluf(d1[nb][2] + h1.x);
            float m11 = siluf(d1[nb][3] + h1.y);
            *(uint32_t*)(smem_raw + OFF_M + row0 * STRB + col * 2) = pack_bf16(m00, m01);
            *(uint32_t*)(smem_raw + OFF_M + row1 * STRB + col * 2) = pack_bf16(m10, m11);
        }
        __syncthreads();   // sync3: m ready

        // ---- GEMM2: D2[64,224] = m[64,128] @ wc[128,224]; each warp: 56 cols ----
        float d2[7][4];
        #pragma unroll
        for (int i = 0; i < 7; i++) { d2[i][0]=0.f; d2[i][1]=0.f; d2[i][2]=0.f; d2[i][3]=0.f; }
        {
            const char* mp  = smem_raw + OFF_M;
            const char* wcp = smem_raw + OFF_WCT;
            #pragma unroll
            for (int ks = 0; ks < 8; ks++) {
                int k0 = ks * 16;
                uint32_t a0 = *(const uint32_t*)(mp + row0 * STRB + (k0 + 2 * tg) * 2);
                uint32_t a1 = *(const uint32_t*)(mp + row1 * STRB + (k0 + 2 * tg) * 2);
                uint32_t a2 = *(const uint32_t*)(mp + row0 * STRB + (k0 + 2 * tg + 8) * 2);
                uint32_t a3 = *(const uint32_t*)(mp + row1 * STRB + (k0 + 2 * tg + 8) * 2);
                #pragma unroll
                for (int nb = 0; nb < 7; nb++) {
                    int n0 = wq * 56 + nb * 8;
                    uint32_t b0 = *(const uint32_t*)(wcp + (n0 + g) * STRB + (k0 + 2 * tg) * 2);
                    uint32_t b1 = *(const uint32_t*)(wcp + (n0 + g) * STRB + (k0 + 2 * tg + 8) * 2);
                    mma_bf16(d2[nb], a0, a1, a2, a3, b0, b1);
                }
            }
        }

        // head logits: cols 128..135 = (wq==2, nb==2)
        if (wq == 2) {
            int h = 2 * tg;
            float e00 = __expf(d2[2][0]);
            float e01 = __expf(d2[2][1]);
            float e10 = __expf(d2[2][2]);
            float e11 = __expf(d2[2][3]);
            wexp_s[row0 * 9 + h]     = e00;
            wexp_s[row0 * 9 + h + 1] = e01;
            wexp_s[row1 * 9 + h]     = e10;
            wexp_s[row1 * 9 + h + 1] = e11;
            float* p0 = g_wsum + (size_t)s0 * Hh + h;
            float* p1 = g_wsum + (size_t)s1 * Hh + h;
            asm volatile("red.global.add.f32 [%0], %1;" :: "l"(p0),     "f"(e00) : "memory");
            asm volatile("red.global.add.f32 [%0], %1;" :: "l"(p0 + 1), "f"(e01) : "memory");
            asm volatile("red.global.add.f32 [%0], %1;" :: "l"(p1),     "f"(e10) : "memory");
            asm volatile("red.global.add.f32 [%0], %1;" :: "l"(p1 + 1), "f"(e11) : "memory");
        }
        __syncthreads();   // sync4: wexp_s ready; all GEMM2 reads of m_s done

        // ---- v-stage: wexp*v -> m_s (bf16); aout epilogue (scattered) ----
        #pragma unroll
        for (int nb = 0; nb < 7; nb++) {
            int col = wq * 56 + nb * 8 + 2 * tg;
            if (col < Ff) {
                int h = col >> 4;
                float w0 = wexp_s[row0 * 9 + h];
                float w1 = wexp_s[row1 * 9 + h];
                *(uint32_t*)(smem_raw + OFF_M + row0 * STRB + col * 2) =
                    pack_bf16(d2[nb][0] * w0, d2[nb][1] * w0);
                *(uint32_t*)(smem_raw + OFF_M + row1 * STRB + col * 2) =
                    pack_bf16(d2[nb][2] * w1, d2[nb][3] * w1);
            } else if (col >= 136 && col < 200) {
                int k2 = col - 136;
                float2 a0v = *(const float2*)(ain + (size_t)(e0 + row0) * EFe + k2);
                float2 a1v = *(const float2*)(ain + (size_t)(e0 + row1) * EFe + k2);
                float2 r0v, r1v;
                r0v.x = a0v.x + d2[nb][0] + bd_s[k2];
                r0v.y = a0v.y + d2[nb][1] + bd_s[k2 + 1];
                r1v.x = a1v.x + d2[nb][2] + bd_s[k2];
                r1v.y = a1v.y + d2[nb][3] + bd_s[k2 + 1];
                *(float2*)(aout + (size_t)(e0 + row0) * EFe + k2) = r0v;
                *(float2*)(aout + (size_t)(e0 + row1) * EFe + k2) = r1v;
            }
        }
        __syncthreads();   // sync5: m_s holds wexp*v for whole tile

        // ---- cooperative coalesced v-reduction into g_o ----
        #pragma unroll
        for (int q = 0; q < 4; q++) {
            int r = warp * 4 + q;
            int sr = src_s[r];
            uint2 p = *(const uint2*)(smem_raw + OFF_M + r * STRB + lane * 8);
            float2 v01 = unpack_bf16(p.x);
            float2 v23 = unpack_bf16(p.y);
            float* ob = g_o + (size_t)sr * Ff + lane * 4;
            asm volatile("red.global.add.v4.f32 [%0], {%1, %2, %3, %4};"
                         :: "l"(ob), "f"(v01.x), "f"(v01.y), "f"(v23.x), "f"(v23.y)
                         : "memory");
        }
        __syncthreads();   // sync6: protect m_s/src_s for next tile
    }
}

// ============== fused node kernel 2 + MLP (HMMA, 128-row tile) =====================
#define N2STR 272
#define OFF2_W  0           // 128*272 = 34816
#define OFF2_XN 34816       // 128*272 = 34816
#define OFF2_T  69632       // 128*272 = 34816
#define OFF2_HM 104448      // 128*136*4 = 69632
#define SM_N2M  174080

__global__ __launch_bounds__(512) void k_node2mlp(const float* __restrict__ input,
                                                  const int* __restrict__ batch,
                                                  const float* __restrict__ w_out,
                                                  const float* __restrict__ b_out,
                                                  const float* __restrict__ w1,
                                                  const float* __restrict__ b1,
                                                  const float* __restrict__ w2,
                                                  const float* __restrict__ b2,
                                                  float* __restrict__ hout) {
    extern __shared__ __align__(16) char smem_raw[];
    const int tid = threadIdx.x;
    const int warp = tid >> 5, lane = tid & 31;
    const int g = lane >> 2, tg = lane & 3;
    const int wr = warp & 7, wq = warp >> 3;
    const int nb = blockIdx.x * NTILE;
    char* wbuf = smem_raw + OFF2_W;
    char* xnb  = smem_raw + OFF2_XN;
    char* tb   = smem_raw + OFF2_T;
    float* hm_s = (float*)(smem_raw + OFF2_HM);

    for (int i = tid; i < NTILE * 32; i += 512) {
        int r = i >> 5, c4 = i & 31;
        int n = nb + r;
        int nc = n < Nn ? n : Nn - 1;
        float4 o4 = ((const float4*)(g_o + (size_t)nc * Ff))[c4];
        int h = c4 >> 2;
        float inv = 1.f / (g_wsum[nc * Hh + h] + 1e-16f);
        *(uint32_t*)(tb + r * N2STR + c4 * 8)     = pack_bf16(o4.x * inv, o4.y * inv);
        *(uint32_t*)(tb + r * N2STR + c4 * 8 + 4) = pack_bf16(o4.z * inv, o4.w * inv);
    }
    for (int i = tid; i < 128 * 128; i += 512) {
        int n = i & 127, k = i >> 7;
        *(__nv_bfloat16*)(wbuf + n * N2STR + k * 2) = __float2bfloat16(w_out[k * Ff + n]);
    }
    __syncthreads();

    const int row0 = wr * 16 + g, row1 = row0 + 8;
    const int na = nb + row0, nb1 = nb + row1;
    const int nca = na < Nn ? na : Nn - 1;
    const int ncb = nb1 < Nn ? nb1 : Nn - 1;

    {
        float d[8][4];
        #pragma unroll
        for (int i = 0; i < 8; i++) { d[i][0]=0.f; d[i][1]=0.f; d[i][2]=0.f; d[i][3]=0.f; }
        #pragma unroll
        for (int ks = 0; ks < 8; ks++) {
            int k0 = ks * 16;
            uint32_t a0 = *(const uint32_t*)(tb + row0 * N2STR + (k0 + 2 * tg) * 2);
            uint32_t a1 = *(const uint32_t*)(tb + row1 * N2STR + (k0 + 2 * tg) * 2);
            uint32_t a2 = *(const uint32_t*)(tb + row0 * N2STR + (k0 + 2 * tg + 8) * 2);
            uint32_t a3 = *(const uint32_t*)(tb + row1 * N2STR + (k0 + 2 * tg + 8) * 2);
            #pragma unroll
            for (int nb2 = 0; nb2 < 8; nb2++) {
                int n0 = wq * 64 + nb2 * 8;
                uint32_t b0 = *(const uint32_t*)(wbuf + (n0 + g) * N2STR + (k0 + 2 * tg) * 2);
                uint32_t b1 = *(const uint32_t*)(wbuf + (n0 + g) * N2STR + (k0 + 2 * tg + 8) * 2);
                mma_bf16(d[nb2], a0, a1, a2, a3, b0, b1);
            }
        }
        #pragma unroll
        for (int nb2 = 0; nb2 < 8; nb2++) {
            int c = wq * 64 + nb2 * 8 + 2 * tg;
            float2 ia = *(const float2*)(input + (size_t)nca * Ff + c);
            float2 ib = *(const float2*)(input + (size_t)ncb * Ff + c);
            float bb0 = __ldg(b_out + c), bb1 = __ldg(b_out + c + 1);
            hm_s[row0 * 136 + c]     = d[nb2][0] + ia.x + bb0;
            hm_s[row0 * 136 + c + 1] = d[nb2][1] + ia.y + bb1;
            hm_s[row1 * 136 + c]     = d[nb2][2] + ib.x + bb0;
            hm_s[row1 * 136 + c + 1] = d[nb2][3] + ib.y + bb1;
        }
    }
    __syncthreads();

    #pragma unroll
    for (int q = 0; q < 8; q++) {
        int r = warp * 8 + q;
        int n = nb + r;
        int nc = n < Nn ? n : Nn - 1;
        float4 x = ((const float4*)(hm_s + r * 136))[lane];
        float s  = x.x + x.y + x.z + x.w;
        float ss = fmaf(x.x, x.x, fmaf(x.y, x.y, fmaf(x.z, x.z, x.w * x.w)));
        #pragma unroll
        for (int o = 16; o > 0; o >>= 1) {
            s  += __shfl_xor_sync(0xffffffffu, s, o);
            ss += __shfl_xor_sync(0xffffffffu, ss, o);
        }
        float mu = s * (1.f / Ff);
        float rstd = rsqrtf(ss * (1.f / Ff) - mu * mu + 1e-5f);
        int bix = batch[nc];
        const float* sb = g_sb_mlp + bix * F2;
        float4 sc = *((const float4*)(sb + lane * 4));
        float4 sh = *((const float4*)(sb + Ff + lane * 4));
        float o0 = (x.x - mu) * rstd * (1.f + sc.x) + sh.x;
        float o1 = (x.y - mu) * rstd * (1.f + sc.y) + sh.y;
        float o2 = (x.z - mu) * rstd * (1.f + sc.z) + sh.z;
        float o3 = (x.w - mu) * rstd * (1.f + sc.w) + sh.w;
        *(uint32_t*)(xnb + r * N2STR + lane * 8)     = pack_bf16(o0, o1);
        *(uint32_t*)(xnb + r * N2STR + lane * 8 + 4) = pack_bf16(o2, o3);
    }

    float oacc[8][4];
    #pragma unroll
    for (int i = 0; i < 8; i++) { oacc[i][0]=0.f; oacc[i][1]=0.f; oacc[i][2]=0.f; oacc[i][3]=0.f; }

    for (int ch = 0; ch < 4; ch++) {
        __syncthreads();
        for (int i = tid; i < 128 * 128; i += 512) {
            int n = i & 127, k = i >> 7;
            *(__nv_bfloat16*)(wbuf + n * N2STR + k * 2) =
                __float2bfloat16(w1[k * 512 + ch * 128 + n]);
        }
        __syncthreads();
        float dt[8][4];
        #pragma unroll
        for (int i = 0; i < 8; i++) { dt[i][0]=0.f; dt[i][1]=0.f; dt[i][2]=0.f; dt[i][3]=0.f; }
        #pragma unroll
        for (int ks = 0; ks < 8; ks++) {
            int k0 = ks * 16;
            uint32_t a0 = *(const uint32_t*)(xnb + row0 * N2STR + (k0 + 2 * tg) * 2);
            uint32_t a1 = *(const uint32_t*)(xnb + row1 * N2STR + (k0 + 2 * tg) * 2);
            uint32_t a2 = *(const uint32_t*)(xnb + row0 * N2STR + (k0 + 2 * tg + 8) * 2);
            uint32_t a3 = *(const uint32_t*)(xnb + row1 * N2STR + (k0 + 2 * tg + 8) * 2);
            #pragma unroll
            for (int nb2 = 0; nb2 < 8; nb2++) {
                int n0 = wq * 64 + nb2 * 8;
                uint32_t b0 = *(const uint32_t*)(wbuf + (n0 + g) * N2STR + (k0 + 2 * tg) * 2);
                uint32_t b1 = *(const uint32_t*)(wbuf + (n0 + g) * N2STR + (k0 + 2 * tg + 8) * 2);
                mma_bf16(dt[nb2], a0, a1, a2, a3, b0, b1);
            }
        }
        #pragma unroll
        for (int nb2 = 0; nb2 < 8; nb2++) {
            int c = wq * 64 + nb2 * 8 + 2 * tg;
            float b10 = __ldg(b1 + ch * 128 + c), b11 = __ldg(b1 + ch * 128 + c + 1);
            *(uint32_t*)(tb + row0 * N2STR + c * 2) =
                pack_bf16(siluf(dt[nb2][0] + b10), siluf(dt[nb2][1] + b11));
            *(uint32_t*)(tb + row1 * N2STR + c * 2) =
                pack_bf16(siluf(dt[nb2][2] + b10), siluf(dt[nb2][3] + b11));
        }
        __syncthreads();
        for (int i = tid; i < 128 * 128; i += 512) {
            int n = i & 127, k = i >> 7;
            *(__nv_bfloat16*)(wbuf + n * N2STR + k * 2) =
                __float2bfloat16(w2[(size_t)(ch * 128 + k) * Ff + n]);
        }
        __syncthreads();
        #pragma unroll
        for (int ks = 0; ks < 8; ks++) {
            int k0 = ks * 16;
            uint32_t a0 = *(const uint32_t*)(tb + row0 * N2STR + (k0 + 2 * tg) * 2);
            uint32_t a1 = *(const uint32_t*)(tb + row1 * N2STR + (k0 + 2 * tg) * 2);
            uint32_t a2 = *(const uint32_t*)(tb + row0 * N2STR + (k0 + 2 * tg + 8) * 2);
            uint32_t a3 = *(const uint32_t*)(tb + row1 * N2STR + (k0 + 2 * tg + 8) * 2);
            #pragma unroll
            for (int nb2 = 0; nb2 < 8; nb2++) {
                int n0 = wq * 64 + nb2 * 8;
                uint32_t b0 = *(const uint32_t*)(wbuf + (n0 + g) * N2STR + (k0 + 2 * tg) * 2);
                uint32_t b1 = *(const uint32_t*)(wbuf + (n0 + g) * N2STR + (k0 + 2 * tg + 8) * 2);
                mma_bf16(oacc[nb2], a0, a1, a2, a3, b0, b1);
            }
        }
    }

    #pragma unroll
    for (int nb2 = 0; nb2 < 8; nb2++) {
        int c = wq * 64 + nb2 * 8 + 2 * tg;
        float b20 = __ldg(b2 + c), b21 = __ldg(b2 + c + 1);
        if (na < Nn) {
            float2 v = {oacc[nb2][0] + hm_s[row0 * 136 + c]     + b20,
                        oacc[nb2][1] + hm_s[row0 * 136 + c + 1] + b21};
            *(float2*)(hout + (size_t)na * Ff + c) = v;
        }
        if (nb1 < Nn) {
            float2 v = {oacc[nb2][2] + hm_s[row1 * 136 + c]     + b20,
                        oacc[nb2][3] + hm_s[row1 * 136 + c + 1] + b21};
            *(float2*)(hout + (size_t)nb1 * Ff + c) = v;
        }
    }
}

// ---------------- launcher ---------------------------------------------------------
extern "C" void kernel_launch(void* const* d_in, const int* in_sizes, int n_in,
                              void* d_out, int out_size) {
    const float* input     = (const float*)d_in[0];
    const float* cond      = (const float*)d_in[1];
    const float* a         = (const float*)d_in[2];
    const int*   batch     = (const int*)d_in[3];
    const int*   edges     = (const int*)d_in[4];
    const float* w_ada_mix = (const float*)d_in[5];
    const float* b_ada_mix = (const float*)d_in[6];
    const float* w_h       = (const float*)d_in[7];
    const float* b_h       = (const float*)d_in[8];
    const float* w_a       = (const float*)d_in[9];
    const float* w_vatt    = (const float*)d_in[10];
    const float* w_out     = (const float*)d_in[11];
    const float* b_out     = (const float*)d_in[12];
    const float* g_edge_p  = (const float*)d_in[13];
    const float* be_edge_p = (const float*)d_in[14];
    const float* w_edge    = (const float*)d_in[15];
    const float* b_edge    = (const float*)d_in[16];
    const float* w_ada_mlp = (const float*)d_in[17];
    const float* b_ada_mlp = (const float*)d_in[18];
    const float* w1        = (const float*)d_in[19];
    const float* b1        = (const float*)d_in[20];
    const float* w2        = (const float*)d_in[21];
    const float* b2        = (const float*)d_in[22];

    float* hout = (float*)d_out;                       // h: [N, F]
    float* aout = (float*)d_out + (size_t)Nn * Ff;     // a_out: [E, EF]

    cudaFuncSetAttribute(k_node1,    cudaFuncAttributeMaxDynamicSharedMemorySize, SM_NODE1);
    cudaFuncSetAttribute(k_edge,     cudaFuncAttributeMaxDynamicSharedMemorySize, SMEDGE);
    cudaFuncSetAttribute(k_node2mlp, cudaFuncAttributeMaxDynamicSharedMemorySize, SM_N2M);

    const int NT = (Nn + NTILE - 1) / NTILE;  // 157

    k_init<<<(Nn * Ff + 255) / 256, 256>>>();
    k_cond<<<dim3(Gg, 2), 256>>>(cond, w_ada_mix, b_ada_mix, w_ada_mlp, b_ada_mlp);
    k_node1<<<NT, 512, SM_NODE1>>>(input, batch, w_h, b_h);
    k_edge<<<296, 512, SMEDGE>>>(a, edges, w_a, w_vatt, w_edge,
                                 g_edge_p, be_edge_p, b_edge, aout);
    k_node2mlp<<<NT, 512, SM_N2M>>>(input, batch, w_out, b_out, w1, b1, w2, b2, hout);
}

// round 11
// speedup vs baseline: 1.6488x; 1.0363x over previous
#include <cuda_runtime.h>
#include <cuda_bf16.h>
#include <cstdint>
#include <cstddef>

#define Nn 20000
#define Ee 320000
#define Ff 128
#define Hh 8
#define EFe 64
#define Aa 128
#define Gg 32
#define F2 256
#define NTILE 128
#define ETILE 64
#define NTILES (Ee / ETILE)

// ---------------- scratch (device globals; no allocations allowed) ----------------
__device__ float g_sb_mix[Gg * F2];
__device__ float g_sb_mlp[Gg * F2];
__device__ float g_hsrc[(size_t)Nn * Ff];
__device__ float g_hdst[(size_t)Nn * Ff];
__device__ float g_wsum[Nn * Hh];
__device__ float g_o[(size_t)Nn * Ff];

__device__ __forceinline__ float siluf(float x) { return x / (1.f + __expf(-x)); }

// bf16 warp MMA: D[16x8] += A[16x16] * B[16x8]
__device__ __forceinline__ void mma_bf16(float* d, uint32_t a0, uint32_t a1,
                                         uint32_t a2, uint32_t a3,
                                         uint32_t b0, uint32_t b1) {
    asm volatile(
        "mma.sync.aligned.m16n8k16.row.col.f32.bf16.bf16.f32 "
        "{%0,%1,%2,%3}, {%4,%5,%6,%7}, {%8,%9}, {%0,%1,%2,%3};"
        : "+f"(d[0]), "+f"(d[1]), "+f"(d[2]), "+f"(d[3])
        : "r"(a0), "r"(a1), "r"(a2), "r"(a3), "r"(b0), "r"(b1));
}

__device__ __forceinline__ void ldsm_x4(uint32_t& r0, uint32_t& r1,
                                        uint32_t& r2, uint32_t& r3, uint32_t addr) {
    asm volatile("ldmatrix.sync.aligned.m8n8.x4.shared.b16 {%0,%1,%2,%3}, [%4];"
                 : "=r"(r0), "=r"(r1), "=r"(r2), "=r"(r3) : "r"(addr));
}
__device__ __forceinline__ void ldsm_x2(uint32_t& r0, uint32_t& r1, uint32_t addr) {
    asm volatile("ldmatrix.sync.aligned.m8n8.x2.shared.b16 {%0,%1}, [%2];"
                 : "=r"(r0), "=r"(r1) : "r"(addr));
}

__device__ __forceinline__ uint32_t pack_bf16(float a, float b) {
    __nv_bfloat162 p = __floats2bfloat162_rn(a, b);
    return *(uint32_t*)&p;
}
__device__ __forceinline__ float2 unpack_bf16(uint32_t u) {
    __nv_bfloat162 p = *(__nv_bfloat162*)&u;
    return make_float2(__bfloat162float(p.x), __bfloat162float(p.y));
}

// ---------------- init: zero accumulators ----------------------------------------
__global__ void k_init() {
    int i = blockIdx.x * 256 + threadIdx.x;
    if (i < Nn * Ff) g_o[i] = 0.f;
    if (i < Nn * Hh) g_wsum[i] = 0.f;
}

// ---------------- cond GEMMs ------------------------------------------------------
__global__ __launch_bounds__(256) void k_cond(const float* __restrict__ cond,
                                              const float* __restrict__ w_mix,
                                              const float* __restrict__ b_mix,
                                              const float* __restrict__ w_mlp,
                                              const float* __restrict__ b_mlp) {
    __shared__ float cs[Aa];
    int g = blockIdx.x;
    int which = blockIdx.y;
    const float* w = which ? w_mlp : w_mix;
    const float* b = which ? b_mlp : b_mix;
    float* outp = which ? g_sb_mlp : g_sb_mix;
    int t = threadIdx.x;
    if (t < Aa) cs[t] = cond[g * Aa + t];
    __syncthreads();
    float acc = b[t];
    #pragma unroll 8
    for (int k = 0; k < Aa; k++) acc = fmaf(cs[k], w[k * F2 + t], acc);
    outp[g * F2 + t] = acc;
}

// ============== node kernel 1 (HMMA, 128-row tile): hh = ada_ln(x) @ w_h + b_h =====
#define N1STR 272
#define N1_OFF_XM 0         // 128*272 = 34816
#define N1_OFF_W  34816     // 256*272 = 69632
#define SM_NODE1  104448

__global__ __launch_bounds__(512) void k_node1(const float* __restrict__ input,
                                               const int* __restrict__ batch,
                                               const float* __restrict__ w_h,
                                               const float* __restrict__ b_h) {
    extern __shared__ __align__(16) char smem_raw[];
    const uint32_t smemU = (uint32_t)__cvta_generic_to_shared(smem_raw);
    const int tid = threadIdx.x;
    const int warp = tid >> 5, lane = tid & 31;
    const int nb = blockIdx.x * NTILE;
    char* xm = smem_raw + N1_OFF_XM;
    char* wb = smem_raw + N1_OFF_W;

    // ldmatrix per-lane offsets (stride 272)
    const uint32_t aoff = ((lane & 7) + ((lane >> 3) & 1) * 8) * 272 + ((lane >> 4) & 1) * 16;
    const uint32_t boff = (lane & 7) * 272 + ((lane >> 3) & 1) * 16;

    for (int i = tid; i < 256 * 128; i += 512) {
        int n = i & 255, k = i >> 8;
        *(__nv_bfloat16*)(wb + n * N1STR + k * 2) = __float2bfloat16(w_h[k * F2 + n]);
    }
    #pragma unroll
    for (int q = 0; q < 8; q++) {
        int r = warp * 8 + q;
        int n = nb + r;
        int nc = n < Nn ? n : Nn - 1;
        float4 x = ((const float4*)(input + (size_t)nc * Ff))[lane];
        float s  = x.x + x.y + x.z + x.w;
        float ss = fmaf(x.x, x.x, fmaf(x.y, x.y, fmaf(x.z, x.z, x.w * x.w)));
        #pragma unroll
        for (int o = 16; o > 0; o >>= 1) {
            s  += __shfl_xor_sync(0xffffffffu, s, o);
            ss += __shfl_xor_sync(0xffffffffu, ss, o);
        }
        float mu = s * (1.f / Ff);
        float rstd = rsqrtf(ss * (1.f / Ff) - mu * mu + 1e-5f);
        int bix = batch[nc];
        const float* sb = g_sb_mix + bix * F2;
        float4 sc = *((const float4*)(sb + lane * 4));
        float4 sh = *((const float4*)(sb + Ff + lane * 4));
        float o0 = (x.x - mu) * rstd * (1.f + sc.x) + sh.x;
        float o1 = (x.y - mu) * rstd * (1.f + sc.y) + sh.y;
        float o2 = (x.z - mu) * rstd * (1.f + sc.z) + sh.z;
        float o3 = (x.w - mu) * rstd * (1.f + sc.w) + sh.w;
        *(uint32_t*)(xm + r * N1STR + lane * 8)     = pack_bf16(o0, o1);
        *(uint32_t*)(xm + r * N1STR + lane * 8 + 4) = pack_bf16(o2, o3);
    }
    __syncthreads();

    const int wr = warp & 7, wq = warp >> 3;
    const int row0 = wr * 16 + (lane >> 2);
    const int na = nb + row0, nbr = na + 8;
    const uint32_t aBase = smemU + N1_OFF_XM + wr * 16 * N1STR + aoff;

    #pragma unroll
    for (int npass = 0; npass < 2; npass++) {
        float d[8][4];
        #pragma unroll
        for (int i = 0; i < 8; i++) { d[i][0]=0.f; d[i][1]=0.f; d[i][2]=0.f; d[i][3]=0.f; }
        #pragma unroll
        for (int ks = 0; ks < 8; ks++) {
            uint32_t a0, a1, a2, a3;
            ldsm_x4(a0, a1, a2, a3, aBase + ks * 32);
            #pragma unroll
            for (int nb2 = 0; nb2 < 8; nb2++) {
                int n0 = npass * 128 + wq * 64 + nb2 * 8;
                uint32_t b0, b1;
                ldsm_x2(b0, b1, smemU + N1_OFF_W + n0 * N1STR + boff + ks * 32);
                mma_bf16(d[nb2], a0, a1, a2, a3, b0, b1);
            }
        }
        float* gout = (npass == 0) ? g_hsrc : g_hdst;
        int tg = lane & 3;
        #pragma unroll
        for (int nb2 = 0; nb2 < 8; nb2++) {
            int c = npass * 128 + wq * 64 + nb2 * 8 + 2 * tg;
            float bb0 = __ldg(b_h + c), bb1 = __ldg(b_h + c + 1);
            int c2 = c - npass * 128;
            if (na < Nn) { float2 v = {d[nb2][0]+bb0, d[nb2][1]+bb1};
                           *(float2*)(gout + (size_t)na * Ff + c2) = v; }
            if (nbr < Nn) { float2 v = {d[nb2][2]+bb0, d[nb2][3]+bb1};
                           *(float2*)(gout + (size_t)nbr * Ff + c2) = v; }
        }
    }
}

// ========== mma.sync bf16 edge kernel — 64-edge tile, 2 CTAs/SM, ldmatrix ==========
#define STRA 144
#define STRB 272
#define OFF_WAT  0            // 128*144 = 18432
#define OFF_WCT  18432        // 224*272 = 60928 -> 79360
#define OFF_AN   79360        // 64*144  = 9216  -> 88576
#define OFF_M    88576        // 64*272  = 17408 -> 105984
#define OFF_WEXP 105984       // 64*9*4  = 2304  -> 108288
#define OFF_SRC  108288
#define OFF_DST  108544
#define OFF_GE   108800
#define OFF_BE   109056
#define OFF_BD   109312
#define SMEDGE   109568       // x2 CTAs = 219136 <= 228KB

__global__ __launch_bounds__(512, 2) void k_edge(const float* __restrict__ ain,
                                                 const int* __restrict__ edges,
                                                 const float* __restrict__ w_a,
                                                 const float* __restrict__ w_vatt,
                                                 const float* __restrict__ w_edge,
                                                 const float* __restrict__ gain_e,
                                                 const float* __restrict__ bias_e,
                                                 const float* __restrict__ b_edge,
                                                 float* __restrict__ aout) {
    extern __shared__ __align__(16) char smem_raw[];
    const uint32_t smemU = (uint32_t)__cvta_generic_to_shared(smem_raw);
    const int tid = threadIdx.x;
    const int warp = tid >> 5, lane = tid & 31;
    const int g = lane >> 2, tg = lane & 3;
    const int wr = warp & 3;       // M block (16 rows)
    const int wq = warp >> 2;      // N group (0..3)

    float* wexp_s = (float*)(smem_raw + OFF_WEXP);
    int*   src_s  = (int*)(smem_raw + OFF_SRC);
    int*   dst_s  = (int*)(smem_raw + OFF_DST);
    float* ge_s   = (float*)(smem_raw + OFF_GE);
    float* be_s   = (float*)(smem_raw + OFF_BE);
    float* bd_s   = (float*)(smem_raw + OFF_BD);

    // ldmatrix per-lane offsets
    const uint32_t aoffA = ((lane & 7) + ((lane >> 3) & 1) * 8) * STRA + ((lane >> 4) & 1) * 16;
    const uint32_t boffA = (lane & 7) * STRA + ((lane >> 3) & 1) * 16;
    const uint32_t aoffB = ((lane & 7) + ((lane >> 3) & 1) * 8) * STRB + ((lane >> 4) & 1) * 16;
    const uint32_t boffB = (lane & 7) * STRB + ((lane >> 3) & 1) * 16;

    // staging — coalesced
    for (int i = tid; i < 128 * 64; i += 512) {
        int n = i & 127, k = i >> 7;
        *(__nv_bfloat16*)(smem_raw + OFF_WAT + n * STRA + k * 2) =
            __float2bfloat16(w_a[k * Ff + n]);
    }
    for (int i = tid; i < 224 * 128; i += 512) {
        int n = i % 224, k = i / 224;
        float v = 0.f;
        if (n < 136)               v = w_vatt[k * 136 + n];
        else if (n < 200)          v = w_edge[k * EFe + (n - 136)];
        *(__nv_bfloat16*)(smem_raw + OFF_WCT + n * STRB + k * 2) = __float2bfloat16(v);
    }
    if (tid < EFe) { ge_s[tid] = gain_e[tid]; be_s[tid] = bias_e[tid]; bd_s[tid] = b_edge[tid]; }
    __syncthreads();

    for (int tile = blockIdx.x; tile < NTILES; tile += gridDim.x) {
        const int e0 = tile * ETILE;

        if (tid < ETILE) {
            src_s[tid] = edges[e0 + tid];
            dst_s[tid] = edges[Ee + e0 + tid];
        }

        // ---- LN(a) -> an (bf16, packed). Each warp: 4 rows, float2 per lane ----
        #pragma unroll
        for (int q = 0; q < 4; q++) {
            int r = warp * 4 + q;
            float2 x = *(const float2*)(ain + (size_t)(e0 + r) * EFe + 2 * lane);
            float s = x.x + x.y;
            float ss = fmaf(x.x, x.x, x.y * x.y);
            #pragma unroll
            for (int o = 16; o > 0; o >>= 1) {
                s  += __shfl_xor_sync(0xffffffffu, s, o);
                ss += __shfl_xor_sync(0xffffffffu, ss, o);
            }
            float mu = s * (1.f / EFe);
            float rstd = rsqrtf(ss * (1.f / EFe) - mu * mu + 1e-5f);
            float v0 = (x.x - mu) * rstd * ge_s[2 * lane]     + be_s[2 * lane];
            float v1 = (x.y - mu) * rstd * ge_s[2 * lane + 1] + be_s[2 * lane + 1];
            *(uint32_t*)(smem_raw + OFF_AN + r * STRA + lane * 4) = pack_bf16(v0, v1);
        }
        __syncthreads();   // sync1

        // ---- phase A: hsum = hsrc[src] + hdst[dst] -> m_s (bf16, coalesced) ----
        #pragma unroll
        for (int q = 0; q < 4; q++) {
            int r = warp * 4 + q;
            int sr = src_s[r], dr = dst_s[r];
            float4 hs = ((const float4*)(g_hsrc + (size_t)sr * Ff))[lane];
            float4 hd = ((const float4*)(g_hdst + (size_t)dr * Ff))[lane];
            uint2 p;
            p.x = pack_bf16(hs.x + hd.x, hs.y + hd.y);
            p.y = pack_bf16(hs.z + hd.z, hs.w + hd.w);
            *(uint2*)(smem_raw + OFF_M + r * STRB + lane * 8) = p;
        }

        const int row0 = wr * 16 + g, row1 = row0 + 8;
        const int s0 = src_s[row0], s1 = src_s[row1];

        // ---- GEMM1: D1[64,128] = an[64,64] @ w_a[64,128]; each warp: 32 cols ----
        float d1[4][4];
        #pragma unroll
        for (int i = 0; i < 4; i++) { d1[i][0]=0.f; d1[i][1]=0.f; d1[i][2]=0.f; d1[i][3]=0.f; }
        {
            const uint32_t aBase = smemU + OFF_AN + wr * 16 * STRA + aoffA;
            #pragma unroll
            for (int ks = 0; ks < 4; ks++) {
                uint32_t a0, a1, a2, a3;
                ldsm_x4(a0, a1, a2, a3, aBase + ks * 32);
                #pragma unroll
                for (int nb = 0; nb < 4; nb++) {
                    int n0 = wq * 32 + nb * 8;
                    uint32_t b0, b1;
                    ldsm_x2(b0, b1, smemU + OFF_WAT + n0 * STRA + boffA + ks * 32);
                    mma_bf16(d1[nb], a0, a1, a2, a3, b0, b1);
                }
            }
        }
        __syncthreads();   // sync2: hsum in m_s ready

        // ---- epilogue 1: m = silu(D1 + hsum) -> m_s (in place, bf16) ----
        #pragma unroll
        for (int nb = 0; nb < 4; nb++) {
            int col = wq * 32 + nb * 8 + 2 * tg;
            float2 h0 = unpack_bf16(*(const uint32_t*)(smem_raw + OFF_M + row0 * STRB + col * 2));
            float2 h1 = unpack_bf16(*(const uint32_t*)(smem_raw + OFF_M + row1 * STRB + col * 2));
            float m00 = siluf(d1[nb][0] + h0.x);
            float m01 = siluf(d1[nb][1] + h0.y);
            float m10 = siluf(d1[nb][2] + h1.x);
            float m11 = siluf(d1[nb][3] + h1.y);
            *(uint32_t*)(smem_raw + OFF_M + row0 * STRB + col * 2) = pack_bf16(m00, m01);
            *(uint32_t*)(smem_raw + OFF_M + row1 * STRB + col * 2) = pack_bf16(m10, m11);
        }
        __syncthreads();   // sync3: m ready

        // ---- GEMM2: D2[64,224] = m[64,128] @ wc[128,224]; each warp: 56 cols ----
        float d2[7][4];
        #pragma unroll
        for (int i = 0; i < 7; i++) { d2[i][0]=0.f; d2[i][1]=0.f; d2[i][2]=0.f; d2[i][3]=0.f; }
        {
            const uint32_t aBase = smemU + OFF_M + wr * 16 * STRB + aoffB;
            #pragma unroll
            for (int ks = 0; ks < 8; ks++) {
                uint32_t a0, a1, a2, a3;
                ldsm_x4(a0, a1, a2, a3, aBase + ks * 32);
                #pragma unroll
                for (int nb = 0; nb < 7; nb++) {
                    int n0 = wq * 56 + nb * 8;
                    uint32_t b0, b1;
                    ldsm_x2(b0, b1, smemU + OFF_WCT + n0 * STRB + boffB + ks * 32);
                    mma_bf16(d2[nb], a0, a1, a2, a3, b0, b1);
                }
            }
        }

        // head logits: cols 128..135 = (wq==2, nb==2)
        if (wq == 2) {
            int h = 2 * tg;
            float e00 = __expf(d2[2][0]);
            float e01 = __expf(d2[2][1]);
            float e10 = __expf(d2[2][2]);
            float e11 = __expf(d2[2][3]);
            wexp_s[row0 * 9 + h]     = e00;
            wexp_s[row0 * 9 + h + 1] = e01;
            wexp_s[row1 * 9 + h]     = e10;
            wexp_s[row1 * 9 + h + 1] = e11;
            float* p0 = g_wsum + (size_t)s0 * Hh + h;
            float* p1 = g_wsum + (size_t)s1 * Hh + h;
            asm volatile("red.global.add.f32 [%0], %1;" :: "l"(p0),     "f"(e00) : "memory");
            asm volatile("red.global.add.f32 [%0], %1;" :: "l"(p0 + 1), "f"(e01) : "memory");
            asm volatile("red.global.add.f32 [%0], %1;" :: "l"(p1),     "f"(e10) : "memory");
            asm volatile("red.global.add.f32 [%0], %1;" :: "l"(p1 + 1), "f"(e11) : "memory");
        }
        __syncthreads();   // sync4

        // ---- v-stage: wexp*v -> m_s (bf16); aout epilogue ----
        #pragma unroll
        for (int nb = 0; nb < 7; nb++) {
            int col = wq * 56 + nb * 8 + 2 * tg;
            if (col < Ff) {
                int h = col >> 4;
                float w0 = wexp_s[row0 * 9 + h];
                float w1 = wexp_s[row1 * 9 + h];
                *(uint32_t*)(smem_raw + OFF_M + row0 * STRB + col * 2) =
                    pack_bf16(d2[nb][0] * w0, d2[nb][1] * w0);
                *(uint32_t*)(smem_raw + OFF_M + row1 * STRB + col * 2) =
                    pack_bf16(d2[nb][2] * w1, d2[nb][3] * w1);
            } else if (col >= 136 && col < 200) {
                int k2 = col - 136;
                float2 a0v = *(const float2*)(ain + (size_t)(e0 + row0) * EFe + k2);
                float2 a1v = *(const float2*)(ain + (size_t)(e0 + row1) * EFe + k2);
                float2 r0v, r1v;
                r0v.x = a0v.x + d2[nb][0] + bd_s[k2];
                r0v.y = a0v.y + d2[nb][1] + bd_s[k2 + 1];
                r1v.x = a1v.x + d2[nb][2] + bd_s[k2];
                r1v.y = a1v.y + d2[nb][3] + bd_s[k2 + 1];
                *(float2*)(aout + (size_t)(e0 + row0) * EFe + k2) = r0v;
                *(float2*)(aout + (size_t)(e0 + row1) * EFe + k2) = r1v;
            }
        }
        __syncthreads();   // sync5

        // ---- cooperative coalesced v-reduction into g_o ----
        #pragma unroll
        for (int q = 0; q < 4; q++) {
            int r = warp * 4 + q;
            int sr = src_s[r];
            uint2 p = *(const uint2*)(smem_raw + OFF_M + r * STRB + lane * 8);
            float2 v01 = unpack_bf16(p.x);
            float2 v23 = unpack_bf16(p.y);
            float* ob = g_o + (size_t)sr * Ff + lane * 4;
            asm volatile("red.global.add.v4.f32 [%0], {%1, %2, %3, %4};"
                         :: "l"(ob), "f"(v01.x), "f"(v01.y), "f"(v23.x), "f"(v23.y)
                         : "memory");
        }
        __syncthreads();   // sync6
    }
}

// ============== fused node kernel 2 + MLP (HMMA, 128-row tile, ldmatrix) ===========
#define N2STR 272
#define OFF2_W  0           // 128*272 = 34816
#define OFF2_XN 34816       // 128*272 = 34816
#define OFF2_T  69632       // 128*272 = 34816
#define OFF2_HM 104448      // 128*136*4 = 69632
#define SM_N2M  174080

__global__ __launch_bounds__(512) void k_node2mlp(const float* __restrict__ input,
                                                  const int* __restrict__ batch,
                                                  const float* __restrict__ w_out,
                                                  const float* __restrict__ b_out,
                                                  const float* __restrict__ w1,
                                                  const float* __restrict__ b1,
                                                  const float* __restrict__ w2,
                                                  const float* __restrict__ b2,
                                                  float* __restrict__ hout) {
    extern __shared__ __align__(16) char smem_raw[];
    const uint32_t smemU = (uint32_t)__cvta_generic_to_shared(smem_raw);
    const int tid = threadIdx.x;
    const int warp = tid >> 5, lane = tid & 31;
    const int g = lane >> 2, tg = lane & 3;
    const int wr = warp & 7, wq = warp >> 3;
    const int nb = blockIdx.x * NTILE;
    char* wbuf = smem_raw + OFF2_W;
    char* xnb  = smem_raw + OFF2_XN;
    char* tb   = smem_raw + OFF2_T;
    float* hm_s = (float*)(smem_raw + OFF2_HM);

    const uint32_t aoff = ((lane & 7) + ((lane >> 3) & 1) * 8) * N2STR + ((lane >> 4) & 1) * 16;
    const uint32_t boff = (lane & 7) * N2STR + ((lane >> 3) & 1) * 16;
    const uint32_t aRow = wr * 16 * N2STR + aoff;

    for (int i = tid; i < NTILE * 32; i += 512) {
        int r = i >> 5, c4 = i & 31;
        int n = nb + r;
        int nc = n < Nn ? n : Nn - 1;
        float4 o4 = ((const float4*)(g_o + (size_t)nc * Ff))[c4];
        int h = c4 >> 2;
        float inv = 1.f / (g_wsum[nc * Hh + h] + 1e-16f);
        *(uint32_t*)(tb + r * N2STR + c4 * 8)     = pack_bf16(o4.x * inv, o4.y * inv);
        *(uint32_t*)(tb + r * N2STR + c4 * 8 + 4) = pack_bf16(o4.z * inv, o4.w * inv);
    }
    for (int i = tid; i < 128 * 128; i += 512) {
        int n = i & 127, k = i >> 7;
        *(__nv_bfloat16*)(wbuf + n * N2STR + k * 2) = __float2bfloat16(w_out[k * Ff + n]);
    }
    __syncthreads();

    const int row0 = wr * 16 + g, row1 = row0 + 8;
    const int na = nb + row0, nb1 = nb + row1;
    const int nca = na < Nn ? na : Nn - 1;
    const int ncb = nb1 < Nn ? nb1 : Nn - 1;

    {
        float d[8][4];
        #pragma unroll
        for (int i = 0; i < 8; i++) { d[i][0]=0.f; d[i][1]=0.f; d[i][2]=0.f; d[i][3]=0.f; }
        #pragma unroll
        for (int ks = 0; ks < 8; ks++) {
            uint32_t a0, a1, a2, a3;
            ldsm_x4(a0, a1, a2, a3, smemU + OFF2_T + aRow + ks * 32);
            #pragma unroll
            for (int nb2 = 0; nb2 < 8; nb2++) {
                int n0 = wq * 64 + nb2 * 8;
                uint32_t b0, b1;
                ldsm_x2(b0, b1, smemU + OFF2_W + n0 * N2STR + boff + ks * 32);
                mma_bf16(d[nb2], a0, a1, a2, a3, b0, b1);
            }
        }
        #pragma unroll
        for (int nb2 = 0; nb2 < 8; nb2++) {
            int c = wq * 64 + nb2 * 8 + 2 * tg;
            float2 ia = *(const float2*)(input + (size_t)nca * Ff + c);
            float2 ib = *(const float2*)(input + (size_t)ncb * Ff + c);
            float bb0 = __ldg(b_out + c), bb1 = __ldg(b_out + c + 1);
            hm_s[row0 * 136 + c]     = d[nb2][0] + ia.x + bb0;
            hm_s[row0 * 136 + c + 1] = d[nb2][1] + ia.y + bb1;
            hm_s[row1 * 136 + c]     = d[nb2][2] + ib.x + bb0;
            hm_s[row1 * 136 + c + 1] = d[nb2][3] + ib.y + bb1;
        }
    }
    __syncthreads();

    #pragma unroll
    for (int q = 0; q < 8; q++) {
        int r = warp * 8 + q;
        int n = nb + r;
        int nc = n < Nn ? n : Nn - 1;
        float4 x = ((const float4*)(hm_s + r * 136))[lane];
        float s  = x.x + x.y + x.z + x.w;
        float ss = fmaf(x.x, x.x, fmaf(x.y, x.y, fmaf(x.z, x.z, x.w * x.w)));
        #pragma unroll
        for (int o = 16; o > 0; o >>= 1) {
            s  += __shfl_xor_sync(0xffffffffu, s, o);
            ss += __shfl_xor_sync(0xffffffffu, ss, o);
        }
        float mu = s * (1.f / Ff);
        float rstd = rsqrtf(ss * (1.f / Ff) - mu * mu + 1e-5f);
        int bix = batch[nc];
        const float* sb = g_sb_mlp + bix * F2;
        float4 sc = *((const float4*)(sb + lane * 4));
        float4 sh = *((const float4*)(sb + Ff + lane * 4));
        float o0 = (x.x - mu) * rstd * (1.f + sc.x) + sh.x;
        float o1 = (x.y - mu) * rstd * (1.f + sc.y) + sh.y;
        float o2 = (x.z - mu) * rstd * (1.f + sc.z) + sh.z;
        float o3 = (x.w - mu) * rstd * (1.f + sc.w) + sh.w;
        *(uint32_t*)(xnb + r * N2STR + lane * 8)     = pack_bf16(o0, o1);
        *(uint32_t*)(xnb + r * N2STR + lane * 8 + 4) = pack_bf16(o2, o3);
    }

    float oacc[8][4];
    #pragma unroll
    for (int i = 0; i < 8; i++) { oacc[i][0]=0.f; oacc[i][1]=0.f; oacc[i][2]=0.f; oacc[i][3]=0.f; }

    for (int ch = 0; ch < 4; ch++) {
        __syncthreads();
        for (int i = tid; i < 128 * 128; i += 512) {
            int n = i & 127, k = i >> 7;
            *(__nv_bfloat16*)(wbuf + n * N2STR + k * 2) =
                __float2bfloat16(w1[k * 512 + ch * 128 + n]);
        }
        __syncthreads();
        float dt[8][4];
        #pragma unroll
        for (int i = 0; i < 8; i++) { dt[i][0]=0.f; dt[i][1]=0.f; dt[i][2]=0.f; dt[i][3]=0.f; }
        #pragma unroll
        for (int ks = 0; ks < 8; ks++) {
            uint32_t a0, a1, a2, a3;
            ldsm_x4(a0, a1, a2, a3, smemU + OFF2_XN + aRow + ks * 32);
            #pragma unroll
            for (int nb2 = 0; nb2 < 8; nb2++) {
                int n0 = wq * 64 + nb2 * 8;
                uint32_t b0, b1;
                ldsm_x2(b0, b1, smemU + OFF2_W + n0 * N2STR + boff + ks * 32);
                mma_bf16(dt[nb2], a0, a1, a2, a3, b0, b1);
            }
        }
        #pragma unroll
        for (int nb2 = 0; nb2 < 8; nb2++) {
            int c = wq * 64 + nb2 * 8 + 2 * tg;
            float b10 = __ldg(b1 + ch * 128 + c), b11 = __ldg(b1 + ch * 128 + c + 1);
            *(uint32_t*)(tb + row0 * N2STR + c * 2) =
                pack_bf16(siluf(dt[nb2][0] + b10), siluf(dt[nb2][1] + b11));
            *(uint32_t*)(tb + row1 * N2STR + c * 2) =
                pack_bf16(siluf(dt[nb2][2] + b10), siluf(dt[nb2][3] + b11));
        }
        __syncthreads();
        for (int i = tid; i < 128 * 128; i += 512) {
            int n = i & 127, k = i >> 7;
            *(__nv_bfloat16*)(wbuf + n * N2STR + k * 2) =
                __float2bfloat16(w2[(size_t)(ch * 128 + k) * Ff + n]);
        }
        __syncthreads();
        #pragma unroll
        for (int ks = 0; ks < 8; ks++) {
            uint32_t a0, a1, a2, a3;
            ldsm_x4(a0, a1, a2, a3, smemU + OFF2_T + aRow + ks * 32);
            #pragma unroll
            for (int nb2 = 0; nb2 < 8; nb2++) {
                int n0 = wq * 64 + nb2 * 8;
                uint32_t b0, b1;
                ldsm_x2(b0, b1, smemU + OFF2_W + n0 * N2STR + boff + ks * 32);
                mma_bf16(oacc[nb2], a0, a1, a2, a3, b0, b1);
            }
        }
    }

    #pragma unroll
    for (int nb2 = 0; nb2 < 8; nb2++) {
        int c = wq * 64 + nb2 * 8 + 2 * tg;
        float b20 = __ldg(b2 + c), b21 = __ldg(b2 + c + 1);
        if (na < Nn) {
            float2 v = {oacc[nb2][0] + hm_s[row0 * 136 + c]     + b20,
                        oacc[nb2][1] + hm_s[row0 * 136 + c + 1] + b21};
            *(float2*)(hout + (size_t)na * Ff + c) = v;
        }
        if (nb1 < Nn) {
            float2 v = {oacc[nb2][2] + hm_s[row1 * 136 + c]     + b20,
                        oacc[nb2][3] + hm_s[row1 * 136 + c + 1] + b21};
            *(float2*)(hout + (size_t)nb1 * Ff + c) = v;
        }
    }
}

// ---------------- launcher ---------------------------------------------------------
extern "C" void kernel_launch(void* const* d_in, const int* in_sizes, int n_in,
                              void* d_out, int out_size) {
    const float* input     = (const float*)d_in[0];
    const float* cond      = (const float*)d_in[1];
    const float* a         = (const float*)d_in[2];
    const int*   batch     = (const int*)d_in[3];
    const int*   edges     = (const int*)d_in[4];
    const float* w_ada_mix = (const float*)d_in[5];
    const float* b_ada_mix = (const float*)d_in[6];
    const float* w_h       = (const float*)d_in[7];
    const float* b_h       = (const float*)d_in[8];
    const float* w_a       = (const float*)d_in[9];
    const float* w_vatt    = (const float*)d_in[10];
    const float* w_out     = (const float*)d_in[11];
    const float* b_out     = (const float*)d_in[12];
    const float* g_edge_p  = (const float*)d_in[13];
    const float* be_edge_p = (const float*)d_in[14];
    const float* w_edge    = (const float*)d_in[15];
    const float* b_edge    = (const float*)d_in[16];
    const float* w_ada_mlp = (const float*)d_in[17];
    const float* b_ada_mlp = (const float*)d_in[18];
    const float* w1        = (const float*)d_in[19];
    const float* b1        = (const float*)d_in[20];
    const float* w2        = (const float*)d_in[21];
    const float* b2        = (const float*)d_in[22];

    float* hout = (float*)d_out;                       // h: [N, F]
    float* aout = (float*)d_out + (size_t)Nn * Ff;     // a_out: [E, EF]

    cudaFuncSetAttribute(k_node1,    cudaFuncAttributeMaxDynamicSharedMemorySize, SM_NODE1);
    cudaFuncSetAttribute(k_edge,     cudaFuncAttributeMaxDynamicSharedMemorySize, SMEDGE);
    cudaFuncSetAttribute(k_node2mlp, cudaFuncAttributeMaxDynamicSharedMemorySize, SM_N2M);

    const int NT = (Nn + NTILE - 1) / NTILE;  // 157

    k_init<<<(Nn * Ff + 255) / 256, 256>>>();
    k_cond<<<dim3(Gg, 2), 256>>>(cond, w_ada_mix, b_ada_mix, w_ada_mlp, b_ada_mlp);
    k_node1<<<NT, 512, SM_NODE1>>>(input, batch, w_h, b_h);
    k_edge<<<296, 512, SMEDGE>>>(a, edges, w_a, w_vatt, w_edge,
                                 g_edge_p, be_edge_p, b_edge, aout);
    k_node2mlp<<<NT, 512, SM_N2M>>>(input, batch, w_out, b_out, w1, b1, w2, b2, hout);
}

// round 13
// speedup vs baseline: 1.6843x; 1.0215x over previous
#include <cuda_runtime.h>
#include <cuda_bf16.h>
#include <cstdint>
#include <cstddef>

#define Nn 20000
#define Ee 320000
#define Ff 128
#define Hh 8
#define EFe 64
#define Aa 128
#define Gg 32
#define F2 256
#define NTILE 128
#define ETILE 64
#define NTILES (Ee / ETILE)

// ---------------- scratch (device globals; no allocations allowed) ----------------
__device__ float g_sb_mix[Gg * F2];
__device__ float g_sb_mlp[Gg * F2];
__device__ float g_hsrc[(size_t)Nn * Ff];
__device__ float g_hdst[(size_t)Nn * Ff];
__device__ float g_wsum[Nn * Hh];
__device__ float g_o[(size_t)Nn * Ff];

__device__ __forceinline__ float siluf(float x) { return x / (1.f + __expf(-x)); }

// bf16 warp MMA: D[16x8] += A[16x16] * B[16x8]
__device__ __forceinline__ void mma_bf16(float* d, uint32_t a0, uint32_t a1,
                                         uint32_t a2, uint32_t a3,
                                         uint32_t b0, uint32_t b1) {
    asm volatile(
        "mma.sync.aligned.m16n8k16.row.col.f32.bf16.bf16.f32 "
        "{%0,%1,%2,%3}, {%4,%5,%6,%7}, {%8,%9}, {%0,%1,%2,%3};"
        : "+f"(d[0]), "+f"(d[1]), "+f"(d[2]), "+f"(d[3])
        : "r"(a0), "r"(a1), "r"(a2), "r"(a3), "r"(b0), "r"(b1));
}

__device__ __forceinline__ void ldsm_x4(uint32_t& r0, uint32_t& r1,
                                        uint32_t& r2, uint32_t& r3, uint32_t addr) {
    asm volatile("ldmatrix.sync.aligned.m8n8.x4.shared.b16 {%0,%1,%2,%3}, [%4];"
                 : "=r"(r0), "=r"(r1), "=r"(r2), "=r"(r3) : "r"(addr));
}
__device__ __forceinline__ void ldsm_x2(uint32_t& r0, uint32_t& r1, uint32_t addr) {
    asm volatile("ldmatrix.sync.aligned.m8n8.x2.shared.b16 {%0,%1}, [%2];"
                 : "=r"(r0), "=r"(r1) : "r"(addr));
}

__device__ __forceinline__ uint32_t pack_bf16(float a, float b) {
    __nv_bfloat162 p = __floats2bfloat162_rn(a, b);
    return *(uint32_t*)&p;
}
__device__ __forceinline__ float2 unpack_bf16(uint32_t u) {
    __nv_bfloat162 p = *(__nv_bfloat162*)&u;
    return make_float2(__bfloat162float(p.x), __bfloat162float(p.y));
}

// ---------------- init: zero accumulators ----------------------------------------
__global__ void k_init() {
    int i = blockIdx.x * 256 + threadIdx.x;
    if (i < Nn * Ff) g_o[i] = 0.f;
    if (i < Nn * Hh) g_wsum[i] = 0.f;
}

// ---------------- cond GEMMs ------------------------------------------------------
__global__ __launch_bounds__(256) void k_cond(const float* __restrict__ cond,
                                              const float* __restrict__ w_mix,
                                              const float* __restrict__ b_mix,
                                              const float* __restrict__ w_mlp,
                                              const float* __restrict__ b_mlp) {
    __shared__ float cs[Aa];
    int g = blockIdx.x;
    int which = blockIdx.y;
    const float* w = which ? w_mlp : w_mix;
    const float* b = which ? b_mlp : b_mix;
    float* outp = which ? g_sb_mlp : g_sb_mix;
    int t = threadIdx.x;
    if (t < Aa) cs[t] = cond[g * Aa + t];
    __syncthreads();
    float acc = b[t];
    #pragma unroll 8
    for (int k = 0; k < Aa; k++) acc = fmaf(cs[k], w[k * F2 + t], acc);
    outp[g * F2 + t] = acc;
}

// ============== node kernel 1 (HMMA, 128-row tile, 2 CTA/SM) =======================
#define N1STR 272
#define N1_OFF_XM 0         // 128*272 = 34816
#define N1_OFF_W  34816     // 256*272 = 69632
#define SM_NODE1  104448    // x2 = 208896 <= 227KB

__global__ __launch_bounds__(512, 2) void k_node1(const float* __restrict__ input,
                                                  const int* __restrict__ batch,
                                                  const float* __restrict__ w_h,
                                                  const float* __restrict__ b_h) {
    extern __shared__ __align__(16) char smem_raw[];
    const uint32_t smemU = (uint32_t)__cvta_generic_to_shared(smem_raw);
    const int tid = threadIdx.x;
    const int warp = tid >> 5, lane = tid & 31;
    const int nb = blockIdx.x * NTILE;
    char* xm = smem_raw + N1_OFF_XM;
    char* wb = smem_raw + N1_OFF_W;

    // A-order x4: row-half varies with lane bit3; k-half with bit4
    const uint32_t a4 = ((lane & 7) + ((lane >> 3) & 1) * 8) * N1STR + ((lane >> 4) & 1) * 16;
    // B-pair-order x4: n-half varies with lane bit4; k-half with bit3
    const uint32_t b4 = ((lane & 7) + ((lane >> 4) & 1) * 8) * N1STR + ((lane >> 3) & 1) * 16;

    for (int i = tid; i < 256 * 128; i += 512) {
        int n = i & 255, k = i >> 8;
        *(__nv_bfloat16*)(wb + n * N1STR + k * 2) = __float2bfloat16(w_h[k * F2 + n]);
    }
    #pragma unroll
    for (int q = 0; q < 8; q++) {
        int r = warp * 8 + q;
        int n = nb + r;
        int nc = n < Nn ? n : Nn - 1;
        float4 x = ((const float4*)(input + (size_t)nc * Ff))[lane];
        float s  = x.x + x.y + x.z + x.w;
        float ss = fmaf(x.x, x.x, fmaf(x.y, x.y, fmaf(x.z, x.z, x.w * x.w)));
        #pragma unroll
        for (int o = 16; o > 0; o >>= 1) {
            s  += __shfl_xor_sync(0xffffffffu, s, o);
            ss += __shfl_xor_sync(0xffffffffu, ss, o);
        }
        float mu = s * (1.f / Ff);
        float rstd = rsqrtf(ss * (1.f / Ff) - mu * mu + 1e-5f);
        int bix = batch[nc];
        const float* sb = g_sb_mix + bix * F2;
        float4 sc = *((const float4*)(sb + lane * 4));
        float4 sh = *((const float4*)(sb + Ff + lane * 4));
        float o0 = (x.x - mu) * rstd * (1.f + sc.x) + sh.x;
        float o1 = (x.y - mu) * rstd * (1.f + sc.y) + sh.y;
        float o2 = (x.z - mu) * rstd * (1.f + sc.z) + sh.z;
        float o3 = (x.w - mu) * rstd * (1.f + sc.w) + sh.w;
        *(uint32_t*)(xm + r * N1STR + lane * 8)     = pack_bf16(o0, o1);
        *(uint32_t*)(xm + r * N1STR + lane * 8 + 4) = pack_bf16(o2, o3);
    }
    __syncthreads();

    const int wr = warp & 7, wq = warp >> 3;
    const int row0 = wr * 16 + (lane >> 2);
    const int na = nb + row0, nbr = na + 8;
    const uint32_t aBase = smemU + N1_OFF_XM + wr * 16 * N1STR + a4;
    const int tg = lane & 3;

    #pragma unroll
    for (int npass = 0; npass < 2; npass++) {
        float d[8][4];
        #pragma unroll
        for (int i = 0; i < 8; i++) { d[i][0]=0.f; d[i][1]=0.f; d[i][2]=0.f; d[i][3]=0.f; }
        #pragma unroll
        for (int ks = 0; ks < 8; ks++) {
            uint32_t a0, a1, a2, a3;
            ldsm_x4(a0, a1, a2, a3, aBase + ks * 32);
            #pragma unroll
            for (int np = 0; np < 4; np++) {   // 4 B pairs = 8 nb
                int n0 = npass * 128 + wq * 64 + np * 16;
                uint32_t b0, b1, b2, b3;
                ldsm_x4(b0, b1, b2, b3, smemU + N1_OFF_W + n0 * N1STR + b4 + ks * 32);
                mma_bf16(d[2 * np],     a0, a1, a2, a3, b0, b1);
                mma_bf16(d[2 * np + 1], a0, a1, a2, a3, b2, b3);
            }
        }
        float* gout = (npass == 0) ? g_hsrc : g_hdst;
        #pragma unroll
        for (int nb2 = 0; nb2 < 8; nb2++) {
            int c = npass * 128 + wq * 64 + nb2 * 8 + 2 * tg;
            float bb0 = __ldg(b_h + c), bb1 = __ldg(b_h + c + 1);
            int c2 = c - npass * 128;
            if (na < Nn) { float2 v = {d[nb2][0]+bb0, d[nb2][1]+bb1};
                           *(float2*)(gout + (size_t)na * Ff + c2) = v; }
            if (nbr < Nn) { float2 v = {d[nb2][2]+bb0, d[nb2][3]+bb1};
                           *(float2*)(gout + (size_t)nbr * Ff + c2) = v; }
        }
    }
}

// ========== mma.sync bf16 edge kernel — 64-edge tile, 2 CTAs/SM, coalesced aout ====
#define STRA 144
#define STRB 272
#define OFF_WAT  0            // 128*144 = 18432
#define OFF_WCT  18432        // 224*272 = 60928 -> 79360
#define OFF_AN   79360        // 64*144  = 9216  -> 88576 (an, then bf16 da staging)
#define OFF_M    88576        // 64*272  = 17408 -> 105984
#define OFF_WEXP 105984       // 64*9*4  = 2304  -> 108288
#define OFF_SRC  108288
#define OFF_DST  108544
#define OFF_GE   108800
#define OFF_BE   109056
#define OFF_BD   109312
#define SMEDGE   109568       // x2 CTAs = 219136 <= 228KB

__global__ __launch_bounds__(512, 2) void k_edge(const float* __restrict__ ain,
                                                 const int* __restrict__ edges,
                                                 const float* __restrict__ w_a,
                                                 const float* __restrict__ w_vatt,
                                                 const float* __restrict__ w_edge,
                                                 const float* __restrict__ gain_e,
                                                 const float* __restrict__ bias_e,
                                                 const float* __restrict__ b_edge,
                                                 float* __restrict__ aout) {
    extern __shared__ __align__(16) char smem_raw[];
    const uint32_t smemU = (uint32_t)__cvta_generic_to_shared(smem_raw);
    const int tid = threadIdx.x;
    const int warp = tid >> 5, lane = tid & 31;
    const int g = lane >> 2, tg = lane & 3;
    const int wr = warp & 3;       // M block (16 rows)
    const int wq = warp >> 2;      // N group (0..3)

    float* wexp_s = (float*)(smem_raw + OFF_WEXP);
    int*   src_s  = (int*)(smem_raw + OFF_SRC);
    int*   dst_s  = (int*)(smem_raw + OFF_DST);
    float* ge_s   = (float*)(smem_raw + OFF_GE);
    float* be_s   = (float*)(smem_raw + OFF_BE);
    float* bd_s   = (float*)(smem_raw + OFF_BD);

    // A-order and B-pair-order ldmatrix offsets for both strides
    const uint32_t a4A = ((lane & 7) + ((lane >> 3) & 1) * 8) * STRA + ((lane >> 4) & 1) * 16;
    const uint32_t b4A = ((lane & 7) + ((lane >> 4) & 1) * 8) * STRA + ((lane >> 3) & 1) * 16;
    const uint32_t a4B = ((lane & 7) + ((lane >> 3) & 1) * 8) * STRB + ((lane >> 4) & 1) * 16;
    const uint32_t b4B = ((lane & 7) + ((lane >> 4) & 1) * 8) * STRB + ((lane >> 3) & 1) * 16;
    const uint32_t x2B = (lane & 7) * STRB + ((lane >> 3) & 1) * 16;

    // staging — coalesced
    for (int i = tid; i < 128 * 64; i += 512) {
        int n = i & 127, k = i >> 7;
        *(__nv_bfloat16*)(smem_raw + OFF_WAT + n * STRA + k * 2) =
            __float2bfloat16(w_a[k * Ff + n]);
    }
    for (int i = tid; i < 224 * 128; i += 512) {
        int n = i % 224, k = i / 224;
        float v = 0.f;
        if (n < 136)               v = w_vatt[k * 136 + n];
        else if (n < 200)          v = w_edge[k * EFe + (n - 136)];
        *(__nv_bfloat16*)(smem_raw + OFF_WCT + n * STRB + k * 2) = __float2bfloat16(v);
    }
    if (tid < EFe) { ge_s[tid] = gain_e[tid]; be_s[tid] = bias_e[tid]; bd_s[tid] = b_edge[tid]; }
    __syncthreads();

    for (int tile = blockIdx.x; tile < NTILES; tile += gridDim.x) {
        const int e0 = tile * ETILE;

        if (tid < ETILE) {
            src_s[tid] = edges[e0 + tid];
            dst_s[tid] = edges[Ee + e0 + tid];
        }

        // ---- LN(a) -> an (bf16, packed). Each warp: 4 rows ----
        #pragma unroll
        for (int q = 0; q < 4; q++) {
            int r = warp * 4 + q;
            float2 x = *(const float2*)(ain + (size_t)(e0 + r) * EFe + 2 * lane);
            float s = x.x + x.y;
            float ss = fmaf(x.x, x.x, x.y * x.y);
            #pragma unroll
            for (int o = 16; o > 0; o >>= 1) {
                s  += __shfl_xor_sync(0xffffffffu, s, o);
                ss += __shfl_xor_sync(0xffffffffu, ss, o);
            }
            float mu = s * (1.f / EFe);
            float rstd = rsqrtf(ss * (1.f / EFe) - mu * mu + 1e-5f);
            float v0 = (x.x - mu) * rstd * ge_s[2 * lane]     + be_s[2 * lane];
            float v1 = (x.y - mu) * rstd * ge_s[2 * lane + 1] + be_s[2 * lane + 1];
            *(uint32_t*)(smem_raw + OFF_AN + r * STRA + lane * 4) = pack_bf16(v0, v1);
        }
        __syncthreads();   // sync1

        // ---- phase A: hsum = hsrc[src] + hdst[dst] -> m_s (bf16, coalesced) ----
        #pragma unroll
        for (int q = 0; q < 4; q++) {
            int r = warp * 4 + q;
            int sr = src_s[r], dr = dst_s[r];
            float4 hs = ((const float4*)(g_hsrc + (size_t)sr * Ff))[lane];
            float4 hd = ((const float4*)(g_hdst + (size_t)dr * Ff))[lane];
            uint2 p;
            p.x = pack_bf16(hs.x + hd.x, hs.y + hd.y);
            p.y = pack_bf16(hs.z + hd.z, hs.w + hd.w);
            *(uint2*)(smem_raw + OFF_M + r * STRB + lane * 8) = p;
        }

        const int row0 = wr * 16 + g, row1 = row0 + 8;
        const int s0 = src_s[row0], s1 = src_s[row1];

        // ---- GEMM1: D1[64,128] = an[64,64] @ w_a[64,128]; warp: 32 cols ----
        float d1[4][4];
        #pragma unroll
        for (int i = 0; i < 4; i++) { d1[i][0]=0.f; d1[i][1]=0.f; d1[i][2]=0.f; d1[i][3]=0.f; }
        {
            const uint32_t aBase = smemU + OFF_AN + wr * 16 * STRA + a4A;
            #pragma unroll
            for (int ks = 0; ks < 4; ks++) {
                uint32_t a0, a1, a2, a3;
                ldsm_x4(a0, a1, a2, a3, aBase + ks * 32);
                #pragma unroll
                for (int np = 0; np < 2; np++) {   // 2 pairs = 4 nb
                    int n0 = wq * 32 + np * 16;
                    uint32_t b0, b1, b2, b3;
                    ldsm_x4(b0, b1, b2, b3, smemU + OFF_WAT + n0 * STRA + b4A + ks * 32);
                    mma_bf16(d1[2 * np],     a0, a1, a2, a3, b0, b1);
                    mma_bf16(d1[2 * np + 1], a0, a1, a2, a3, b2, b3);
                }
            }
        }
        __syncthreads();   // sync2: hsum in m_s ready

        // ---- epilogue 1: m = silu(D1 + hsum) -> m_s (in place, bf16) ----
        #pragma unroll
        for (int nb = 0; nb < 4; nb++) {
            int col = wq * 32 + nb * 8 + 2 * tg;
            float2 h0 = unpack_bf16(*(const uint32_t*)(smem_raw + OFF_M + row0 * STRB + col * 2));
            float2 h1 = unpack_bf16(*(const uint32_t*)(smem_raw + OFF_M + row1 * STRB + col * 2));
            float m00 = siluf(d1[nb][0] + h0.x);
            float m01 = siluf(d1[nb][1] + h0.y);
            float m10 = siluf(d1[nb][2] + h1.x);
            float m11 = siluf(d1[nb][3] + h1.y);
            *(uint32_t*)(smem_raw + OFF_M + row0 * STRB + col * 2) = pack_bf16(m00, m01);
            *(uint32_t*)(smem_raw + OFF_M + row1 * STRB + col * 2) = pack_bf16(m10, m11);
        }
        __syncthreads();   // sync3: m ready

        // ---- GEMM2: D2[64,224] = m[64,128] @ wc[128,224]; warp: 56 cols ----
        float d2[7][4];
        #pragma unroll
        for (int i = 0; i < 7; i++) { d2[i][0]=0.f; d2[i][1]=0.f; d2[i][2]=0.f; d2[i][3]=0.f; }
        {
            const uint32_t aBase = smemU + OFF_M + wr * 16 * STRB + a4B;
            #pragma unroll
            for (int ks = 0; ks < 8; ks++) {
                uint32_t a0, a1, a2, a3;
                ldsm_x4(a0, a1, a2, a3, aBase + ks * 32);
                #pragma unroll
                for (int np = 0; np < 3; np++) {   // 3 pairs = nb 0..5
                    int n0 = wq * 56 + np * 16;
                    uint32_t b0, b1, b2, b3;
                    ldsm_x4(b0, b1, b2, b3, smemU + OFF_WCT + n0 * STRB + b4B + ks * 32);
                    mma_bf16(d2[2 * np],     a0, a1, a2, a3, b0, b1);
                    mma_bf16(d2[2 * np + 1], a0, a1, a2, a3, b2, b3);
                }
                {   // nb 6
                    int n0 = wq * 56 + 48;
                    uint32_t b0, b1;
                    ldsm_x2(b0, b1, smemU + OFF_WCT + n0 * STRB + x2B + ks * 32);
                    mma_bf16(d2[6], a0, a1, a2, a3, b0, b1);
                }
            }
        }

        // head logits: cols 128..135 = (wq==2, nb==2)
        if (wq == 2) {
            int h = 2 * tg;
            float e00 = __expf(d2[2][0]);
            float e01 = __expf(d2[2][1]);
            float e10 = __expf(d2[2][2]);
            float e11 = __expf(d2[2][3]);
            wexp_s[row0 * 9 + h]     = e00;
            wexp_s[row0 * 9 + h + 1] = e01;
            wexp_s[row1 * 9 + h]     = e10;
            wexp_s[row1 * 9 + h + 1] = e11;
            float* p0 = g_wsum + (size_t)s0 * Hh + h;
            float* p1 = g_wsum + (size_t)s1 * Hh + h;
            asm volatile("red.global.add.f32 [%0], %1;" :: "l"(p0),     "f"(e00) : "memory");
            asm volatile("red.global.add.f32 [%0], %1;" :: "l"(p0 + 1), "f"(e01) : "memory");
            asm volatile("red.global.add.f32 [%0], %1;" :: "l"(p1),     "f"(e10) : "memory");
            asm volatile("red.global.add.f32 [%0], %1;" :: "l"(p1 + 1), "f"(e11) : "memory");
        }
        __syncthreads();   // sync4: wexp ready; GEMM reads of m_s & an done

        // ---- v-stage: wexp*v -> m_s; da -> an buffer (both bf16, smem only) ----
        #pragma unroll
        for (int nb = 0; nb < 7; nb++) {
            int col = wq * 56 + nb * 8 + 2 * tg;
            if (col < Ff) {
                int h = col >> 4;
                float w0 = wexp_s[row0 * 9 + h];
                float w1 = wexp_s[row1 * 9 + h];
                *(uint32_t*)(smem_raw + OFF_M + row0 * STRB + col * 2) =
                    pack_bf16(d2[nb][0] * w0, d2[nb][1] * w0);
                *(uint32_t*)(smem_raw + OFF_M + row1 * STRB + col * 2) =
                    pack_bf16(d2[nb][2] * w1, d2[nb][3] * w1);
            } else if (col >= 136 && col < 200) {
                int k2 = col - 136;
                *(uint32_t*)(smem_raw + OFF_AN + row0 * STRA + k2 * 2) =
                    pack_bf16(d2[nb][0], d2[nb][1]);
                *(uint32_t*)(smem_raw + OFF_AN + row1 * STRA + k2 * 2) =
                    pack_bf16(d2[nb][2], d2[nb][3]);
            }
        }
        __syncthreads();   // sync5: m_s = wexp*v, an = da for whole tile

        // ---- cooperative coalesced epilogues: g_o reduction + aout write ----
        #pragma unroll
        for (int q = 0; q < 4; q++) {
            int r = warp * 4 + q;
            int sr = src_s[r];
            uint2 p = *(const uint2*)(smem_raw + OFF_M + r * STRB + lane * 8);
            float2 v01 = unpack_bf16(p.x);
            float2 v23 = unpack_bf16(p.y);
            float* ob = g_o + (size_t)sr * Ff + lane * 4;
            asm volatile("red.global.add.v4.f32 [%0], {%1, %2, %3, %4};"
                         :: "l"(ob), "f"(v01.x), "f"(v01.y), "f"(v23.x), "f"(v23.y)
                         : "memory");
            // aout: coalesced (row contiguous, float2 per lane)
            float2 da = unpack_bf16(*(const uint32_t*)(smem_raw + OFF_AN + r * STRA + lane * 4));
            float2 av = *(const float2*)(ain + (size_t)(e0 + r) * EFe + 2 * lane);
            float2 ro;
            ro.x = av.x + da.x + bd_s[2 * lane];
            ro.y = av.y + da.y + bd_s[2 * lane + 1];
            *(float2*)(aout + (size_t)(e0 + r) * EFe + 2 * lane) = ro;
        }
        __syncthreads();   // sync6
    }
}

// ============== fused node kernel 2 + MLP (HMMA, 128-row tile, ldmatrix) ===========
#define N2STR 272
#define OFF2_W  0           // 128*272 = 34816
#define OFF2_XN 34816       // 128*272 = 34816
#define OFF2_T  69632       // 128*272 = 34816
#define OFF2_HM 104448      // 128*136*4 = 69632
#define SM_N2M  174080

__global__ __launch_bounds__(512) void k_node2mlp(const float* __restrict__ input,
                                                  const int* __restrict__ batch,
                                                  const float* __restrict__ w_out,
                                                  const float* __restrict__ b_out,
                                                  const float* __restrict__ w1,
                                                  const float* __restrict__ b1,
                                                  const float* __restrict__ w2,
                                                  const float* __restrict__ b2,
                                                  float* __restrict__ hout) {
    extern __shared__ __align__(16) char smem_raw[];
    const uint32_t smemU = (uint32_t)__cvta_generic_to_shared(smem_raw);
    const int tid = threadIdx.x;
    const int warp = tid >> 5, lane = tid & 31;
    const int g = lane >> 2, tg = lane & 3;
    const int wr = warp & 7, wq = warp >> 3;
    const int nb = blockIdx.x * NTILE;
    char* wbuf = smem_raw + OFF2_W;
    char* xnb  = smem_raw + OFF2_XN;
    char* tb   = smem_raw + OFF2_T;
    float* hm_s = (float*)(smem_raw + OFF2_HM);

    const uint32_t a4 = ((lane & 7) + ((lane >> 3) & 1) * 8) * N2STR + ((lane >> 4) & 1) * 16;
    const uint32_t b4 = ((lane & 7) + ((lane >> 4) & 1) * 8) * N2STR + ((lane >> 3) & 1) * 16;
    const uint32_t aRow = wr * 16 * N2STR + a4;

    for (int i = tid; i < NTILE * 32; i += 512) {
        int r = i >> 5, c4 = i & 31;
        int n = nb + r;
        int nc = n < Nn ? n : Nn - 1;
        float4 o4 = ((const float4*)(g_o + (size_t)nc * Ff))[c4];
        int h = c4 >> 2;
        float inv = 1.f / (g_wsum[nc * Hh + h] + 1e-16f);
        *(uint32_t*)(tb + r * N2STR + c4 * 8)     = pack_bf16(o4.x * inv, o4.y * inv);
        *(uint32_t*)(tb + r * N2STR + c4 * 8 + 4) = pack_bf16(o4.z * inv, o4.w * inv);
    }
    for (int i = tid; i < 128 * 128; i += 512) {
        int n = i & 127, k = i >> 7;
        *(__nv_bfloat16*)(wbuf + n * N2STR + k * 2) = __float2bfloat16(w_out[k * Ff + n]);
    }
    __syncthreads();

    const int row0 = wr * 16 + g, row1 = row0 + 8;
    const int na = nb + row0, nb1 = nb + row1;
    const int nca = na < Nn ? na : Nn - 1;
    const int ncb = nb1 < Nn ? nb1 : Nn - 1;

    {
        float d[8][4];
        #pragma unroll
        for (int i = 0; i < 8; i++) { d[i][0]=0.f; d[i][1]=0.f; d[i][2]=0.f; d[i][3]=0.f; }
        #pragma unroll
        for (int ks = 0; ks < 8; ks++) {
            uint32_t a0, a1, a2, a3;
            ldsm_x4(a0, a1, a2, a3, smemU + OFF2_T + aRow + ks * 32);
            #pragma unroll
            for (int np = 0; np < 4; np++) {
                int n0 = wq * 64 + np * 16;
                uint32_t b0, b1, b2, b3;
                ldsm_x4(b0, b1, b2, b3, smemU + OFF2_W + n0 * N2STR + b4 + ks * 32);
                mma_bf16(d[2 * np],     a0, a1, a2, a3, b0, b1);
                mma_bf16(d[2 * np + 1], a0, a1, a2, a3, b2, b3);
            }
        }
        #pragma unroll
        for (int nb2 = 0; nb2 < 8; nb2++) {
            int c = wq * 64 + nb2 * 8 + 2 * tg;
            float2 ia = *(const float2*)(input + (size_t)nca * Ff + c);
            float2 ib = *(const float2*)(input + (size_t)ncb * Ff + c);
            float bb0 = __ldg(b_out + c), bb1 = __ldg(b_out + c + 1);
            hm_s[row0 * 136 + c]     = d[nb2][0] + ia.x + bb0;
            hm_s[row0 * 136 + c + 1] = d[nb2][1] + ia.y + bb1;
            hm_s[row1 * 136 + c]     = d[nb2][2] + ib.x + bb0;
            hm_s[row1 * 136 + c + 1] = d[nb2][3] + ib.y + bb1;
        }
    }
    __syncthreads();

    #pragma unroll
    for (int q = 0; q < 8; q++) {
        int r = warp * 8 + q;
        int n = nb + r;
        int nc = n < Nn ? n : Nn - 1;
        float4 x = ((const float4*)(hm_s + r * 136))[lane];
        float s  = x.x + x.y + x.z + x.w;
        float ss = fmaf(x.x, x.x, fmaf(x.y, x.y, fmaf(x.z, x.z, x.w * x.w)));
        #pragma unroll
        for (int o = 16; o > 0; o >>= 1) {
            s  += __shfl_xor_sync(0xffffffffu, s, o);
            ss += __shfl_xor_sync(0xffffffffu, ss, o);
        }
        float mu = s * (1.f / Ff);
        float rstd = rsqrtf(ss * (1.f / Ff) - mu * mu + 1e-5f);
        int bix = batch[nc];
        const float* sb = g_sb_mlp + bix * F2;
        float4 sc = *((const float4*)(sb + lane * 4));
        float4 sh = *((const float4*)(sb + Ff + lane * 4));
        float o0 = (x.x - mu) * rstd * (1.f + sc.x) + sh.x;
        float o1 = (x.y - mu) * rstd * (1.f + sc.y) + sh.y;
        float o2 = (x.z - mu) * rstd * (1.f + sc.z) + sh.z;
        float o3 = (x.w - mu) * rstd * (1.f + sc.w) + sh.w;
        *(uint32_t*)(xnb + r * N2STR + lane * 8)     = pack_bf16(o0, o1);
        *(uint32_t*)(xnb + r * N2STR + lane * 8 + 4) = pack_bf16(o2, o3);
    }

    float oacc[8][4];
    #pragma unroll
    for (int i = 0; i < 8; i++) { oacc[i][0]=0.f; oacc[i][1]=0.f; oacc[i][2]=0.f; oacc[i][3]=0.f; }

    for (int ch = 0; ch < 4; ch++) {
        __syncthreads();
        for (int i = tid; i < 128 * 128; i += 512) {
            int n = i & 127, k = i >> 7;
            *(__nv_bfloat16*)(wbuf + n * N2STR + k * 2) =
                __float2bfloat16(w1[k * 512 + ch * 128 + n]);
        }
        __syncthreads();
        float dt[8][4];
        #pragma unroll
        for (int i = 0; i < 8; i++) { dt[i][0]=0.f; dt[i][1]=0.f; dt[i][2]=0.f; dt[i][3]=0.f; }
        #pragma unroll
        for (int ks = 0; ks < 8; ks++) {
            uint32_t a0, a1, a2, a3;
            ldsm_x4(a0, a1, a2, a3, smemU + OFF2_XN + aRow + ks * 32);
            #pragma unroll
            for (int np = 0; np < 4; np++) {
                int n0 = wq * 64 + np * 16;
                uint32_t b0, b1, b2, b3;
                ldsm_x4(b0, b1, b2, b3, smemU + OFF2_W + n0 * N2STR + b4 + ks * 32);
                mma_bf16(dt[2 * np],     a0, a1, a2, a3, b0, b1);
                mma_bf16(dt[2 * np + 1], a0, a1, a2, a3, b2, b3);
            }
        }
        #pragma unroll
        for (int nb2 = 0; nb2 < 8; nb2++) {
            int c = wq * 64 + nb2 * 8 + 2 * tg;
            float b10 = __ldg(b1 + ch * 128 + c), b11 = __ldg(b1 + ch * 128 + c + 1);
            *(uint32_t*)(tb + row0 * N2STR + c * 2) =
                pack_bf16(siluf(dt[nb2][0] + b10), siluf(dt[nb2][1] + b11));
            *(uint32_t*)(tb + row1 * N2STR + c * 2) =
                pack_bf16(siluf(dt[nb2][2] + b10), siluf(dt[nb2][3] + b11));
        }
        __syncthreads();
        for (int i = tid; i < 128 * 128; i += 512) {
            int n = i & 127, k = i >> 7;
            *(__nv_bfloat16*)(wbuf + n * N2STR + k * 2) =
                __float2bfloat16(w2[(size_t)(ch * 128 + k) * Ff + n]);
        }
        __syncthreads();
        #pragma unroll
        for (int ks = 0; ks < 8; ks++) {
            uint32_t a0, a1, a2, a3;
            ldsm_x4(a0, a1, a2, a3, smemU + OFF2_T + aRow + ks * 32);
            #pragma unroll
            for (int np = 0; np < 4; np++) {
                int n0 = wq * 64 + np * 16;
                uint32_t b0, b1, b2, b3;
                ldsm_x4(b0, b1, b2, b3, smemU + OFF2_W + n0 * N2STR + b4 + ks * 32);
                mma_bf16(oacc[2 * np],     a0, a1, a2, a3, b0, b1);
                mma_bf16(oacc[2 * np + 1], a0, a1, a2, a3, b2, b3);
            }
        }
    }

    #pragma unroll
    for (int nb2 = 0; nb2 < 8; nb2++) {
        int c = wq * 64 + nb2 * 8 + 2 * tg;
        float b20 = __ldg(b2 + c), b21 = __ldg(b2 + c + 1);
        if (na < Nn) {
            float2 v = {oacc[nb2][0] + hm_s[row0 * 136 + c]     + b20,
                        oacc[nb2][1] + hm_s[row0 * 136 + c + 1] + b21};
            *(float2*)(hout + (size_t)na * Ff + c) = v;
        }
        if (nb1 < Nn) {
            float2 v = {oacc[nb2][2] + hm_s[row1 * 136 + c]     + b20,
                        oacc[nb2][3] + hm_s[row1 * 136 + c + 1] + b21};
            *(float2*)(hout + (size_t)nb1 * Ff + c) = v;
        }
    }
}

// ---------------- launcher ---------------------------------------------------------
extern "C" void kernel_launch(void* const* d_in, const int* in_sizes, int n_in,
                              void* d_out, int out_size) {
    const float* input     = (const float*)d_in[0];
    const float* cond      = (const float*)d_in[1];
    const float* a         = (const float*)d_in[2];
    const int*   batch     = (const int*)d_in[3];
    const int*   edges     = (const int*)d_in[4];
    const float* w_ada_mix = (const float*)d_in[5];
    const float* b_ada_mix = (const float*)d_in[6];
    const float* w_h       = (const float*)d_in[7];
    const float* b_h       = (const float*)d_in[8];
    const float* w_a       = (const float*)d_in[9];
    const float* w_vatt    = (const float*)d_in[10];
    const float* w_out     = (const float*)d_in[11];
    const float* b_out     = (const float*)d_in[12];
    const float* g_edge_p  = (const float*)d_in[13];
    const float* be_edge_p = (const float*)d_in[14];
    const float* w_edge    = (const float*)d_in[15];
    const float* b_edge    = (const float*)d_in[16];
    const float* w_ada_mlp = (const float*)d_in[17];
    const float* b_ada_mlp = (const float*)d_in[18];
    const float* w1        = (const float*)d_in[19];
    const float* b1        = (const float*)d_in[20];
    const float* w2        = (const float*)d_in[21];
    const float* b2        = (const float*)d_in[22];

    float* hout = (float*)d_out;                       // h: [N, F]
    float* aout = (float*)d_out + (size_t)Nn * Ff;     // a_out: [E, EF]

    cudaFuncSetAttribute(k_node1,    cudaFuncAttributeMaxDynamicSharedMemorySize, SM_NODE1);
    cudaFuncSetAttribute(k_edge,     cudaFuncAttributeMaxDynamicSharedMemorySize, SMEDGE);
    cudaFuncSetAttribute(k_node2mlp, cudaFuncAttributeMaxDynamicSharedMemorySize, SM_N2M);

    const int NT = (Nn + NTILE - 1) / NTILE;  // 157

    k_init<<<(Nn * Ff + 255) / 256, 256>>>();
    k_cond<<<dim3(Gg, 2), 256>>>(cond, w_ada_mix, b_ada_mix, w_ada_mlp, b_ada_mlp);
    k_node1<<<NT, 512, SM_NODE1>>>(input, batch, w_h, b_h);
    k_edge<<<296, 512, SMEDGE>>>(a, edges, w_a, w_vatt, w_edge,
                                 g_edge_p, be_edge_p, b_edge, aout);
    k_node2mlp<<<NT, 512, SM_N2M>>>(input, batch, w_out, b_out, w1, b1, w2, b2, hout);
}

// round 14
// speedup vs baseline: 1.9520x; 1.1589x over previous
#include <cuda_runtime.h>
#include <cuda_bf16.h>
#include <cstdint>
#include <cstddef>

#define Nn 20000
#define Ee 320000
#define Ff 128
#define Hh 8
#define EFe 64
#define Aa 128
#define Gg 32
#define F2 256
#define NTILE 128
#define ETILE 64
#define NTILES (Ee / ETILE)

// ---------------- scratch (device globals; no allocations allowed) ----------------
__device__ float g_sb_mix[Gg * F2];
__device__ float g_sb_mlp[Gg * F2];
__device__ float g_hsrc[(size_t)Nn * Ff];
__device__ float g_hdst[(size_t)Nn * Ff];
__device__ float g_wsum[Nn * Hh];
__device__ float g_o[(size_t)Nn * Ff];
// prepacked bf16 transposed weights
__device__ __nv_bfloat16 pbH[256 * 128];   // w_h^T  [n][k]
__device__ __nv_bfloat16 pbO[128 * 128];   // w_out^T
__device__ __nv_bfloat16 pb1[512 * 128];   // w1^T   [n(512)][k(128)]
__device__ __nv_bfloat16 pb2[128 * 512];   // w2^T   [n(128)][k(512)]

__device__ __forceinline__ float siluf(float x) { return x / (1.f + __expf(-x)); }

__device__ __forceinline__ void mma_bf16(float* d, uint32_t a0, uint32_t a1,
                                         uint32_t a2, uint32_t a3,
                                         uint32_t b0, uint32_t b1) {
    asm volatile(
        "mma.sync.aligned.m16n8k16.row.col.f32.bf16.bf16.f32 "
        "{%0,%1,%2,%3}, {%4,%5,%6,%7}, {%8,%9}, {%0,%1,%2,%3};"
        : "+f"(d[0]), "+f"(d[1]), "+f"(d[2]), "+f"(d[3])
        : "r"(a0), "r"(a1), "r"(a2), "r"(a3), "r"(b0), "r"(b1));
}

__device__ __forceinline__ void ldsm_x4(uint32_t& r0, uint32_t& r1,
                                        uint32_t& r2, uint32_t& r3, uint32_t addr) {
    asm volatile("ldmatrix.sync.aligned.m8n8.x4.shared.b16 {%0,%1,%2,%3}, [%4];"
                 : "=r"(r0), "=r"(r1), "=r"(r2), "=r"(r3) : "r"(addr));
}
__device__ __forceinline__ void ldsm_x2(uint32_t& r0, uint32_t& r1, uint32_t addr) {
    asm volatile("ldmatrix.sync.aligned.m8n8.x2.shared.b16 {%0,%1}, [%2];"
                 : "=r"(r0), "=r"(r1) : "r"(addr));
}

__device__ __forceinline__ void cp16(uint32_t dst, const void* src) {
    asm volatile("cp.async.cg.shared.global [%0], [%1], 16;" :: "r"(dst), "l"(src));
}
#define CP_COMMIT() asm volatile("cp.async.commit_group;" ::: "memory")
#define CP_WAIT(N)  asm volatile("cp.async.wait_group %0;" :: "n"(N) : "memory")

__device__ __forceinline__ uint32_t pack_bf16(float a, float b) {
    __nv_bfloat162 p = __floats2bfloat162_rn(a, b);
    return *(uint32_t*)&p;
}
__device__ __forceinline__ float2 unpack_bf16(uint32_t u) {
    __nv_bfloat162 p = *(__nv_bfloat162*)&u;
    return make_float2(__bfloat162float(p.x), __bfloat162float(p.y));
}

// ---------------- init: zero accumulators ----------------------------------------
__global__ void k_init() {
    int i = blockIdx.x * 256 + threadIdx.x;
    if (i < Nn * Ff) g_o[i] = 0.f;
    if (i < Nn * Hh) g_wsum[i] = 0.f;
}

// ---------------- k_prep: tiled-transpose weights into bf16 [n][k] ----------------
__global__ __launch_bounds__(256) void k_prep(const float* __restrict__ w_h,
                                              const float* __restrict__ w_out,
                                              const float* __restrict__ w1,
                                              const float* __restrict__ w2) {
    __shared__ float t[32][33];
    int b = blockIdx.x;
    const float* src; __nv_bfloat16* dst; int K, N, tk, tn;
    if (b < 32)       { src = w_h;   dst = pbH; K = 128; N = 256; tk = b & 3;  tn = b >> 2; }
    else if (b < 48)  { b -= 32;  src = w_out; dst = pbO; K = 128; N = 128; tk = b & 3;  tn = b >> 2; }
    else if (b < 112) { b -= 48;  src = w1;    dst = pb1; K = 128; N = 512; tk = b & 3;  tn = b >> 2; }
    else              { b -= 112; src = w2;    dst = pb2; K = 512; N = 128; tk = b & 15; tn = b >> 4; }
    int k0 = tk * 32, n0 = tn * 32;
    int lx = threadIdx.x & 31, ly = threadIdx.x >> 5;
    #pragma unroll
    for (int j = 0; j < 32; j += 8)
        t[ly + j][lx] = src[(size_t)(k0 + ly + j) * N + n0 + lx];
    __syncthreads();
    #pragma unroll
    for (int j = 0; j < 32; j += 8)
        dst[(size_t)(n0 + ly + j) * K + k0 + lx] = __float2bfloat16(t[lx][ly + j]);
}

// ---------------- cond GEMMs ------------------------------------------------------
__global__ __launch_bounds__(256) void k_cond(const float* __restrict__ cond,
                                              const float* __restrict__ w_mix,
                                              const float* __restrict__ b_mix,
                                              const float* __restrict__ w_mlp,
                                              const float* __restrict__ b_mlp) {
    __shared__ float cs[Aa];
    int g = blockIdx.x;
    int which = blockIdx.y;
    const float* w = which ? w_mlp : w_mix;
    const float* b = which ? b_mlp : b_mix;
    float* outp = which ? g_sb_mlp : g_sb_mix;
    int t = threadIdx.x;
    if (t < Aa) cs[t] = cond[g * Aa + t];
    __syncthreads();
    float acc = b[t];
    #pragma unroll 8
    for (int k = 0; k < Aa; k++) acc = fmaf(cs[k], w[k * F2 + t], acc);
    outp[g * F2 + t] = acc;
}

// ============== node kernel 1 (HMMA, 128-row tile, 2 CTA/SM, cp.async W) ===========
#define N1STR 272
#define N1_OFF_XM 0         // 128*272 = 34816
#define N1_OFF_W  34816     // 256*272 = 69632
#define SM_NODE1  104448    // x2 = 208896

__global__ __launch_bounds__(512, 2) void k_node1(const float* __restrict__ input,
                                                  const int* __restrict__ batch,
                                                  const float* __restrict__ b_h) {
    extern __shared__ __align__(16) char smem_raw[];
    const uint32_t smemU = (uint32_t)__cvta_generic_to_shared(smem_raw);
    const int tid = threadIdx.x;
    const int warp = tid >> 5, lane = tid & 31;
    const int nb = blockIdx.x * NTILE;
    char* xm = smem_raw + N1_OFF_XM;

    const uint32_t a4 = ((lane & 7) + ((lane >> 3) & 1) * 8) * N1STR + ((lane >> 4) & 1) * 16;
    const uint32_t b4 = ((lane & 7) + ((lane >> 4) & 1) * 8) * N1STR + ((lane >> 3) & 1) * 16;

    // async-stage prepacked w_h^T while LN runs
    for (int i = tid; i < 256 * 16; i += 512) {
        int n = i >> 4, k16 = i & 15;
        cp16(smemU + N1_OFF_W + n * N1STR + k16 * 16, pbH + n * 128 + k16 * 8);
    }
    CP_COMMIT();

    #pragma unroll
    for (int q = 0; q < 8; q++) {
        int r = warp * 8 + q;
        int n = nb + r;
        int nc = n < Nn ? n : Nn - 1;
        float4 x = ((const float4*)(input + (size_t)nc * Ff))[lane];
        float s  = x.x + x.y + x.z + x.w;
        float ss = fmaf(x.x, x.x, fmaf(x.y, x.y, fmaf(x.z, x.z, x.w * x.w)));
        #pragma unroll
        for (int o = 16; o > 0; o >>= 1) {
            s  += __shfl_xor_sync(0xffffffffu, s, o);
            ss += __shfl_xor_sync(0xffffffffu, ss, o);
        }
        float mu = s * (1.f / Ff);
        float rstd = rsqrtf(ss * (1.f / Ff) - mu * mu + 1e-5f);
        int bix = batch[nc];
        const float* sb = g_sb_mix + bix * F2;
        float4 sc = *((const float4*)(sb + lane * 4));
        float4 sh = *((const float4*)(sb + Ff + lane * 4));
        float o0 = (x.x - mu) * rstd * (1.f + sc.x) + sh.x;
        float o1 = (x.y - mu) * rstd * (1.f + sc.y) + sh.y;
        float o2 = (x.z - mu) * rstd * (1.f + sc.z) + sh.z;
        float o3 = (x.w - mu) * rstd * (1.f + sc.w) + sh.w;
        *(uint32_t*)(xm + r * N1STR + lane * 8)     = pack_bf16(o0, o1);
        *(uint32_t*)(xm + r * N1STR + lane * 8 + 4) = pack_bf16(o2, o3);
    }
    CP_WAIT(0);
    __syncthreads();

    const int wr = warp & 7, wq = warp >> 3;
    const int row0 = wr * 16 + (lane >> 2);
    const int na = nb + row0, nbr = na + 8;
    const uint32_t aBase = smemU + N1_OFF_XM + wr * 16 * N1STR + a4;
    const int tg = lane & 3;

    #pragma unroll
    for (int npass = 0; npass < 2; npass++) {
        float d[8][4];
        #pragma unroll
        for (int i = 0; i < 8; i++) { d[i][0]=0.f; d[i][1]=0.f; d[i][2]=0.f; d[i][3]=0.f; }
        #pragma unroll
        for (int ks = 0; ks < 8; ks++) {
            uint32_t a0, a1, a2, a3;
            ldsm_x4(a0, a1, a2, a3, aBase + ks * 32);
            #pragma unroll
            for (int np = 0; np < 4; np++) {
                int n0 = npass * 128 + wq * 64 + np * 16;
                uint32_t b0, b1, b2, b3;
                ldsm_x4(b0, b1, b2, b3, smemU + N1_OFF_W + n0 * N1STR + b4 + ks * 32);
                mma_bf16(d[2 * np],     a0, a1, a2, a3, b0, b1);
                mma_bf16(d[2 * np + 1], a0, a1, a2, a3, b2, b3);
            }
        }
        float* gout = (npass == 0) ? g_hsrc : g_hdst;
        #pragma unroll
        for (int nb2 = 0; nb2 < 8; nb2++) {
            int c = npass * 128 + wq * 64 + nb2 * 8 + 2 * tg;
            float bb0 = __ldg(b_h + c), bb1 = __ldg(b_h + c + 1);
            int c2 = c - npass * 128;
            if (na < Nn) { float2 v = {d[nb2][0]+bb0, d[nb2][1]+bb1};
                           *(float2*)(gout + (size_t)na * Ff + c2) = v; }
            if (nbr < Nn) { float2 v = {d[nb2][2]+bb0, d[nb2][3]+bb1};
                           *(float2*)(gout + (size_t)nbr * Ff + c2) = v; }
        }
    }
}

// ========== mma.sync bf16 edge kernel — 64-edge tile, 2 CTAs/SM, 5 syncs ===========
#define STRA 144
#define STRB 272
#define OFF_WAT  0
#define OFF_WCT  18432
#define OFF_AN   79360
#define OFF_M    88576
#define OFF_WEXP 105984
#define OFF_SRC  108288
#define OFF_GE   108800
#define OFF_BE   109056
#define OFF_BD   109312
#define SMEDGE   109568

__global__ __launch_bounds__(512, 2) void k_edge(const float* __restrict__ ain,
                                                 const int* __restrict__ edges,
                                                 const float* __restrict__ w_a,
                                                 const float* __restrict__ w_vatt,
                                                 const float* __restrict__ w_edge,
                                                 const float* __restrict__ gain_e,
                                                 const float* __restrict__ bias_e,
                                                 const float* __restrict__ b_edge,
                                                 float* __restrict__ aout) {
    extern __shared__ __align__(16) char smem_raw[];
    const uint32_t smemU = (uint32_t)__cvta_generic_to_shared(smem_raw);
    const int tid = threadIdx.x;
    const int warp = tid >> 5, lane = tid & 31;
    const int g = lane >> 2, tg = lane & 3;
    const int wr = warp & 3;
    const int wq = warp >> 2;

    float* wexp_s = (float*)(smem_raw + OFF_WEXP);
    int*   src_s  = (int*)(smem_raw + OFF_SRC);
    float* ge_s   = (float*)(smem_raw + OFF_GE);
    float* be_s   = (float*)(smem_raw + OFF_BE);
    float* bd_s   = (float*)(smem_raw + OFF_BD);

    const uint32_t a4A = ((lane & 7) + ((lane >> 3) & 1) * 8) * STRA + ((lane >> 4) & 1) * 16;
    const uint32_t b4A = ((lane & 7) + ((lane >> 4) & 1) * 8) * STRA + ((lane >> 3) & 1) * 16;
    const uint32_t a4B = ((lane & 7) + ((lane >> 3) & 1) * 8) * STRB + ((lane >> 4) & 1) * 16;
    const uint32_t b4B = ((lane & 7) + ((lane >> 4) & 1) * 8) * STRB + ((lane >> 3) & 1) * 16;
    const uint32_t x2B = (lane & 7) * STRB + ((lane >> 3) & 1) * 16;

    for (int i = tid; i < 128 * 64; i += 512) {
        int n = i & 127, k = i >> 7;
        *(__nv_bfloat16*)(smem_raw + OFF_WAT + n * STRA + k * 2) =
            __float2bfloat16(w_a[k * Ff + n]);
    }
    for (int i = tid; i < 224 * 128; i += 512) {
        int n = i % 224, k = i / 224;
        float v = 0.f;
        if (n < 136)               v = w_vatt[k * 136 + n];
        else if (n < 200)          v = w_edge[k * EFe + (n - 136)];
        *(__nv_bfloat16*)(smem_raw + OFF_WCT + n * STRB + k * 2) = __float2bfloat16(v);
    }
    if (tid < EFe) { ge_s[tid] = gain_e[tid]; be_s[tid] = bias_e[tid]; bd_s[tid] = b_edge[tid]; }
    __syncthreads();

    for (int tile = blockIdx.x; tile < NTILES; tile += gridDim.x) {
        const int e0 = tile * ETILE;

        if (tid < ETILE) src_s[tid] = edges[e0 + tid];

        // ---- LN(a) -> an (bf16) ----
        #pragma unroll
        for (int q = 0; q < 4; q++) {
            int r = warp * 4 + q;
            float2 x = *(const float2*)(ain + (size_t)(e0 + r) * EFe + 2 * lane);
            float s = x.x + x.y;
            float ss = fmaf(x.x, x.x, x.y * x.y);
            #pragma unroll
            for (int o = 16; o > 0; o >>= 1) {
                s  += __shfl_xor_sync(0xffffffffu, s, o);
                ss += __shfl_xor_sync(0xffffffffu, ss, o);
            }
            float mu = s * (1.f / EFe);
            float rstd = rsqrtf(ss * (1.f / EFe) - mu * mu + 1e-5f);
            float v0 = (x.x - mu) * rstd * ge_s[2 * lane]     + be_s[2 * lane];
            float v1 = (x.y - mu) * rstd * ge_s[2 * lane + 1] + be_s[2 * lane + 1];
            *(uint32_t*)(smem_raw + OFF_AN + r * STRA + lane * 4) = pack_bf16(v0, v1);
        }

        // ---- hsum = hsrc[src] + hdst[dst] -> m_s (bf16; indices from global) ----
        #pragma unroll
        for (int q = 0; q < 4; q++) {
            int r = warp * 4 + q;
            int sr = __ldg(edges + e0 + r);
            int dr = __ldg(edges + Ee + e0 + r);
            float4 hs = ((const float4*)(g_hsrc + (size_t)sr * Ff))[lane];
            float4 hd = ((const float4*)(g_hdst + (size_t)dr * Ff))[lane];
            uint2 p;
            p.x = pack_bf16(hs.x + hd.x, hs.y + hd.y);
            p.y = pack_bf16(hs.z + hd.z, hs.w + hd.w);
            *(uint2*)(smem_raw + OFF_M + r * STRB + lane * 8) = p;
        }
        __syncthreads();   // sync1: an + hsum + src_s ready

        const int row0 = wr * 16 + g, row1 = row0 + 8;
        const int s0 = src_s[row0], s1 = src_s[row1];

        // ---- GEMM1 ----
        float d1[4][4];
        #pragma unroll
        for (int i = 0; i < 4; i++) { d1[i][0]=0.f; d1[i][1]=0.f; d1[i][2]=0.f; d1[i][3]=0.f; }
        {
            const uint32_t aBase = smemU + OFF_AN + wr * 16 * STRA + a4A;
            #pragma unroll
            for (int ks = 0; ks < 4; ks++) {
                uint32_t a0, a1, a2, a3;
                ldsm_x4(a0, a1, a2, a3, aBase + ks * 32);
                #pragma unroll
                for (int np = 0; np < 2; np++) {
                    int n0 = wq * 32 + np * 16;
                    uint32_t b0, b1, b2, b3;
                    ldsm_x4(b0, b1, b2, b3, smemU + OFF_WAT + n0 * STRA + b4A + ks * 32);
                    mma_bf16(d1[2 * np],     a0, a1, a2, a3, b0, b1);
                    mma_bf16(d1[2 * np + 1], a0, a1, a2, a3, b2, b3);
                }
            }
        }

        // ---- epilogue 1 (own cells: read hsum, write m; no barrier needed) ----
        #pragma unroll
        for (int nb = 0; nb < 4; nb++) {
            int col = wq * 32 + nb * 8 + 2 * tg;
            float2 h0 = unpack_bf16(*(const uint32_t*)(smem_raw + OFF_M + row0 * STRB + col * 2));
            float2 h1 = unpack_bf16(*(const uint32_t*)(smem_raw + OFF_M + row1 * STRB + col * 2));
            float m00 = siluf(d1[nb][0] + h0.x);
            float m01 = siluf(d1[nb][1] + h0.y);
            float m10 = siluf(d1[nb][2] + h1.x);
            float m11 = siluf(d1[nb][3] + h1.y);
            *(uint32_t*)(smem_raw + OFF_M + row0 * STRB + col * 2) = pack_bf16(m00, m01);
            *(uint32_t*)(smem_raw + OFF_M + row1 * STRB + col * 2) = pack_bf16(m10, m11);
        }
        __syncthreads();   // sync2: m ready

        // ---- GEMM2 ----
        float d2[7][4];
        #pragma unroll
        for (int i = 0; i < 7; i++) { d2[i][0]=0.f; d2[i][1]=0.f; d2[i][2]=0.f; d2[i][3]=0.f; }
        {
            const uint32_t aBase = smemU + OFF_M + wr * 16 * STRB + a4B;
            #pragma unroll
            for (int ks = 0; ks < 8; ks++) {
                uint32_t a0, a1, a2, a3;
                ldsm_x4(a0, a1, a2, a3, aBase + ks * 32);
                #pragma unroll
                for (int np = 0; np < 3; np++) {
                    int n0 = wq * 56 + np * 16;
                    uint32_t b0, b1, b2, b3;
                    ldsm_x4(b0, b1, b2, b3, smemU + OFF_WCT + n0 * STRB + b4B + ks * 32);
                    mma_bf16(d2[2 * np],     a0, a1, a2, a3, b0, b1);
                    mma_bf16(d2[2 * np + 1], a0, a1, a2, a3, b2, b3);
                }
                {
                    int n0 = wq * 56 + 48;
                    uint32_t b0, b1;
                    ldsm_x2(b0, b1, smemU + OFF_WCT + n0 * STRB + x2B + ks * 32);
                    mma_bf16(d2[6], a0, a1, a2, a3, b0, b1);
                }
            }
        }

        if (wq == 2) {
            int h = 2 * tg;
            float e00 = __expf(d2[2][0]);
            float e01 = __expf(d2[2][1]);
            float e10 = __expf(d2[2][2]);
            float e11 = __expf(d2[2][3]);
            wexp_s[row0 * 9 + h]     = e00;
            wexp_s[row0 * 9 + h + 1] = e01;
            wexp_s[row1 * 9 + h]     = e10;
            wexp_s[row1 * 9 + h + 1] = e11;
            float* p0 = g_wsum + (size_t)s0 * Hh + h;
            float* p1 = g_wsum + (size_t)s1 * Hh + h;
            asm volatile("red.global.add.f32 [%0], %1;" :: "l"(p0),     "f"(e00) : "memory");
            asm volatile("red.global.add.f32 [%0], %1;" :: "l"(p0 + 1), "f"(e01) : "memory");
            asm volatile("red.global.add.f32 [%0], %1;" :: "l"(p1),     "f"(e10) : "memory");
            asm volatile("red.global.add.f32 [%0], %1;" :: "l"(p1 + 1), "f"(e11) : "memory");
        }
        __syncthreads();   // sync3: wexp ready; GEMM reads of m_s & an done

        // ---- v-stage: wexp*v -> m_s; da -> an buffer ----
        #pragma unroll
        for (int nb = 0; nb < 7; nb++) {
            int col = wq * 56 + nb * 8 + 2 * tg;
            if (col < Ff) {
                int h = col >> 4;
                float w0 = wexp_s[row0 * 9 + h];
                float w1 = wexp_s[row1 * 9 + h];
                *(uint32_t*)(smem_raw + OFF_M + row0 * STRB + col * 2) =
                    pack_bf16(d2[nb][0] * w0, d2[nb][1] * w0);
                *(uint32_t*)(smem_raw + OFF_M + row1 * STRB + col * 2) =
                    pack_bf16(d2[nb][2] * w1, d2[nb][3] * w1);
            } else if (col >= 136 && col < 200) {
                int k2 = col - 136;
                *(uint32_t*)(smem_raw + OFF_AN + row0 * STRA + k2 * 2) =
                    pack_bf16(d2[nb][0], d2[nb][1]);
                *(uint32_t*)(smem_raw + OFF_AN + row1 * STRA + k2 * 2) =
                    pack_bf16(d2[nb][2], d2[nb][3]);
            }
        }
        __syncthreads();   // sync4

        // ---- cooperative coalesced epilogues ----
        #pragma unroll
        for (int q = 0; q < 4; q++) {
            int r = warp * 4 + q;
            int sr = src_s[r];
            uint2 p = *(const uint2*)(smem_raw + OFF_M + r * STRB + lane * 8);
            float2 v01 = unpack_bf16(p.x);
            float2 v23 = unpack_bf16(p.y);
            float* ob = g_o + (size_t)sr * Ff + lane * 4;
            asm volatile("red.global.add.v4.f32 [%0], {%1, %2, %3, %4};"
                         :: "l"(ob), "f"(v01.x), "f"(v01.y), "f"(v23.x), "f"(v23.y)
                         : "memory");
            float2 da = unpack_bf16(*(const uint32_t*)(smem_raw + OFF_AN + r * STRA + lane * 4));
            float2 av = *(const float2*)(ain + (size_t)(e0 + r) * EFe + 2 * lane);
            float2 ro;
            ro.x = av.x + da.x + bd_s[2 * lane];
            ro.y = av.y + da.y + bd_s[2 * lane + 1];
            *(float2*)(aout + (size_t)(e0 + r) * EFe + 2 * lane) = ro;
        }
        __syncthreads();   // sync5
    }
}

// ============== fused node kernel 2 + MLP (double-buffered cp.async weights) =======
#define N2STR 272
#define OFF2_W  0           // W0: 34816
#define OFF2_W2 34816       // W1: 34816
#define OFF2_XN 69632
#define OFF2_T  104448
#define OFF2_HM 139264      // 128*136*4 = 69632
#define SM_N2M  208896

__global__ __launch_bounds__(512) void k_node2mlp(const float* __restrict__ input,
                                                  const int* __restrict__ batch,
                                                  const float* __restrict__ b_out,
                                                  const float* __restrict__ b1,
                                                  const float* __restrict__ b2,
                                                  float* __restrict__ hout) {
    extern __shared__ __align__(16) char smem_raw[];
    const uint32_t smemU = (uint32_t)__cvta_generic_to_shared(smem_raw);
    const int tid = threadIdx.x;
    const int warp = tid >> 5, lane = tid & 31;
    const int g = lane >> 2, tg = lane & 3;
    const int wr = warp & 7, wq = warp >> 3;
    const int nb = blockIdx.x * NTILE;
    char* xnb  = smem_raw + OFF2_XN;
    char* tb   = smem_raw + OFF2_T;
    float* hm_s = (float*)(smem_raw + OFF2_HM);

    const uint32_t a4 = ((lane & 7) + ((lane >> 3) & 1) * 8) * N2STR + ((lane >> 4) & 1) * 16;
    const uint32_t b4 = ((lane & 7) + ((lane >> 4) & 1) * 8) * N2STR + ((lane >> 3) & 1) * 16;
    const uint32_t aRow = wr * 16 * N2STR + a4;

    // prefetch w_out -> W0, w1[0] -> W1
    for (int i = tid; i < 2048; i += 512) {
        int n = i >> 4, k16 = i & 15;
        cp16(smemU + OFF2_W + n * N2STR + k16 * 16, pbO + n * 128 + k16 * 8);
    }
    CP_COMMIT();
    for (int i = tid; i < 2048; i += 512) {
        int n = i >> 4, k16 = i & 15;
        cp16(smemU + OFF2_W2 + n * N2STR + k16 * 16, pb1 + n * 128 + k16 * 8);
    }
    CP_COMMIT();

    // stage A = o / wsum (bf16) into T
    for (int i = tid; i < NTILE * 32; i += 512) {
        int r = i >> 5, c4 = i & 31;
        int n = nb + r;
        int nc = n < Nn ? n : Nn - 1;
        float4 o4 = ((const float4*)(g_o + (size_t)nc * Ff))[c4];
        int h = c4 >> 2;
        float inv = 1.f / (g_wsum[nc * Hh + h] + 1e-16f);
        *(uint32_t*)(tb + r * N2STR + c4 * 8)     = pack_bf16(o4.x * inv, o4.y * inv);
        *(uint32_t*)(tb + r * N2STR + c4 * 8 + 4) = pack_bf16(o4.z * inv, o4.w * inv);
    }
    CP_WAIT(1);
    __syncthreads();

    const int row0 = wr * 16 + g, row1 = row0 + 8;
    const int na = nb + row0, nb1 = nb + row1;
    const int nca = na < Nn ? na : Nn - 1;
    const int ncb = nb1 < Nn ? nb1 : Nn - 1;

    // GEMM: hm = (o/wsum) @ w_out   (A = T, B = W0)
    {
        float d[8][4];
        #pragma unroll
        for (int i = 0; i < 8; i++) { d[i][0]=0.f; d[i][1]=0.f; d[i][2]=0.f; d[i][3]=0.f; }
        #pragma unroll
        for (int ks = 0; ks < 8; ks++) {
            uint32_t a0, a1, a2, a3;
            ldsm_x4(a0, a1, a2, a3, smemU + OFF2_T + aRow + ks * 32);
            #pragma unroll
            for (int np = 0; np < 4; np++) {
                int n0 = wq * 64 + np * 16;
                uint32_t b0, b1, b2, b3;
                ldsm_x4(b0, b1, b2, b3, smemU + OFF2_W + n0 * N2STR + b4 + ks * 32);
                mma_bf16(d[2 * np],     a0, a1, a2, a3, b0, b1);
                mma_bf16(d[2 * np + 1], a0, a1, a2, a3, b2, b3);
            }
        }
        #pragma unroll
        for (int nb2 = 0; nb2 < 8; nb2++) {
            int c = wq * 64 + nb2 * 8 + 2 * tg;
            float2 ia = *(const float2*)(input + (size_t)nca * Ff + c);
            float2 ib = *(const float2*)(input + (size_t)ncb * Ff + c);
            float bb0 = __ldg(b_out + c), bb1 = __ldg(b_out + c + 1);
            hm_s[row0 * 136 + c]     = d[nb2][0] + ia.x + bb0;
            hm_s[row0 * 136 + c + 1] = d[nb2][1] + ia.y + bb1;
            hm_s[row1 * 136 + c]     = d[nb2][2] + ib.x + bb0;
            hm_s[row1 * 136 + c + 1] = d[nb2][3] + ib.y + bb1;
        }
    }
    __syncthreads();

    // ada_ln(mlp) -> xn bf16
    #pragma unroll
    for (int q = 0; q < 8; q++) {
        int r = warp * 8 + q;
        int n = nb + r;
        int nc = n < Nn ? n : Nn - 1;
        float4 x = ((const float4*)(hm_s + r * 136))[lane];
        float s  = x.x + x.y + x.z + x.w;
        float ss = fmaf(x.x, x.x, fmaf(x.y, x.y, fmaf(x.z, x.z, x.w * x.w)));
        #pragma unroll
        for (int o = 16; o > 0; o >>= 1) {
            s  += __shfl_xor_sync(0xffffffffu, s, o);
            ss += __shfl_xor_sync(0xffffffffu, ss, o);
        }
        float mu = s * (1.f / Ff);
        float rstd = rsqrtf(ss * (1.f / Ff) - mu * mu + 1e-5f);
        int bix = batch[nc];
        const float* sb = g_sb_mlp + bix * F2;
        float4 sc = *((const float4*)(sb + lane * 4));
        float4 sh = *((const float4*)(sb + Ff + lane * 4));
        float o0 = (x.x - mu) * rstd * (1.f + sc.x) + sh.x;
        float o1 = (x.y - mu) * rstd * (1.f + sc.y) + sh.y;
        float o2 = (x.z - mu) * rstd * (1.f + sc.z) + sh.z;
        float o3 = (x.w - mu) * rstd * (1.f + sc.w) + sh.w;
        *(uint32_t*)(xnb + r * N2STR + lane * 8)     = pack_bf16(o0, o1);
        *(uint32_t*)(xnb + r * N2STR + lane * 8 + 4) = pack_bf16(o2, o3);
    }

    float oacc[8][4];
    #pragma unroll
    for (int i = 0; i < 8; i++) { oacc[i][0]=0.f; oacc[i][1]=0.f; oacc[i][2]=0.f; oacc[i][3]=0.f; }

    for (int ch = 0; ch < 4; ch++) {
        __syncthreads();                                  // (A)
        // prefetch w2[ch] -> W0
        for (int i = tid; i < 2048; i += 512) {
            int n = i >> 4, k16 = i & 15;
            cp16(smemU + OFF2_W + n * N2STR + k16 * 16, pb2 + n * 512 + ch * 128 + k16 * 8);
        }
        CP_COMMIT();
        CP_WAIT(1);                                       // w1[ch] (older) done
        __syncthreads();                                  // (B)

        // GEMM dt (A = xn, B = W1 holding w1[ch])
        float dt[8][4];
        #pragma unroll
        for (int i = 0; i < 8; i++) { dt[i][0]=0.f; dt[i][1]=0.f; dt[i][2]=0.f; dt[i][3]=0.f; }
        #pragma unroll
        for (int ks = 0; ks < 8; ks++) {
            uint32_t a0, a1, a2, a3;
            ldsm_x4(a0, a1, a2, a3, smemU + OFF2_XN + aRow + ks * 32);
            #pragma unroll
            for (int np = 0; np < 4; np++) {
                int n0 = wq * 64 + np * 16;
                uint32_t b0, b1, b2, b3;
                ldsm_x4(b0, b1, b2, b3, smemU + OFF2_W2 + n0 * N2STR + b4 + ks * 32);
                mma_bf16(dt[2 * np],     a0, a1, a2, a3, b0, b1);
                mma_bf16(dt[2 * np + 1], a0, a1, a2, a3, b2, b3);
            }
        }
        #pragma unroll
        for (int nb2 = 0; nb2 < 8; nb2++) {
            int c = wq * 64 + nb2 * 8 + 2 * tg;
            float b10 = __ldg(b1 + ch * 128 + c), b11 = __ldg(b1 + ch * 128 + c + 1);
            *(uint32_t*)(tb + row0 * N2STR + c * 2) =
                pack_bf16(siluf(dt[nb2][0] + b10), siluf(dt[nb2][1] + b11));
            *(uint32_t*)(tb + row1 * N2STR + c * 2) =
                pack_bf16(siluf(dt[nb2][2] + b10), siluf(dt[nb2][3] + b11));
        }
        __syncthreads();                                  // (C)
        if (ch < 3) {
            for (int i = tid; i < 2048; i += 512) {
                int n = i >> 4, k16 = i & 15;
                cp16(smemU + OFF2_W2 + n * N2STR + k16 * 16,
                     pb1 + (size_t)(ch + 1) * 128 * 128 + n * 128 + k16 * 8);
            }
            CP_COMMIT();
            CP_WAIT(1);                                   // w2[ch] done
        } else {
            CP_WAIT(0);
        }
        __syncthreads();                                  // (D)

        // GEMM oacc (A = T, B = W0 holding w2[ch])
        #pragma unroll
        for (int ks = 0; ks < 8; ks++) {
            uint32_t a0, a1, a2, a3;
            ldsm_x4(a0, a1, a2, a3, smemU + OFF2_T + aRow + ks * 32);
            #pragma unroll
            for (int np = 0; np < 4; np++) {
                int n0 = wq * 64 + np * 16;
                uint32_t b0, b1, b2, b3;
                ldsm_x4(b0, b1, b2, b3, smemU + OFF2_W + n0 * N2STR + b4 + ks * 32);
                mma_bf16(oacc[2 * np],     a0, a1, a2, a3, b0, b1);
                mma_bf16(oacc[2 * np + 1], a0, a1, a2, a3, b2, b3);
            }
        }
    }

    #pragma unroll
    for (int nb2 = 0; nb2 < 8; nb2++) {
        int c = wq * 64 + nb2 * 8 + 2 * tg;
        float b20 = __ldg(b2 + c), b21 = __ldg(b2 + c + 1);
        if (na < Nn) {
            float2 v = {oacc[nb2][0] + hm_s[row0 * 136 + c]     + b20,
                        oacc[nb2][1] + hm_s[row0 * 136 + c + 1] + b21};
            *(float2*)(hout + (size_t)na * Ff + c) = v;
        }
        if (nb1 < Nn) {
            float2 v = {oacc[nb2][2] + hm_s[row1 * 136 + c]     + b20,
                        oacc[nb2][3] + hm_s[row1 * 136 + c + 1] + b21};
            *(float2*)(hout + (size_t)nb1 * Ff + c) = v;
        }
    }
}

// ---------------- launcher ---------------------------------------------------------
extern "C" void kernel_launch(void* const* d_in, const int* in_sizes, int n_in,
                              void* d_out, int out_size) {
    const float* input     = (const float*)d_in[0];
    const float* cond      = (const float*)d_in[1];
    const float* a         = (const float*)d_in[2];
    const int*   batch     = (const int*)d_in[3];
    const int*   edges     = (const int*)d_in[4];
    const float* w_ada_mix = (const float*)d_in[5];
    const float* b_ada_mix = (const float*)d_in[6];
    const float* w_h       = (const float*)d_in[7];
    const float* b_h       = (const float*)d_in[8];
    const float* w_a       = (const float*)d_in[9];
    const float* w_vatt    = (const float*)d_in[10];
    const float* w_out     = (const float*)d_in[11];
    const float* b_out     = (const float*)d_in[12];
    const float* g_edge_p  = (const float*)d_in[13];
    const float* be_edge_p = (const float*)d_in[14];
    const float* w_edge    = (const float*)d_in[15];
    const float* b_edge    = (const float*)d_in[16];
    const float* w_ada_mlp = (const float*)d_in[17];
    const float* b_ada_mlp = (const float*)d_in[18];
    const float* w1        = (const float*)d_in[19];
    const float* b1        = (const float*)d_in[20];
    const float* w2        = (const float*)d_in[21];
    const float* b2        = (const float*)d_in[22];

    float* hout = (float*)d_out;                       // h: [N, F]
    float* aout = (float*)d_out + (size_t)Nn * Ff;     // a_out: [E, EF]

    cudaFuncSetAttribute(k_node1,    cudaFuncAttributeMaxDynamicSharedMemorySize, SM_NODE1);
    cudaFuncSetAttribute(k_edge,     cudaFuncAttributeMaxDynamicSharedMemorySize, SMEDGE);
    cudaFuncSetAttribute(k_node2mlp, cudaFuncAttributeMaxDynamicSharedMemorySize, SM_N2M);

    const int NT = (Nn + NTILE - 1) / NTILE;  // 157

    k_init<<<(Nn * Ff + 255) / 256, 256>>>();
    k_prep<<<176, 256>>>(w_h, w_out, w1, w2);
    k_cond<<<dim3(Gg, 2), 256>>>(cond, w_ada_mix, b_ada_mix, w_ada_mlp, b_ada_mlp);
    k_node1<<<NT, 512, SM_NODE1>>>(input, batch, b_h);
    k_edge<<<296, 512, SMEDGE>>>(a, edges, w_a, w_vatt, w_edge,
                                 g_edge_p, be_edge_p, b_edge, aout);
    k_node2mlp<<<NT, 512, SM_N2M>>>(input, batch, b_out, b1, b2, hout);
}